// round 2
// baseline (speedup 1.0000x reference)
#include <cuda_runtime.h>
#include <cuda_bf16.h>
#include <math.h>

// ---------------- constants ----------------
#define BB 4
#define TT 12
#define BT 48            // B*T
#define DD 384           // D
#define C2 768           // 2*D
#define NP 12288         // BT*16*16 positions
#define KC 6912          // 9*768 conv im2col K
#define DFF 1536
#define DFF2 3072
#define KENC 1024        // CIN*P*P
#define NDEC 1024        // COUT*P*P
#define LL 4

// ---------------- device scratch ----------------
__device__ float g_Z[(size_t)NP * C2];
__device__ float g_A1[(size_t)NP * C2];
__device__ float g_XE[(size_t)NP * C2];
__device__ float g_DEC[(size_t)NP * C2];
__device__ float g_IM[(size_t)NP * KC];      // im2col (encoder reuses prefix)
__device__ float g_H[(size_t)NP * DFF2];     // MLP hidden / final Ylin
__device__ float g_Wc[(size_t)LL * KC * C2];
__device__ float g_Ebig[(size_t)LL * C2 * C2];
__device__ float g_Eibig[(size_t)LL * C2 * C2];
__device__ float g_Wsbig[(size_t)LL * C2 * C2];
__device__ float g_W1big[(size_t)LL * C2 * DFF2];
__device__ float g_W2big[(size_t)LL * DFF2 * C2];
__device__ float g_xmean[BT * C2];
__device__ float g_flux[BT * C2];
__device__ float g_src[BT * C2];
__device__ float g_gate[BT * DD];
__device__ float g_OD[BT * C2];
__device__ float g_OF[BT * C2];

// ---------------- helpers ----------------
__device__ __forceinline__ float softplus_f(float x) {
    return (x > 20.f) ? x : log1pf(expf(x));
}
__device__ __forceinline__ float gelu_tanh(float x) {
    float x3 = x * x * x;
    float t = tanhf(0.7978845608028654f * (x + 0.044715f * x3));
    return 0.5f * x * (1.f + t);
}

// ---------------- SGEMM: C[M,N] = A[M,K] @ B, tiles 128x128x8 ----------------
// TB=false: B is [K][N]; TB=true: B is [N][K] (C += A @ B^T)
template <bool TB, bool ACC, bool GELU_, bool BIAS_>
__global__ __launch_bounds__(256) void sgemm_k(
    const float* __restrict__ A, const float* __restrict__ B,
    float* __restrict__ C, const float* __restrict__ bias,
    int M, int N, int K)
{
    __shared__ float As[8][128];
    __shared__ float Bs[8][128];
    const int tid = threadIdx.x;
    const int bm = blockIdx.y * 128;
    const int bn = blockIdx.x * 128;

    const int arow = tid >> 1;
    const int acol = (tid & 1) * 4;
    const int trow = (tid >> 4) * 8;
    const int tcol = (tid & 15) * 8;

    float acc[8][8];
#pragma unroll
    for (int i = 0; i < 8; i++)
#pragma unroll
        for (int j = 0; j < 8; j++) acc[i][j] = 0.f;

    const float* Ab = A + (size_t)bm * K;

    for (int k0 = 0; k0 < K; k0 += 8) {
        float4 av = *(const float4*)(Ab + (size_t)arow * K + k0 + acol);
        As[acol + 0][arow] = av.x;
        As[acol + 1][arow] = av.y;
        As[acol + 2][arow] = av.z;
        As[acol + 3][arow] = av.w;
        if (TB) {
            float4 bv = *(const float4*)(B + (size_t)(bn + arow) * K + k0 + acol);
            Bs[acol + 0][arow] = bv.x;
            Bs[acol + 1][arow] = bv.y;
            Bs[acol + 2][arow] = bv.z;
            Bs[acol + 3][arow] = bv.w;
        } else {
            int brow = tid >> 5;
            int bcol = (tid & 31) * 4;
            float4 bv = *(const float4*)(B + (size_t)(k0 + brow) * N + bn + bcol);
            *(float4*)&Bs[brow][bcol] = bv;
        }
        __syncthreads();
#pragma unroll
        for (int kk = 0; kk < 8; kk++) {
            float a[8], b[8];
            *(float4*)(a) = *(const float4*)&As[kk][trow];
            *(float4*)(a + 4) = *(const float4*)&As[kk][trow + 4];
            *(float4*)(b) = *(const float4*)&Bs[kk][tcol];
            *(float4*)(b + 4) = *(const float4*)&Bs[kk][tcol + 4];
#pragma unroll
            for (int i = 0; i < 8; i++)
#pragma unroll
                for (int j = 0; j < 8; j++) acc[i][j] += a[i] * b[j];
        }
        __syncthreads();
    }

#pragma unroll
    for (int i = 0; i < 8; i++) {
        int m = bm + trow + i;
        float* Crow = C + (size_t)m * N + bn + tcol;
#pragma unroll
        for (int j = 0; j < 8; j++) {
            float v = acc[i][j];
            if (BIAS_) v += bias[bn + tcol + j];
            if (GELU_) v = gelu_tanh(v);
            if (ACC) Crow[j] += v;
            else Crow[j] = v;
        }
    }
}

// tiny GEMM for source = flux @ Wsbig (M=48)
__global__ void gemm_small_k(const float* __restrict__ A, const float* __restrict__ B,
                             float* __restrict__ C, int M, int N, int K)
{
    int idx = blockIdx.x * blockDim.x + threadIdx.x;
    if (idx >= M * N) return;
    int m = idx / N, n = idx % N;
    float s = 0.f;
    for (int k = 0; k < K; k++) s += A[(size_t)m * K + k] * B[(size_t)k * N + n];
    C[idx] = s;
}

// ---------------- weight build kernels ----------------
// dst[(2K)x(2N)] = [[re, im],[-im, re]]
__global__ void build_cbig_k(float* __restrict__ dst, const float* __restrict__ re,
                             const float* __restrict__ im, int Kd, int Nd)
{
    int idx = blockIdx.x * blockDim.x + threadIdx.x;
    int N2 = 2 * Nd;
    if (idx >= 2 * Kd * N2) return;
    int k2 = idx / N2, n2 = idx % N2;
    bool ki = k2 >= Kd, ni = n2 >= Nd;
    int k = ki ? k2 - Kd : k2;
    int n = ni ? n2 - Nd : n2;
    float v;
    if (!ki && !ni) v = re[(size_t)k * Nd + n];
    else if (!ki && ni) v = im[(size_t)k * Nd + n];
    else if (ki && !ni) v = -im[(size_t)k * Nd + n];
    else v = re[(size_t)k * Nd + n];
    dst[idx] = v;
}

// Wc[l][k=(r*3+s)*768+ci][co] = cw[l][co][ci][r][s]
__global__ void build_convw_k(float* __restrict__ dst, const float* __restrict__ cw)
{
    int idx = blockIdx.x * blockDim.x + threadIdx.x;  // L*KC*C2 threads
    int co = idx % C2;
    int k = (idx / C2) % KC;
    int l = idx / (C2 * KC);
    int ci = k % C2;
    int rs = k / C2;
    dst[idx] = cw[(((size_t)(l * C2 + co) * C2 + ci) * 9) + rs];
}

// ---------------- im2col ----------------
__global__ void enc_im2col_k(float* __restrict__ P, const float* __restrict__ x)
{
    int idx = blockIdx.x * blockDim.x + threadIdx.x;  // NP*1024
    int kk = idx % KENC;
    int n = idx / KENC;
    int cin = kk / 256;
    int ii = (kk / 16) % 16;
    int jj = kk % 16;
    int bt = n / 256;
    int ph = (n / 16) % 16;
    int pw = n % 16;
    P[idx] = x[(((size_t)(bt * 4 + cin) * 256) + ph * 16 + ii) * 256 + pw * 16 + jj];
}

__global__ void conv_im2col_k(float* __restrict__ IM, const float* __restrict__ A)
{
    int idx = blockIdx.x * blockDim.x + threadIdx.x;  // NP*KC
    int k = idx % KC;
    int n = idx / KC;
    int ci = k % C2;
    int rs = k / C2;
    int dy = rs / 3 - 1;
    int dx = rs % 3 - 1;
    int bt = n / 256;
    int h = (n / 16) % 16;
    int w = n % 16;
    int hh = h + dy, ww = w + dx;
    float v = 0.f;
    if (hh >= 0 && hh < 16 && ww >= 0 && ww < 16)
        v = A[((size_t)(bt * 256 + hh * 16 + ww)) * C2 + ci];
    IM[idx] = v;
}

// ---------------- layernorm over 768 channels ----------------
__global__ void layernorm_k(const float* __restrict__ X, const float* __restrict__ g,
                            const float* __restrict__ b, float* __restrict__ Y)
{
    __shared__ float red[256];
    int n = blockIdx.x;
    int tid = threadIdx.x;
    const float* x = X + (size_t)n * C2;
    float v0 = x[tid], v1 = x[tid + 256], v2 = x[tid + 512];
    red[tid] = v0 + v1 + v2;
    __syncthreads();
    for (int off = 128; off > 0; off >>= 1) {
        if (tid < off) red[tid] += red[tid + off];
        __syncthreads();
    }
    float m = red[0] * (1.f / 768.f);
    __syncthreads();
    float d0 = v0 - m, d1 = v1 - m, d2 = v2 - m;
    red[tid] = d0 * d0 + d1 * d1 + d2 * d2;
    __syncthreads();
    for (int off = 128; off > 0; off >>= 1) {
        if (tid < off) red[tid] += red[tid + off];
        __syncthreads();
    }
    float var = red[0] * (1.f / 768.f);
    float rstd = rsqrtf(var + 1e-5f);
    float* y = Y + (size_t)n * C2;
    y[tid] = d0 * rstd * g[tid] + b[tid];
    y[tid + 256] = d1 * rstd * g[tid + 256] + b[tid + 256];
    y[tid + 512] = d2 * rstd * g[tid + 512] + b[tid + 512];
}

// ---------------- mean over 256 spatial positions ----------------
__global__ void rowmean_k(const float* __restrict__ XE, float* __restrict__ xm)
{
    int bt = blockIdx.x;
    int c = threadIdx.x;  // 768 threads
    float s = 0.f;
    const float* p = XE + (size_t)bt * 256 * C2 + c;
    for (int hw = 0; hw < 256; hw++) s += p[(size_t)hw * C2];
    xm[bt * C2 + c] = s * (1.f / 256.f);
}

// ---------------- flux scan + gate ----------------
__global__ void fluxscan_k(const float* __restrict__ xm, const float* __restrict__ dt,
                           const float* __restrict__ lamf_p, const float* __restrict__ Wg,
                           float* __restrict__ flux, float* __restrict__ gate)
{
    int tid = blockIdx.x * blockDim.x + threadIdx.x;  // BB*DD = 1536
    int b = tid / DD, e = tid % DD;
    float lamf = softplus_f(lamf_p[e]);
    float wg = Wg[e];
    float fr = 0.f, fi = 0.f;
    for (int t = 0; t < TT; t++) {
        int bt = b * TT + t;
        float dtv = dt[bt];
        float a = expf(-lamf * dtv);
        float xr = xm[bt * C2 + e] * dtv;
        float xi = xm[bt * C2 + DD + e] * dtv;
        fr = fr * a + xr;
        fi = fi * a + xi;
        flux[bt * C2 + e] = fr;
        flux[bt * C2 + DD + e] = fi;
        gate[bt * DD + e] = 1.f / (1.f + expf(-fr * wg));
    }
}

// ---------------- op_decay / op_forcing ----------------
__global__ void opdecay_k(const float* __restrict__ dt, const float* __restrict__ nu,
                          const float* __restrict__ omega, float* __restrict__ OD,
                          float* __restrict__ OF)
{
    int idx = blockIdx.x * blockDim.x + threadIdx.x;  // BT*DD
    int bt = idx / DD, e = idx % DD;
    float sp = softplus_f(nu[e]);
    float lr = fminf(fmaxf(-sp, -5.f), 0.3f);
    float li = omega[e];
    float dtv = dt[bt];
    float er = expf(lr * dtv);
    float odr = er * cosf(li * dtv);
    float odi = er * sinf(li * dtv);
    OD[bt * C2 + e] = odr;
    OD[bt * C2 + DD + e] = odi;
    float nr = odr - 1.f, ni = odi;
    float den = lr * lr + li * li;
    OF[bt * C2 + e] = (nr * lr + ni * li) / den;
    OF[bt * C2 + DD + e] = (ni * lr - nr * li) / den;
}

// ---------------- forcing + u_t (in place on XE) ----------------
__global__ void forcing_k(float* __restrict__ XE, const float* __restrict__ gate,
                          const float* __restrict__ src, const float* __restrict__ OF)
{
    int idx = blockIdx.x * blockDim.x + threadIdx.x;  // NP*DD
    int e = idx % DD;
    int n = idx / DD;
    int bt = n / 256;
    float g = gate[bt * DD + e];
    float sr = src[bt * C2 + e], si = src[bt * C2 + DD + e];
    size_t base = (size_t)n * C2;
    float xr = XE[base + e], xi = XE[base + DD + e];
    float fr = xr * g + sr * (1.f - g);
    float fi = xi * g + si * (1.f - g);
    float ofr = OF[bt * C2 + e], ofi = OF[bt * C2 + DD + e];
    XE[base + e] = fr * ofr - fi * ofi;
    XE[base + DD + e] = fr * ofi + fi * ofr;
}

// ---------------- u scan over T (in place on XE) ----------------
__global__ void uscan_k(float* __restrict__ XE, const float* __restrict__ OD)
{
    int tid = blockIdx.x * blockDim.x + threadIdx.x;  // BB*256*DD
    int e = tid % DD;
    int hw = (tid / DD) % 256;
    int b = tid / (DD * 256);
    float ur = 0.f, ui = 0.f;
    for (int t = 0; t < TT; t++) {
        int bt = b * TT + t;
        float odr = OD[bt * C2 + e], odi = OD[bt * C2 + DD + e];
        size_t base = (size_t)(bt * 256 + hw) * C2;
        float xr = XE[base + e], xi = XE[base + DD + e];
        float nr = ur * odr - ui * odi + xr;
        float ni = ur * odi + ui * odr + xi;
        ur = nr; ui = ni;
        XE[base + e] = ur;
        XE[base + DD + e] = ui;
    }
}

__global__ void zadd_k(float* __restrict__ Z, const float* __restrict__ D_)
{
    int idx = blockIdx.x * blockDim.x + threadIdx.x;
    Z[idx] += D_[idx];
}

// ---------------- output scatter ----------------
__global__ void scatter_k(float* __restrict__ out, const float* __restrict__ Y)
{
    int idx = blockIdx.x * blockDim.x + threadIdx.x;  // B*T*4*256*256
    int Wp = idx % 256;
    int Hp = (idx / 256) % 256;
    int co = (idx / 65536) % 4;
    int bt = idx / (65536 * 4);
    int hp = Hp / 16, pi = Hp % 16;
    int wp = Wp / 16, pj = Wp % 16;
    int n = bt * 256 + hp * 16 + wp;
    int o = co * 256 + pi * 16 + pj;
    out[idx] = Y[(size_t)n * NDEC + o];
}

// ---------------- host-side dispatch ----------------
static void run_sgemm(const float* A, const float* B, float* C, const float* bias,
                      int M, int N, int K, int mode)
{
    dim3 grid(N / 128, M / 128);
    switch (mode) {
        case 0: sgemm_k<false, false, false, false><<<grid, 256>>>(A, B, C, nullptr, M, N, K); break;
        case 1: sgemm_k<false, true, false, true><<<grid, 256>>>(A, B, C, bias, M, N, K); break;    // acc + bias
        case 2: sgemm_k<false, false, true, false><<<grid, 256>>>(A, B, C, nullptr, M, N, K); break; // gelu
        case 3: sgemm_k<false, true, false, false><<<grid, 256>>>(A, B, C, nullptr, M, N, K); break; // acc
        case 4: sgemm_k<true, false, false, true><<<grid, 256>>>(A, B, C, bias, M, N, K); break;     // NT + bias
    }
}

template <typename T>
static T* sym(const void* s)
{
    void* p = nullptr;
    cudaGetSymbolAddress(&p, s);
    return (T*)p;
}

extern "C" void kernel_launch(void* const* d_in, const int* in_sizes, int n_in,
                              void* d_out, int out_size)
{
    const float* x       = (const float*)d_in[0];
    const float* dt      = (const float*)d_in[1];
    const float* enc_w   = (const float*)d_in[2];
    const float* enc_b   = (const float*)d_in[3];
    const float* ns_g    = (const float*)d_in[4];
    const float* ns_b    = (const float*)d_in[5];
    const float* cw      = (const float*)d_in[6];
    const float* cb      = (const float*)d_in[7];
    const float* nt_g    = (const float*)d_in[8];
    const float* nt_b    = (const float*)d_in[9];
    const float* E_re    = (const float*)d_in[10];
    const float* E_im    = (const float*)d_in[11];
    const float* Ei_re   = (const float*)d_in[12];
    const float* Ei_im   = (const float*)d_in[13];
    const float* lamflux = (const float*)d_in[14];
    const float* Ws_re   = (const float*)d_in[15];
    const float* Ws_im   = (const float*)d_in[16];
    const float* Wg      = (const float*)d_in[17];
    const float* nu      = (const float*)d_in[18];
    const float* omega   = (const float*)d_in[19];
    const float* w1_re   = (const float*)d_in[20];
    const float* w1_im   = (const float*)d_in[21];
    const float* w2_re   = (const float*)d_in[22];
    const float* w2_im   = (const float*)d_in[23];
    const float* dec_w   = (const float*)d_in[24];
    const float* dec_b   = (const float*)d_in[25];
    float* out = (float*)d_out;

    float* Z    = sym<float>(g_Z);
    float* A1   = sym<float>(g_A1);
    float* XE   = sym<float>(g_XE);
    float* DEC  = sym<float>(g_DEC);
    float* IM   = sym<float>(g_IM);
    float* H    = sym<float>(g_H);
    float* Wc   = sym<float>(g_Wc);
    float* Eb   = sym<float>(g_Ebig);
    float* Eib  = sym<float>(g_Eibig);
    float* Wsb  = sym<float>(g_Wsbig);
    float* W1b  = sym<float>(g_W1big);
    float* W2b  = sym<float>(g_W2big);
    float* xm   = sym<float>(g_xmean);
    float* flux = sym<float>(g_flux);
    float* src  = sym<float>(g_src);
    float* gate = sym<float>(g_gate);
    float* OD   = sym<float>(g_OD);
    float* OF   = sym<float>(g_OF);

    // ---- build big weight matrices ----
    for (int l = 0; l < LL; l++) {
        int nE = 2 * DD * 2 * DD;
        build_cbig_k<<<nE / 256, 256>>>(Eb + (size_t)l * C2 * C2, E_re + (size_t)l * DD * DD,
                                        E_im + (size_t)l * DD * DD, DD, DD);
        build_cbig_k<<<nE / 256, 256>>>(Eib + (size_t)l * C2 * C2, Ei_re + (size_t)l * DD * DD,
                                        Ei_im + (size_t)l * DD * DD, DD, DD);
        build_cbig_k<<<nE / 256, 256>>>(Wsb + (size_t)l * C2 * C2, Ws_re + (size_t)l * DD * DD,
                                        Ws_im + (size_t)l * DD * DD, DD, DD);
        int n1 = 2 * DD * 2 * DFF;
        build_cbig_k<<<n1 / 256, 256>>>(W1b + (size_t)l * C2 * DFF2, w1_re + (size_t)l * DD * DFF,
                                        w1_im + (size_t)l * DD * DFF, DD, DFF);
        build_cbig_k<<<n1 / 256, 256>>>(W2b + (size_t)l * DFF2 * C2, w2_re + (size_t)l * DFF * DD,
                                        w2_im + (size_t)l * DFF * DD, DFF, DD);
    }
    build_convw_k<<<(LL * KC * C2) / 256, 256>>>(Wc, cw);

    // ---- encoder: patch-embed GEMM ----
    enc_im2col_k<<<(NP * KENC) / 256, 256>>>(IM, x);
    run_sgemm(IM, enc_w, Z, enc_b, NP, C2, KENC, 4);  // NT + bias -> Z [re|im]

    for (int l = 0; l < LL; l++) {
        // spatial mixing: LN -> conv3x3 (+residual into Z)
        layernorm_k<<<NP, 256>>>(Z, ns_g + l * C2, ns_b + l * C2, A1);
        conv_im2col_k<<<((size_t)NP * KC) / 256, 256>>>(IM, A1);
        run_sgemm(IM, Wc + (size_t)l * KC * C2, Z, cb + l * C2, NP, C2, KC, 1);  // Z += conv + cb

        // spectral: x_eig = Z @ E
        run_sgemm(Z, Eb + (size_t)l * C2 * C2, XE, nullptr, NP, C2, C2, 0);

        // temporal flux path
        rowmean_k<<<BT, C2>>>(XE, xm);
        fluxscan_k<<<6, 256>>>(xm, dt, lamflux + l * DD, Wg + l * DD, flux, gate);
        gemm_small_k<<<(BT * C2) / 256, 256>>>(flux, Wsb + (size_t)l * C2 * C2, src, BT, C2, C2);
        opdecay_k<<<(BT * DD) / 256, 256>>>(dt, nu + l * DD, omega + l * DD, OD, OF);
        forcing_k<<<(NP * DD) / 256, 256>>>(XE, gate, src, OF);
        uscan_k<<<(BB * 256 * DD) / 256, 256>>>(XE, OD);

        // decode back: DEC = u_out @ Ei
        run_sgemm(XE, Eib + (size_t)l * C2 * C2, DEC, nullptr, NP, C2, C2, 0);

        // MLP branch on LN(DEC), residual into DEC, then Z += DEC
        layernorm_k<<<NP, 256>>>(DEC, nt_g + l * C2, nt_b + l * C2, A1);
        run_sgemm(A1, W1b + (size_t)l * C2 * DFF2, H, nullptr, NP, DFF2, C2, 2);   // gelu
        run_sgemm(H, W2b + (size_t)l * DFF2 * C2, DEC, nullptr, NP, C2, DFF2, 3);  // DEC += delta
        zadd_k<<<(NP * C2) / 256, 256>>>(Z, DEC);
    }

    // ---- decoder GEMM + pixel-shuffle scatter ----
    run_sgemm(Z, dec_w, H, dec_b, NP, NDEC, C2, 4);  // NT + bias -> Ylin in H
    scatter_k<<<(BT * 4 * 256 * 256) / 256, 256>>>(out, H);

    (void)in_sizes; (void)n_in; (void)out_size;
}

// round 6
// speedup vs baseline: 1.8085x; 1.8085x over previous
#include <cuda_runtime.h>
#include <cuda_bf16.h>
#include <math.h>
#include <stdint.h>

// ---------------- constants ----------------
#define BB 4
#define TT 12
#define BT 48
#define DD 384
#define C2 768
#define NP 12288
#define KC 6912
#define DFF 1536
#define DFF2 3072
#define KENC 1024
#define NDEC 1024
#define LL 4

typedef __nv_bfloat16 bf16;

// ---------------- device scratch ----------------
__device__ float g_Z[(size_t)NP * C2];
__device__ float g_A1[(size_t)NP * C2];
__device__ float g_XE[(size_t)NP * C2];
__device__ float g_DEC[(size_t)NP * C2];
__device__ float g_Y[(size_t)NP * NDEC];
__device__ bf16 g_IM0[(size_t)NP * KC];
__device__ bf16 g_IM1[(size_t)NP * KC];
__device__ bf16 g_Ab0[(size_t)NP * C2];
__device__ bf16 g_Ab1[(size_t)NP * C2];
__device__ bf16 g_Hb0[(size_t)NP * DFF2];
__device__ bf16 g_Hb1[(size_t)NP * DFF2];
__device__ bf16 g_Wcb0[(size_t)LL * C2 * KC];
__device__ bf16 g_Wcb1[(size_t)LL * C2 * KC];
__device__ bf16 g_Eb0[(size_t)LL * C2 * C2];
__device__ bf16 g_Eb1[(size_t)LL * C2 * C2];
__device__ bf16 g_Eib0[(size_t)LL * C2 * C2];
__device__ bf16 g_Eib1[(size_t)LL * C2 * C2];
__device__ bf16 g_W1b0[(size_t)LL * DFF2 * C2];   // [N=3072][K=768]
__device__ bf16 g_W1b1[(size_t)LL * DFF2 * C2];
__device__ bf16 g_W2b0[(size_t)LL * C2 * DFF2];   // [N=768][K=3072]
__device__ bf16 g_W2b1[(size_t)LL * C2 * DFF2];
__device__ bf16 g_encb0[C2 * KENC];
__device__ bf16 g_encb1[C2 * KENC];
__device__ bf16 g_decb0[NDEC * C2];
__device__ bf16 g_decb1[NDEC * C2];
__device__ float g_Wsbig[(size_t)LL * C2 * C2];
__device__ float g_xmean[BT * C2];
__device__ float g_flux[BT * C2];
__device__ float g_src[BT * C2];
__device__ float g_gate[BT * DD];
__device__ float g_OD[BT * C2];
__device__ float g_OF[BT * C2];

// ---------------- helpers ----------------
__device__ __forceinline__ float softplus_f(float x) {
    return (x > 20.f) ? x : log1pf(expf(x));
}
__device__ __forceinline__ float gelu_tanh(float x) {
    float x3 = x * x * x;
    float t = tanhf(0.7978845608028654f * (x + 0.044715f * x3));
    return 0.5f * x * (1.f + t);
}
__device__ __forceinline__ uint32_t smem_u32(const void* p) {
    uint32_t a;
    asm("{ .reg .u64 t; cvta.to.shared.u64 t, %1; cvt.u32.u64 %0, t; }" : "=r"(a) : "l"(p));
    return a;
}

__device__ __forceinline__ void cp16(uint32_t dst, const void* src) {
    asm volatile("cp.async.cg.shared.global [%0], [%1], 16;" :: "r"(dst), "l"(src) : "memory");
}
#define CP_COMMIT() asm volatile("cp.async.commit_group;" ::: "memory")
#define CP_WAIT0() asm volatile("cp.async.wait_group 0;" ::: "memory")
#define CP_WAIT1() asm volatile("cp.async.wait_group 1;" ::: "memory")

#define LDSM4(r, addr) \
    asm volatile("ldmatrix.sync.aligned.m8n8.x4.shared.b16 {%0,%1,%2,%3}, [%4];" \
                 : "=r"((r)[0]), "=r"((r)[1]), "=r"((r)[2]), "=r"((r)[3]) : "r"(addr))

#define MMA16816(d, a, bb0, bb1) \
    asm volatile("mma.sync.aligned.m16n8k16.row.col.f32.bf16.bf16.f32 " \
                 "{%0,%1,%2,%3}, {%4,%5,%6,%7}, {%8,%9}, {%0,%1,%2,%3};" \
                 : "+f"((d)[0]), "+f"((d)[1]), "+f"((d)[2]), "+f"((d)[3]) \
                 : "r"((a)[0]), "r"((a)[1]), "r"((a)[2]), "r"((a)[3]), \
                   "r"(bb0), "r"(bb1))

// ---------------- warp-MMA bf16 GEMM ----------------
// C[M=12288, N] = A @ B^T with 2-way bf16 split: A0B0 + A1B0 + A0B1.
// A0/A1: [M][K] bf16 row-major; B0/B1: [N][K] bf16 row-major. K % 32 == 0.
// Block tile 128x128x32, 8 warps (4M x 2N), warp tile 32x64.
// smem per stage: 4 matrices x 128 rows x 80B (32 bf16 + 8 pad) = 40960B.
// MODE: 0 store, 1 store+bias, 2 acc, 3 acc+bias, 4 gelu->bf16-split (C0,C1)
#define MAT_BYTES 10240
#define STAGE_B 40960
#define SMEM_TOTAL_G (2 * STAGE_B)

template <int MODE>
__global__ __launch_bounds__(256) void hgemm_k(
    const bf16* __restrict__ A0, const bf16* __restrict__ A1,
    const bf16* __restrict__ B0, const bf16* __restrict__ B1,
    float* __restrict__ C, bf16* __restrict__ C0, bf16* __restrict__ C1,
    const float* __restrict__ bias, int N, int K)
{
    extern __shared__ char smem[];
    uint32_t sb = smem_u32(smem);
    const int tid = threadIdx.x;
    const int wid = tid >> 5;
    const int lane = tid & 31;
    const int m0 = blockIdx.x * 128;
    const int n0 = blockIdx.y * 128;
    const int wm = wid & 3;       // 0..3 (M)
    const int wn = wid >> 2;      // 0..1 (N)

    const bf16* srcs[4];
    srcs[0] = A0 + (size_t)m0 * K;
    srcs[1] = A1 + (size_t)m0 * K;
    srcs[2] = B0 + (size_t)n0 * K;
    srcs[3] = B1 + (size_t)n0 * K;

    auto load_chunk = [&](int k0, int buf) {
        uint32_t st = sb + buf * STAGE_B;
#pragma unroll
        for (int i = 0; i < 8; i++) {
            int id = tid + 256 * i;
            int mat = id >> 9;            // constant per i
            int cid = id & 511;
            int row = cid >> 2, c4 = cid & 3;
            uint32_t dst = st + mat * MAT_BYTES + row * 80 + c4 * 16;
            cp16(dst, srcs[mat] + (size_t)row * K + k0 + c4 * 8);
        }
    };

    float acc[2][8][4];
#pragma unroll
    for (int i = 0; i < 2; i++)
#pragma unroll
        for (int j = 0; j < 8; j++)
#pragma unroll
            for (int e = 0; e < 4; e++) acc[i][j][e] = 0.f;

    const int nc = K >> 5;
    load_chunk(0, 0);
    CP_COMMIT();

    const int lrow = lane & 15;
    const int lcol = lane >> 4;

    for (int c = 0; c < nc; c++) {
        int buf = c & 1;
        if (c + 1 < nc) {
            load_chunk((c + 1) << 5, buf ^ 1);
            CP_COMMIT();
            CP_WAIT1();
        } else {
            CP_WAIT0();
        }
        __syncthreads();
        uint32_t st = sb + buf * STAGE_B;
#pragma unroll
        for (int ks = 0; ks < 2; ks++) {
            uint32_t a0[2][4], a1[2][4], b0r[4][4], b1r[4][4];
#pragma unroll
            for (int mi = 0; mi < 2; mi++) {
                uint32_t ad = st + (wm * 32 + mi * 16 + lrow) * 80 + ks * 32 + lcol * 16;
                LDSM4(a0[mi], ad);
                LDSM4(a1[mi], ad + MAT_BYTES);
            }
#pragma unroll
            for (int nq = 0; nq < 4; nq++) {
                uint32_t bd = st + 2 * MAT_BYTES + (wn * 64 + nq * 16 + lrow) * 80 + ks * 32 + lcol * 16;
                LDSM4(b0r[nq], bd);
                LDSM4(b1r[nq], bd + MAT_BYTES);
            }
#pragma unroll
            for (int mi = 0; mi < 2; mi++) {
#pragma unroll
                for (int nq = 0; nq < 4; nq++) {
                    MMA16816(acc[mi][nq * 2],     a0[mi], b0r[nq][0], b0r[nq][2]);
                    MMA16816(acc[mi][nq * 2 + 1], a0[mi], b0r[nq][1], b0r[nq][3]);
                    MMA16816(acc[mi][nq * 2],     a1[mi], b0r[nq][0], b0r[nq][2]);
                    MMA16816(acc[mi][nq * 2 + 1], a1[mi], b0r[nq][1], b0r[nq][3]);
                    MMA16816(acc[mi][nq * 2],     a0[mi], b1r[nq][0], b1r[nq][2]);
                    MMA16816(acc[mi][nq * 2 + 1], a0[mi], b1r[nq][1], b1r[nq][3]);
                }
            }
        }
        __syncthreads();
    }

    // epilogue
#pragma unroll
    for (int mi = 0; mi < 2; mi++) {
#pragma unroll
        for (int nj = 0; nj < 8; nj++) {
            int row = m0 + wm * 32 + mi * 16 + (lane >> 2);
            int col = n0 + wn * 64 + nj * 8 + (lane & 3) * 2;
            float* d = acc[mi][nj];
#pragma unroll
            for (int h = 0; h < 2; h++) {   // h=0: row, h=1: row+8
                int r = row + h * 8;
                float v0 = d[h * 2 + 0], v1 = d[h * 2 + 1];
                if (MODE == 1 || MODE == 3) {
                    v0 += bias[col];
                    v1 += bias[col + 1];
                }
                size_t co = (size_t)r * N + col;
                if (MODE == 4) {
                    float gq0 = gelu_tanh(v0), gq1 = gelu_tanh(v1);
                    bf16 h0 = __float2bfloat16(gq0);
                    bf16 h1 = __float2bfloat16(gq1);
                    C0[co] = h0;
                    C0[co + 1] = h1;
                    C1[co] = __float2bfloat16(gq0 - __bfloat162float(h0));
                    C1[co + 1] = __float2bfloat16(gq1 - __bfloat162float(h1));
                } else if (MODE == 2 || MODE == 3) {
                    C[co] += v0;
                    C[co + 1] += v1;
                } else {
                    C[co] = v0;
                    C[co + 1] = v1;
                }
            }
        }
    }
}

// ---------------- tiny fp32 GEMM (M=48) ----------------
__global__ void gemm_small_k(const float* __restrict__ A, const float* __restrict__ B,
                             float* __restrict__ C, int M, int N, int K)
{
    int idx = blockIdx.x * blockDim.x + threadIdx.x;
    if (idx >= M * N) return;
    int m = idx / N, n = idx % N;
    float s = 0.f;
    for (int k = 0; k < K; k++) s += A[(size_t)m * K + k] * B[(size_t)k * N + n];
    C[idx] = s;
}

// ---------------- weight builders ----------------
__global__ void build_cbig_k(float* __restrict__ dst, const float* __restrict__ re,
                             const float* __restrict__ im, int Kd, int Nd)
{
    int idx = blockIdx.x * blockDim.x + threadIdx.x;
    int N2 = 2 * Nd;
    if (idx >= 2 * Kd * N2) return;
    int k2 = idx / N2, n2 = idx % N2;
    bool ki = k2 >= Kd, ni = n2 >= Nd;
    int k = ki ? k2 - Kd : k2;
    int n = ni ? n2 - Nd : n2;
    float v;
    if (!ki && !ni) v = re[(size_t)k * Nd + n];
    else if (!ki && ni) v = im[(size_t)k * Nd + n];
    else if (ki && !ni) v = -im[(size_t)k * Nd + n];
    else v = re[(size_t)k * Nd + n];
    dst[idx] = v;
}

// transposed big as bf16 splits: dst[n2][k2] = big[k2][n2]
__global__ void build_cbigT_split_k(bf16* __restrict__ d0, bf16* __restrict__ d1,
                                    const float* __restrict__ re, const float* __restrict__ im,
                                    int Kd, int Nd)
{
    int idx = blockIdx.x * blockDim.x + threadIdx.x;
    int K2 = 2 * Kd;
    if (idx >= 2 * Nd * K2) return;
    int n2 = idx / K2, k2 = idx % K2;
    bool ki = k2 >= Kd, ni = n2 >= Nd;
    int k = ki ? k2 - Kd : k2;
    int n = ni ? n2 - Nd : n2;
    float v;
    if (!ki && !ni) v = re[(size_t)k * Nd + n];
    else if (!ki && ni) v = im[(size_t)k * Nd + n];
    else if (ki && !ni) v = -im[(size_t)k * Nd + n];
    else v = re[(size_t)k * Nd + n];
    bf16 h = __float2bfloat16(v);
    d0[idx] = h;
    d1[idx] = __float2bfloat16(v - __bfloat162float(h));
}

__global__ void build_convwT_split_k(bf16* __restrict__ d0, bf16* __restrict__ d1,
                                     const float* __restrict__ cw)
{
    size_t idx = (size_t)blockIdx.x * blockDim.x + threadIdx.x;
    if (idx >= (size_t)LL * C2 * KC) return;
    int k = idx % KC;
    int co = (idx / KC) % C2;
    int l = idx / ((size_t)KC * C2);
    int ci = k % C2;
    int rs = k / C2;
    float v = cw[(((size_t)(l * C2 + co) * C2 + ci) * 9) + rs];
    bf16 h = __float2bfloat16(v);
    d0[idx] = h;
    d1[idx] = __float2bfloat16(v - __bfloat162float(h));
}

__global__ void split_k(const float* __restrict__ src, bf16* __restrict__ d0,
                        bf16* __restrict__ d1, size_t n)
{
    size_t idx = (size_t)blockIdx.x * blockDim.x + threadIdx.x;
    if (idx >= n) return;
    float v = src[idx];
    bf16 h = __float2bfloat16(v);
    d0[idx] = h;
    d1[idx] = __float2bfloat16(v - __bfloat162float(h));
}

// ---------------- im2col (bf16 split outputs) ----------------
__global__ void enc_im2col_split_k(bf16* __restrict__ P0, bf16* __restrict__ P1,
                                   const float* __restrict__ x)
{
    size_t idx = (size_t)blockIdx.x * blockDim.x + threadIdx.x;
    int kk = idx % KENC;
    int n = idx / KENC;
    int cin = kk / 256;
    int ii = (kk / 16) % 16;
    int jj = kk % 16;
    int bt = n / 256;
    int ph = (n / 16) % 16;
    int pw = n % 16;
    float v = x[(((size_t)(bt * 4 + cin) * 256) + ph * 16 + ii) * 256 + pw * 16 + jj];
    bf16 h = __float2bfloat16(v);
    P0[idx] = h;
    P1[idx] = __float2bfloat16(v - __bfloat162float(h));
}

__global__ void conv_im2col_split_k(bf16* __restrict__ IM0, bf16* __restrict__ IM1,
                                    const float* __restrict__ A)
{
    size_t idx = (size_t)blockIdx.x * blockDim.x + threadIdx.x;
    if (idx >= (size_t)NP * KC) return;
    int k = idx % KC;
    int n = idx / KC;
    int ci = k % C2;
    int rs = k / C2;
    int dy = rs / 3 - 1;
    int dx = rs % 3 - 1;
    int bt = n / 256;
    int h = (n / 16) % 16;
    int w = n % 16;
    int hh = h + dy, ww = w + dx;
    float v = 0.f;
    if (hh >= 0 && hh < 16 && ww >= 0 && ww < 16)
        v = A[((size_t)(bt * 256 + hh * 16 + ww)) * C2 + ci];
    bf16 hi = __float2bfloat16(v);
    IM0[idx] = hi;
    IM1[idx] = __float2bfloat16(v - __bfloat162float(hi));
}

// ---------------- layernorm over 768 channels ----------------
template <bool SPLIT>
__global__ void layernorm_k(const float* __restrict__ X, const float* __restrict__ g,
                            const float* __restrict__ b, float* __restrict__ Y,
                            bf16* __restrict__ Y0, bf16* __restrict__ Y1)
{
    __shared__ float red[256];
    int n = blockIdx.x;
    int tid = threadIdx.x;
    const float* x = X + (size_t)n * C2;
    float v0 = x[tid], v1 = x[tid + 256], v2 = x[tid + 512];
    red[tid] = v0 + v1 + v2;
    __syncthreads();
    for (int off = 128; off > 0; off >>= 1) {
        if (tid < off) red[tid] += red[tid + off];
        __syncthreads();
    }
    float m = red[0] * (1.f / 768.f);
    __syncthreads();
    float d0 = v0 - m, d1 = v1 - m, d2 = v2 - m;
    red[tid] = d0 * d0 + d1 * d1 + d2 * d2;
    __syncthreads();
    for (int off = 128; off > 0; off >>= 1) {
        if (tid < off) red[tid] += red[tid + off];
        __syncthreads();
    }
    float var = red[0] * (1.f / 768.f);
    float rstd = rsqrtf(var + 1e-5f);
    float o0 = d0 * rstd * g[tid] + b[tid];
    float o1 = d1 * rstd * g[tid + 256] + b[tid + 256];
    float o2 = d2 * rstd * g[tid + 512] + b[tid + 512];
    if (SPLIT) {
        size_t base = (size_t)n * C2;
        bf16 h0 = __float2bfloat16(o0);
        bf16 h1 = __float2bfloat16(o1);
        bf16 h2 = __float2bfloat16(o2);
        Y0[base + tid] = h0;
        Y0[base + tid + 256] = h1;
        Y0[base + tid + 512] = h2;
        Y1[base + tid] = __float2bfloat16(o0 - __bfloat162float(h0));
        Y1[base + tid + 256] = __float2bfloat16(o1 - __bfloat162float(h1));
        Y1[base + tid + 512] = __float2bfloat16(o2 - __bfloat162float(h2));
    } else {
        float* y = Y + (size_t)n * C2;
        y[tid] = o0;
        y[tid + 256] = o1;
        y[tid + 512] = o2;
    }
}

// ---------------- mean over 256 spatial positions ----------------
__global__ void rowmean_k(const float* __restrict__ XE, float* __restrict__ xm)
{
    int bt = blockIdx.x;
    int c = threadIdx.x;
    float s = 0.f;
    const float* p = XE + (size_t)bt * 256 * C2 + c;
    for (int hw = 0; hw < 256; hw++) s += p[(size_t)hw * C2];
    xm[bt * C2 + c] = s * (1.f / 256.f);
}

// ---------------- flux scan + gate ----------------
__global__ void fluxscan_k(const float* __restrict__ xm, const float* __restrict__ dt,
                           const float* __restrict__ lamf_p, const float* __restrict__ Wg,
                           float* __restrict__ flux, float* __restrict__ gate)
{
    int tid = blockIdx.x * blockDim.x + threadIdx.x;
    int b = tid / DD, e = tid % DD;
    float lamf = softplus_f(lamf_p[e]);
    float wg = Wg[e];
    float fr = 0.f, fi = 0.f;
    for (int t = 0; t < TT; t++) {
        int bt = b * TT + t;
        float dtv = dt[bt];
        float a = expf(-lamf * dtv);
        float xr = xm[bt * C2 + e] * dtv;
        float xi = xm[bt * C2 + DD + e] * dtv;
        fr = fr * a + xr;
        fi = fi * a + xi;
        flux[bt * C2 + e] = fr;
        flux[bt * C2 + DD + e] = fi;
        gate[bt * DD + e] = 1.f / (1.f + expf(-fr * wg));
    }
}

// ---------------- op_decay / op_forcing ----------------
__global__ void opdecay_k(const float* __restrict__ dt, const float* __restrict__ nu,
                          const float* __restrict__ omega, float* __restrict__ OD,
                          float* __restrict__ OF)
{
    int idx = blockIdx.x * blockDim.x + threadIdx.x;
    int bt = idx / DD, e = idx % DD;
    float sp = softplus_f(nu[e]);
    float lr = fminf(fmaxf(-sp, -5.f), 0.3f);
    float li = omega[e];
    float dtv = dt[bt];
    float er = expf(lr * dtv);
    float odr = er * cosf(li * dtv);
    float odi = er * sinf(li * dtv);
    OD[bt * C2 + e] = odr;
    OD[bt * C2 + DD + e] = odi;
    float nr = odr - 1.f, ni = odi;
    float den = lr * lr + li * li;
    OF[bt * C2 + e] = (nr * lr + ni * li) / den;
    OF[bt * C2 + DD + e] = (ni * lr - nr * li) / den;
}

// ---------------- forcing + u_t (in place on XE) ----------------
__global__ void forcing_k(float* __restrict__ XE, const float* __restrict__ gate,
                          const float* __restrict__ src, const float* __restrict__ OF)
{
    size_t idx = (size_t)blockIdx.x * blockDim.x + threadIdx.x;
    int e = idx % DD;
    int n = idx / DD;
    int bt = n / 256;
    float g = gate[bt * DD + e];
    float sr = src[bt * C2 + e], si = src[bt * C2 + DD + e];
    size_t base = (size_t)n * C2;
    float xr = XE[base + e], xi = XE[base + DD + e];
    float fr = xr * g + sr * (1.f - g);
    float fi = xi * g + si * (1.f - g);
    float ofr = OF[bt * C2 + e], ofi = OF[bt * C2 + DD + e];
    XE[base + e] = fr * ofr - fi * ofi;
    XE[base + DD + e] = fr * ofi + fi * ofr;
}

// ---------------- u scan over T (in place on XE) ----------------
__global__ void uscan_k(float* __restrict__ XE, const float* __restrict__ OD)
{
    int tid = blockIdx.x * blockDim.x + threadIdx.x;
    int e = tid % DD;
    int hw = (tid / DD) % 256;
    int b = tid / (DD * 256);
    float ur = 0.f, ui = 0.f;
    for (int t = 0; t < TT; t++) {
        int bt = b * TT + t;
        float odr = OD[bt * C2 + e], odi = OD[bt * C2 + DD + e];
        size_t base = (size_t)(bt * 256 + hw) * C2;
        float xr = XE[base + e], xi = XE[base + DD + e];
        float nr = ur * odr - ui * odi + xr;
        float ni = ur * odi + ui * odr + xi;
        ur = nr; ui = ni;
        XE[base + e] = ur;
        XE[base + DD + e] = ui;
    }
}

__global__ void zadd_k(float* __restrict__ Z, const float* __restrict__ D_)
{
    size_t idx = (size_t)blockIdx.x * blockDim.x + threadIdx.x;
    Z[idx] += D_[idx];
}

// ---------------- output scatter ----------------
__global__ void scatter_k(float* __restrict__ out, const float* __restrict__ Y)
{
    size_t idx = (size_t)blockIdx.x * blockDim.x + threadIdx.x;
    int Wp = idx % 256;
    int Hp = (idx / 256) % 256;
    int co = (idx / 65536) % 4;
    int bt = idx / ((size_t)65536 * 4);
    int hp = Hp / 16, pi = Hp % 16;
    int wp = Wp / 16, pj = Wp % 16;
    int n = bt * 256 + hp * 16 + wp;
    int o = co * 256 + pi * 16 + pj;
    out[idx] = Y[(size_t)n * NDEC + o];
}

// ---------------- host side ----------------
template <typename T>
static T* sym(const void* s)
{
    void* p = nullptr;
    cudaGetSymbolAddress(&p, s);
    return (T*)p;
}

static void tc_gemm(int mode, const bf16* A0, const bf16* A1, const bf16* B0, const bf16* B1,
                    float* C, bf16* C0, bf16* C1, const float* bias, int N, int K)
{
    dim3 grid(NP / 128, N / 128);
    switch (mode) {
        case 0:
            cudaFuncSetAttribute(hgemm_k<0>, cudaFuncAttributeMaxDynamicSharedMemorySize, SMEM_TOTAL_G);
            hgemm_k<0><<<grid, 256, SMEM_TOTAL_G>>>(A0, A1, B0, B1, C, C0, C1, bias, N, K);
            break;
        case 1:
            cudaFuncSetAttribute(hgemm_k<1>, cudaFuncAttributeMaxDynamicSharedMemorySize, SMEM_TOTAL_G);
            hgemm_k<1><<<grid, 256, SMEM_TOTAL_G>>>(A0, A1, B0, B1, C, C0, C1, bias, N, K);
            break;
        case 2:
            cudaFuncSetAttribute(hgemm_k<2>, cudaFuncAttributeMaxDynamicSharedMemorySize, SMEM_TOTAL_G);
            hgemm_k<2><<<grid, 256, SMEM_TOTAL_G>>>(A0, A1, B0, B1, C, C0, C1, bias, N, K);
            break;
        case 3:
            cudaFuncSetAttribute(hgemm_k<3>, cudaFuncAttributeMaxDynamicSharedMemorySize, SMEM_TOTAL_G);
            hgemm_k<3><<<grid, 256, SMEM_TOTAL_G>>>(A0, A1, B0, B1, C, C0, C1, bias, N, K);
            break;
        case 4:
            cudaFuncSetAttribute(hgemm_k<4>, cudaFuncAttributeMaxDynamicSharedMemorySize, SMEM_TOTAL_G);
            hgemm_k<4><<<grid, 256, SMEM_TOTAL_G>>>(A0, A1, B0, B1, C, C0, C1, bias, N, K);
            break;
    }
}

extern "C" void kernel_launch(void* const* d_in, const int* in_sizes, int n_in,
                              void* d_out, int out_size)
{
    const float* x       = (const float*)d_in[0];
    const float* dt      = (const float*)d_in[1];
    const float* enc_w   = (const float*)d_in[2];
    const float* enc_b   = (const float*)d_in[3];
    const float* ns_g    = (const float*)d_in[4];
    const float* ns_b    = (const float*)d_in[5];
    const float* cw      = (const float*)d_in[6];
    const float* cb      = (const float*)d_in[7];
    const float* nt_g    = (const float*)d_in[8];
    const float* nt_b    = (const float*)d_in[9];
    const float* E_re    = (const float*)d_in[10];
    const float* E_im    = (const float*)d_in[11];
    const float* Ei_re   = (const float*)d_in[12];
    const float* Ei_im   = (const float*)d_in[13];
    const float* lamflux = (const float*)d_in[14];
    const float* Ws_re   = (const float*)d_in[15];
    const float* Ws_im   = (const float*)d_in[16];
    const float* Wg      = (const float*)d_in[17];
    const float* nu      = (const float*)d_in[18];
    const float* omega   = (const float*)d_in[19];
    const float* w1_re   = (const float*)d_in[20];
    const float* w1_im   = (const float*)d_in[21];
    const float* w2_re   = (const float*)d_in[22];
    const float* w2_im   = (const float*)d_in[23];
    const float* dec_w   = (const float*)d_in[24];
    const float* dec_b   = (const float*)d_in[25];
    float* out = (float*)d_out;

    float* Z   = sym<float>(g_Z);
    float* A1f = sym<float>(g_A1);
    float* XE  = sym<float>(g_XE);
    float* DEC = sym<float>(g_DEC);
    float* Y   = sym<float>(g_Y);
    bf16* IM0  = sym<bf16>(g_IM0);
    bf16* IM1  = sym<bf16>(g_IM1);
    bf16* Ab0  = sym<bf16>(g_Ab0);
    bf16* Ab1  = sym<bf16>(g_Ab1);
    bf16* Hb0  = sym<bf16>(g_Hb0);
    bf16* Hb1  = sym<bf16>(g_Hb1);
    bf16* Wcb0 = sym<bf16>(g_Wcb0);
    bf16* Wcb1 = sym<bf16>(g_Wcb1);
    bf16* Eb0  = sym<bf16>(g_Eb0);
    bf16* Eb1  = sym<bf16>(g_Eb1);
    bf16* Eib0 = sym<bf16>(g_Eib0);
    bf16* Eib1 = sym<bf16>(g_Eib1);
    bf16* W1b0 = sym<bf16>(g_W1b0);
    bf16* W1b1 = sym<bf16>(g_W1b1);
    bf16* W2b0 = sym<bf16>(g_W2b0);
    bf16* W2b1 = sym<bf16>(g_W2b1);
    bf16* encb0 = sym<bf16>(g_encb0);
    bf16* encb1 = sym<bf16>(g_encb1);
    bf16* decb0 = sym<bf16>(g_decb0);
    bf16* decb1 = sym<bf16>(g_decb1);
    float* Wsb  = sym<float>(g_Wsbig);
    float* xm   = sym<float>(g_xmean);
    float* flux = sym<float>(g_flux);
    float* src  = sym<float>(g_src);
    float* gate = sym<float>(g_gate);
    float* OD   = sym<float>(g_OD);
    float* OF   = sym<float>(g_OF);

    // ---- build weights ----
    for (int l = 0; l < LL; l++) {
        int nE = C2 * C2;
        build_cbigT_split_k<<<nE / 256, 256>>>(Eb0 + (size_t)l * nE, Eb1 + (size_t)l * nE,
                                               E_re + (size_t)l * DD * DD, E_im + (size_t)l * DD * DD, DD, DD);
        build_cbigT_split_k<<<nE / 256, 256>>>(Eib0 + (size_t)l * nE, Eib1 + (size_t)l * nE,
                                               Ei_re + (size_t)l * DD * DD, Ei_im + (size_t)l * DD * DD, DD, DD);
        build_cbig_k<<<nE / 256, 256>>>(Wsb + (size_t)l * nE,
                                        Ws_re + (size_t)l * DD * DD, Ws_im + (size_t)l * DD * DD, DD, DD);
        int n1 = DFF2 * C2;
        build_cbigT_split_k<<<n1 / 256, 256>>>(W1b0 + (size_t)l * n1, W1b1 + (size_t)l * n1,
                                               w1_re + (size_t)l * DD * DFF, w1_im + (size_t)l * DD * DFF, DD, DFF);
        build_cbigT_split_k<<<n1 / 256, 256>>>(W2b0 + (size_t)l * n1, W2b1 + (size_t)l * n1,
                                               w2_re + (size_t)l * DFF * DD, w2_im + (size_t)l * DFF * DD, DFF, DD);
    }
    build_convwT_split_k<<<((size_t)LL * C2 * KC + 255) / 256, 256>>>(Wcb0, Wcb1, cw);
    split_k<<<(C2 * KENC) / 256, 256>>>(enc_w, encb0, encb1, (size_t)C2 * KENC);
    split_k<<<(NDEC * C2) / 256, 256>>>(dec_w, decb0, decb1, (size_t)NDEC * C2);

    // ---- encoder ----
    enc_im2col_split_k<<<((size_t)NP * KENC) / 256, 256>>>(IM0, IM1, x);
    tc_gemm(1, IM0, IM1, encb0, encb1, Z, nullptr, nullptr, enc_b, C2, KENC);

    for (int l = 0; l < LL; l++) {
        // spatial: LN -> conv3x3 (+residual into Z)
        layernorm_k<false><<<NP, 256>>>(Z, ns_g + l * C2, ns_b + l * C2, A1f, nullptr, nullptr);
        conv_im2col_split_k<<<((size_t)NP * KC + 255) / 256, 256>>>(IM0, IM1, A1f);
        tc_gemm(3, IM0, IM1, Wcb0 + (size_t)l * C2 * KC, Wcb1 + (size_t)l * C2 * KC,
                Z, nullptr, nullptr, cb + l * C2, C2, KC);

        // spectral: XE = Z @ E
        split_k<<<((size_t)NP * C2) / 256, 256>>>(Z, Ab0, Ab1, (size_t)NP * C2);
        tc_gemm(0, Ab0, Ab1, Eb0 + (size_t)l * C2 * C2, Eb1 + (size_t)l * C2 * C2,
                XE, nullptr, nullptr, nullptr, C2, C2);

        // temporal flux path
        rowmean_k<<<BT, C2>>>(XE, xm);
        fluxscan_k<<<6, 256>>>(xm, dt, lamflux + l * DD, Wg + l * DD, flux, gate);
        gemm_small_k<<<(BT * C2) / 256, 256>>>(flux, Wsb + (size_t)l * C2 * C2, src, BT, C2, C2);
        opdecay_k<<<(BT * DD) / 256, 256>>>(dt, nu + l * DD, omega + l * DD, OD, OF);
        forcing_k<<<((size_t)NP * DD) / 256, 256>>>(XE, gate, src, OF);
        uscan_k<<<(BB * 256 * DD) / 256, 256>>>(XE, OD);

        // decode back: DEC = u_out @ Ei
        split_k<<<((size_t)NP * C2) / 256, 256>>>(XE, Ab0, Ab1, (size_t)NP * C2);
        tc_gemm(0, Ab0, Ab1, Eib0 + (size_t)l * C2 * C2, Eib1 + (size_t)l * C2 * C2,
                DEC, nullptr, nullptr, nullptr, C2, C2);

        // MLP branch on LN(DEC), residual into DEC, then Z += DEC
        layernorm_k<true><<<NP, 256>>>(DEC, nt_g + l * C2, nt_b + l * C2, nullptr, Ab0, Ab1);
        tc_gemm(4, Ab0, Ab1, W1b0 + (size_t)l * DFF2 * C2, W1b1 + (size_t)l * DFF2 * C2,
                nullptr, Hb0, Hb1, nullptr, DFF2, C2);
        tc_gemm(2, Hb0, Hb1, W2b0 + (size_t)l * C2 * DFF2, W2b1 + (size_t)l * C2 * DFF2,
                DEC, nullptr, nullptr, nullptr, C2, DFF2);
        zadd_k<<<((size_t)NP * C2) / 256, 256>>>(Z, DEC);
    }

    // ---- decoder + pixel shuffle ----
    split_k<<<((size_t)NP * C2) / 256, 256>>>(Z, Ab0, Ab1, (size_t)NP * C2);
    tc_gemm(1, Ab0, Ab1, decb0, decb1, Y, nullptr, nullptr, dec_b, NDEC, C2);
    scatter_k<<<((size_t)BT * 4 * 256 * 256) / 256, 256>>>(out, Y);

    (void)in_sizes; (void)n_in; (void)out_size;
}

// round 8
// speedup vs baseline: 2.0999x; 1.1611x over previous
#include <cuda_runtime.h>
#include <cuda_bf16.h>
#include <math.h>
#include <stdint.h>

// ---------------- constants ----------------
#define BB 4
#define TT 12
#define BT 48
#define DD 384
#define C2 768
#define NP 12288
#define KC 6912
#define DFF 1536
#define DFF2 3072
#define KENC 1024
#define NDEC 1024
#define LL 4

typedef __nv_bfloat16 bf16;

// ---------------- device scratch ----------------
__device__ float g_Z[(size_t)NP * C2];
__device__ float g_XE[(size_t)NP * C2];
__device__ float g_DEC[(size_t)NP * C2];
__device__ bf16 g_IM0[(size_t)NP * KENC];
__device__ bf16 g_IM1[(size_t)NP * KENC];
__device__ bf16 g_Ab0[(size_t)NP * C2];
__device__ bf16 g_Ab1[(size_t)NP * C2];
__device__ bf16 g_Zb0[(size_t)NP * C2];
__device__ bf16 g_Zb1[(size_t)NP * C2];
__device__ bf16 g_Hb0[(size_t)NP * DFF2];
__device__ bf16 g_Hb1[(size_t)NP * DFF2];
__device__ bf16 g_Wcb0[(size_t)LL * C2 * KC];
__device__ bf16 g_Wcb1[(size_t)LL * C2 * KC];
__device__ bf16 g_Eb0[(size_t)LL * C2 * C2];
__device__ bf16 g_Eb1[(size_t)LL * C2 * C2];
__device__ bf16 g_Eib0[(size_t)LL * C2 * C2];
__device__ bf16 g_Eib1[(size_t)LL * C2 * C2];
__device__ bf16 g_W1b0[(size_t)LL * DFF2 * C2];   // [N=3072][K=768]
__device__ bf16 g_W1b1[(size_t)LL * DFF2 * C2];
__device__ bf16 g_W2b0[(size_t)LL * C2 * DFF2];   // [N=768][K=3072]
__device__ bf16 g_W2b1[(size_t)LL * C2 * DFF2];
__device__ bf16 g_encb0[C2 * KENC];
__device__ bf16 g_encb1[C2 * KENC];
__device__ bf16 g_decb0[NDEC * C2];
__device__ bf16 g_decb1[NDEC * C2];
__device__ float g_Wsbig[(size_t)LL * C2 * C2];
__device__ float g_xmean[BT * C2];
__device__ float g_flux[BT * C2];
__device__ float g_src[BT * C2];
__device__ float g_gate[BT * DD];
__device__ float g_OD[BT * C2];
__device__ float g_OF[BT * C2];

// ---------------- helpers ----------------
__device__ __forceinline__ float softplus_f(float x) {
    return (x > 20.f) ? x : log1pf(expf(x));
}
__device__ __forceinline__ float gelu_tanh(float x) {
    float x3 = x * x * x;
    float t = tanhf(0.7978845608028654f * (x + 0.044715f * x3));
    return 0.5f * x * (1.f + t);
}
__device__ __forceinline__ uint32_t smem_u32(const void* p) {
    uint32_t a;
    asm("{ .reg .u64 t; cvta.to.shared.u64 t, %1; cvt.u32.u64 %0, t; }" : "=r"(a) : "l"(p));
    return a;
}
__device__ __forceinline__ void cp16(uint32_t dst, const void* src) {
    asm volatile("cp.async.cg.shared.global [%0], [%1], 16;" :: "r"(dst), "l"(src) : "memory");
}
__device__ __forceinline__ void cp16z(uint32_t dst, const void* src, uint32_t sz) {
    asm volatile("cp.async.cg.shared.global [%0], [%1], 16, %2;" :: "r"(dst), "l"(src), "r"(sz) : "memory");
}
#define CP_COMMIT() asm volatile("cp.async.commit_group;" ::: "memory")
#define CP_WAIT0() asm volatile("cp.async.wait_group 0;" ::: "memory")
#define CP_WAIT1() asm volatile("cp.async.wait_group 1;" ::: "memory")

#define LDSM4(r, addr) \
    asm volatile("ldmatrix.sync.aligned.m8n8.x4.shared.b16 {%0,%1,%2,%3}, [%4];" \
                 : "=r"((r)[0]), "=r"((r)[1]), "=r"((r)[2]), "=r"((r)[3]) : "r"(addr))

#define MMA16816(d, a, bb0, bb1) \
    asm volatile("mma.sync.aligned.m16n8k16.row.col.f32.bf16.bf16.f32 " \
                 "{%0,%1,%2,%3}, {%4,%5,%6,%7}, {%8,%9}, {%0,%1,%2,%3};" \
                 : "+f"((d)[0]), "+f"((d)[1]), "+f"((d)[2]), "+f"((d)[3]) \
                 : "r"((a)[0]), "r"((a)[1]), "r"((a)[2]), "r"((a)[3]), \
                   "r"(bb0), "r"(bb1))

// ---------------- warp-MMA bf16 GEMM ----------------
// C[M=12288, N] = A @ B^T with 2-way bf16 split: A0B0 + A1B0 + A0B1.
// Block tile 256x128x32, 8 warps (4M x 2N), warp tile 64x64.
// smem per stage: A 2x(256x80B) + B 2x(128x80B) = 61440B; 2 stages = 120KB.
// grid: x = N/128 (fast -> A tile L2 reuse), y = M/256.
// MODE: 0 store, 1 store+bias, 3 acc+bias+split-emit, 4 gelu->split, 6 Z-fuse, 7 dec-scatter
// CONV: A-loader does implicit 3x3 im2col from Ab [NP][C2] (K = 9*768).
#define MATA_B 20480
#define MATB_B 10240
#define STAGE_B 61440
#define SMEM_TOTAL_G (2 * STAGE_B)

template <int MODE, bool CONV>
__global__ __launch_bounds__(256) void hgemm_k(
    const bf16* __restrict__ A0, const bf16* __restrict__ A1,
    const bf16* __restrict__ B0, const bf16* __restrict__ B1,
    float* __restrict__ C, bf16* __restrict__ C0, bf16* __restrict__ C1,
    const float* __restrict__ Caux, const float* __restrict__ bias, int N, int K)
{
    extern __shared__ char smem[];
    uint32_t sb = smem_u32(smem);
    const int tid = threadIdx.x;
    const int wid = tid >> 5;
    const int lane = tid & 31;
    const int n0 = blockIdx.x * 128;
    const int m0 = blockIdx.y * 256;
    const int wm = wid & 3;       // 0..3 (M, x64)
    const int wn = wid >> 2;      // 0..1 (N, x64)

    auto load_chunk = [&](int k0, int buf) {
        uint32_t st = sb + buf * STAGE_B;
        // A: 2 mats x 256 rows x 4 vecs = 2048
#pragma unroll
        for (int i = 0; i < 8; i++) {
            int id = tid + 256 * i;
            int mat = id >> 10;
            int cid = id & 1023;
            int row = cid >> 2, c4 = cid & 3;
            uint32_t dst = st + mat * MATA_B + row * 80 + c4 * 16;
            const bf16* Asrc = mat ? A1 : A0;
            if (CONV) {
                int kk = k0 + c4 * 8;
                int rs = kk / 768;
                int ci = kk - rs * 768;
                int dy = rs / 3 - 1, dx = rs - (rs / 3) * 3 - 1;
                int m = m0 + row;
                int bt = m >> 8;
                int h = (m >> 4) & 15, w = m & 15;
                int hh = h + dy, ww = w + dx;
                bool ok = ((unsigned)hh < 16u) && ((unsigned)ww < 16u);
                const bf16* sp = Asrc + ((size_t)((bt << 8) + (hh << 4) + ww) * 768 + ci);
                if (!ok) sp = Asrc;
                cp16z(dst, sp, ok ? 16u : 0u);
            } else {
                cp16(dst, Asrc + (size_t)(m0 + row) * K + k0 + c4 * 8);
            }
        }
        // B: 2 mats x 128 rows x 4 vecs = 1024
#pragma unroll
        for (int i = 0; i < 4; i++) {
            int id = tid + 256 * i;
            int mat = id >> 9;
            int cid = id & 511;
            int row = cid >> 2, c4 = cid & 3;
            uint32_t dst = st + 2 * MATA_B + mat * MATB_B + row * 80 + c4 * 16;
            const bf16* Bsrc = mat ? B1 : B0;
            cp16(dst, Bsrc + (size_t)(n0 + row) * K + k0 + c4 * 8);
        }
    };

    float acc[4][8][4];
#pragma unroll
    for (int i = 0; i < 4; i++)
#pragma unroll
        for (int j = 0; j < 8; j++)
#pragma unroll
            for (int e = 0; e < 4; e++) acc[i][j][e] = 0.f;

    const int nc = K >> 5;
    load_chunk(0, 0);
    CP_COMMIT();

    const int lrow = lane & 15;
    const int lcol = lane >> 4;

    for (int c = 0; c < nc; c++) {
        int buf = c & 1;
        if (c + 1 < nc) {
            load_chunk((c + 1) << 5, buf ^ 1);
            CP_COMMIT();
            CP_WAIT1();
        } else {
            CP_WAIT0();
        }
        __syncthreads();
        uint32_t st = sb + buf * STAGE_B;
#pragma unroll
        for (int ks = 0; ks < 2; ks++) {
            uint32_t a0[4][4], a1[4][4];
#pragma unroll
            for (int mi = 0; mi < 4; mi++) {
                uint32_t ad = st + (wm * 64 + mi * 16 + lrow) * 80 + ks * 32 + lcol * 16;
                LDSM4(a0[mi], ad);
                LDSM4(a1[mi], ad + MATA_B);
            }
#pragma unroll
            for (int nq = 0; nq < 4; nq++) {
                uint32_t b0r[4], b1r[4];
                uint32_t bd = st + 2 * MATA_B + (wn * 64 + nq * 16 + lrow) * 80 + ks * 32 + lcol * 16;
                LDSM4(b0r, bd);
                LDSM4(b1r, bd + MATB_B);
#pragma unroll
                for (int mi = 0; mi < 4; mi++) {
                    MMA16816(acc[mi][nq * 2],     a0[mi], b0r[0], b0r[2]);
                    MMA16816(acc[mi][nq * 2 + 1], a0[mi], b0r[1], b0r[3]);
                    MMA16816(acc[mi][nq * 2],     a1[mi], b0r[0], b0r[2]);
                    MMA16816(acc[mi][nq * 2 + 1], a1[mi], b0r[1], b0r[3]);
                    MMA16816(acc[mi][nq * 2],     a0[mi], b1r[0], b1r[2]);
                    MMA16816(acc[mi][nq * 2 + 1], a0[mi], b1r[1], b1r[3]);
                }
            }
        }
        __syncthreads();
    }

    // epilogue
#pragma unroll
    for (int mi = 0; mi < 4; mi++) {
#pragma unroll
        for (int nj = 0; nj < 8; nj++) {
            int row = m0 + wm * 64 + mi * 16 + (lane >> 2);
            int col = n0 + wn * 64 + nj * 8 + (lane & 3) * 2;
            float* d = acc[mi][nj];
#pragma unroll
            for (int h = 0; h < 2; h++) {
                int r = row + h * 8;
                float v0 = d[h * 2 + 0], v1 = d[h * 2 + 1];
                if (MODE == 1 || MODE == 3 || MODE == 7) {
                    v0 += bias[col];
                    v1 += bias[col + 1];
                }
                size_t co = (size_t)r * N + col;
                if (MODE == 0 || MODE == 1) {
                    C[co] = v0;
                    C[co + 1] = v1;
                } else if (MODE == 3) {
                    float z0 = C[co] + v0, z1 = C[co + 1] + v1;
                    C[co] = z0;
                    C[co + 1] = z1;
                    bf16 h0 = __float2bfloat16(z0), h1 = __float2bfloat16(z1);
                    C0[co] = h0;
                    C0[co + 1] = h1;
                    C1[co] = __float2bfloat16(z0 - __bfloat162float(h0));
                    C1[co + 1] = __float2bfloat16(z1 - __bfloat162float(h1));
                } else if (MODE == 4) {
                    float gq0 = gelu_tanh(v0), gq1 = gelu_tanh(v1);
                    bf16 h0 = __float2bfloat16(gq0), h1 = __float2bfloat16(gq1);
                    C0[co] = h0;
                    C0[co + 1] = h1;
                    C1[co] = __float2bfloat16(gq0 - __bfloat162float(h0));
                    C1[co + 1] = __float2bfloat16(gq1 - __bfloat162float(h1));
                } else if (MODE == 6) {
                    C[co] += Caux[co] + v0;
                    C[co + 1] += Caux[co + 1] + v1;
                } else if (MODE == 7) {
                    // pixel-shuffle scatter: r -> (bt,hp,wp), col -> (co4,pi,pj)
                    int bt = r >> 8;
                    int hp = (r >> 4) & 15, wp = r & 15;
                    int co4 = col >> 8;
                    int rem = col & 255;
                    int pi = rem >> 4, pj = rem & 15;
                    size_t o = (((size_t)(bt * 4 + co4) * 256 + hp * 16 + pi) * 256) + wp * 16 + pj;
                    C[o] = v0;
                    C[o + 1] = v1;
                }
            }
        }
    }
}

// ---------------- tiny fp32 GEMM (M=48) ----------------
__global__ void gemm_small_k(const float* __restrict__ A, const float* __restrict__ B,
                             float* __restrict__ C, int M, int N, int K)
{
    int idx = blockIdx.x * blockDim.x + threadIdx.x;
    if (idx >= M * N) return;
    int m = idx / N, n = idx % N;
    float s = 0.f;
    for (int k = 0; k < K; k++) s += A[(size_t)m * K + k] * B[(size_t)k * N + n];
    C[idx] = s;
}

// ---------------- weight builders ----------------
// fp32 big [2K][2N] for gemm_small
__global__ void build_cbig_k(float* __restrict__ dst, const float* __restrict__ re,
                             const float* __restrict__ im, int Kd, int Nd)
{
    int idx = blockIdx.x * blockDim.x + threadIdx.x;
    int N2 = 2 * Nd;
    if (idx >= 2 * Kd * N2) return;
    int k2 = idx / N2, n2 = idx % N2;
    bool ki = k2 >= Kd, ni = n2 >= Nd;
    int k = ki ? k2 - Kd : k2;
    int n = ni ? n2 - Nd : n2;
    float v;
    if (!ki && !ni) v = re[(size_t)k * Nd + n];
    else if (!ki && ni) v = im[(size_t)k * Nd + n];
    else if (ki && !ni) v = -im[(size_t)k * Nd + n];
    else v = re[(size_t)k * Nd + n];
    dst[idx] = v;
}

// tiled transpose-split: dst[n2][k2] = big[k2][n2] as bf16 hi/lo
// grid (2Kd/32, 2Nd/32), block (32,8)
__global__ void build_cbigT_tile_k(bf16* __restrict__ d0, bf16* __restrict__ d1,
                                   const float* __restrict__ re, const float* __restrict__ im,
                                   int Kd, int Nd)
{
    __shared__ float tile[32][33];
    int k2_0 = blockIdx.x * 32, n2_0 = blockIdx.y * 32;
    bool ki = k2_0 >= Kd, ni = n2_0 >= Nd;
    int k0 = k2_0 - (ki ? Kd : 0), n0 = n2_0 - (ni ? Nd : 0);
    const float* s = (ki != ni) ? im : re;
    float sign = (ki && !ni) ? -1.f : 1.f;
    int tx = threadIdx.x, ty = threadIdx.y;
#pragma unroll
    for (int j = 0; j < 4; j++) {
        int r = ty + j * 8;
        tile[r][tx] = s[(size_t)(k0 + r) * Nd + n0 + tx];
    }
    __syncthreads();
    int K2 = 2 * Kd;
#pragma unroll
    for (int j = 0; j < 4; j++) {
        int r = ty + j * 8;
        float v = sign * tile[tx][r];
        size_t o = (size_t)(n2_0 + r) * K2 + k2_0 + tx;
        bf16 h = __float2bfloat16(v);
        d0[o] = h;
        d1[o] = __float2bfloat16(v - __bfloat162float(h));
    }
}

// conv weights: dst[l][co][rs*768+ci] = cw[l][co][ci][rs]; grid (C2, LL)
__global__ void build_convwT_k(bf16* __restrict__ d0, bf16* __restrict__ d1,
                               const float* __restrict__ cw)
{
    __shared__ float s[KC];
    int co = blockIdx.x, l = blockIdx.y;
    const float* srcr = cw + ((size_t)(l * C2 + co)) * KC;
    for (int i = threadIdx.x; i < KC; i += 256) s[i] = srcr[i];
    __syncthreads();
    size_t base = ((size_t)l * C2 + co) * KC;
    for (int k = threadIdx.x; k < KC; k += 256) {
        int rs = k / 768;
        int ci = k - rs * 768;
        float v = s[ci * 9 + rs];
        bf16 h = __float2bfloat16(v);
        d0[base + k] = h;
        d1[base + k] = __float2bfloat16(v - __bfloat162float(h));
    }
}

// vectorized fp32 -> bf16 split (n % 4 == 0)
__global__ void split4_k(const float* __restrict__ src, bf16* __restrict__ d0,
                         bf16* __restrict__ d1, size_t n4)
{
    size_t idx = (size_t)blockIdx.x * blockDim.x + threadIdx.x;
    if (idx >= n4) return;
    float4 v = ((const float4*)src)[idx];
    bf16 h0 = __float2bfloat16(v.x), h1 = __float2bfloat16(v.y);
    bf16 h2 = __float2bfloat16(v.z), h3 = __float2bfloat16(v.w);
    __nv_bfloat162 p0 = {h0, h1}, p1 = {h2, h3};
    __nv_bfloat162 q0 = {__float2bfloat16(v.x - __bfloat162float(h0)),
                         __float2bfloat16(v.y - __bfloat162float(h1))};
    __nv_bfloat162 q1 = {__float2bfloat16(v.z - __bfloat162float(h2)),
                         __float2bfloat16(v.w - __bfloat162float(h3))};
    ((__nv_bfloat162*)d0)[idx * 2] = p0;
    ((__nv_bfloat162*)d0)[idx * 2 + 1] = p1;
    ((__nv_bfloat162*)d1)[idx * 2] = q0;
    ((__nv_bfloat162*)d1)[idx * 2 + 1] = q1;
}

// ---------------- encoder im2col (vectorized x4) ----------------
__global__ void enc_im2col4_k(bf16* __restrict__ P0, bf16* __restrict__ P1,
                              const float* __restrict__ x)
{
    size_t idx = (size_t)blockIdx.x * blockDim.x + threadIdx.x;  // NP*KENC/4
    size_t flat = idx * 4;
    int kk = flat % KENC;
    int n = flat / KENC;
    int cin = kk >> 8;
    int ii = (kk >> 4) & 15;
    int jj = kk & 15;
    int bt = n >> 8;
    int ph = (n >> 4) & 15;
    int pw = n & 15;
    const float* xp = x + ((((size_t)(bt * 4 + cin) * 256) + ph * 16 + ii) * 256 + pw * 16 + jj);
    float4 v = *(const float4*)xp;
    bf16 h0 = __float2bfloat16(v.x), h1 = __float2bfloat16(v.y);
    bf16 h2 = __float2bfloat16(v.z), h3 = __float2bfloat16(v.w);
    __nv_bfloat162 p0 = {h0, h1}, p1 = {h2, h3};
    __nv_bfloat162 q0 = {__float2bfloat16(v.x - __bfloat162float(h0)),
                         __float2bfloat16(v.y - __bfloat162float(h1))};
    __nv_bfloat162 q1 = {__float2bfloat16(v.z - __bfloat162float(h2)),
                         __float2bfloat16(v.w - __bfloat162float(h3))};
    ((__nv_bfloat162*)P0)[idx * 2] = p0;
    ((__nv_bfloat162*)P0)[idx * 2 + 1] = p1;
    ((__nv_bfloat162*)P1)[idx * 2] = q0;
    ((__nv_bfloat162*)P1)[idx * 2 + 1] = q1;
}

// ---------------- layernorm over 768 channels, emits bf16 splits ----------------
__global__ void layernorm_k(const float* __restrict__ X, const float* __restrict__ g,
                            const float* __restrict__ b,
                            bf16* __restrict__ Y0, bf16* __restrict__ Y1)
{
    __shared__ float red[256];
    int n = blockIdx.x;
    int tid = threadIdx.x;
    const float* x = X + (size_t)n * C2;
    float v0 = x[tid], v1 = x[tid + 256], v2 = x[tid + 512];
    red[tid] = v0 + v1 + v2;
    __syncthreads();
    for (int off = 128; off > 0; off >>= 1) {
        if (tid < off) red[tid] += red[tid + off];
        __syncthreads();
    }
    float m = red[0] * (1.f / 768.f);
    __syncthreads();
    float d0 = v0 - m, d1 = v1 - m, d2 = v2 - m;
    red[tid] = d0 * d0 + d1 * d1 + d2 * d2;
    __syncthreads();
    for (int off = 128; off > 0; off >>= 1) {
        if (tid < off) red[tid] += red[tid + off];
        __syncthreads();
    }
    float var = red[0] * (1.f / 768.f);
    float rstd = rsqrtf(var + 1e-5f);
    float o0 = d0 * rstd * g[tid] + b[tid];
    float o1 = d1 * rstd * g[tid + 256] + b[tid + 256];
    float o2 = d2 * rstd * g[tid + 512] + b[tid + 512];
    size_t base = (size_t)n * C2;
    bf16 h0 = __float2bfloat16(o0);
    bf16 h1 = __float2bfloat16(o1);
    bf16 h2 = __float2bfloat16(o2);
    Y0[base + tid] = h0;
    Y0[base + tid + 256] = h1;
    Y0[base + tid + 512] = h2;
    Y1[base + tid] = __float2bfloat16(o0 - __bfloat162float(h0));
    Y1[base + tid + 256] = __float2bfloat16(o1 - __bfloat162float(h1));
    Y1[base + tid + 512] = __float2bfloat16(o2 - __bfloat162float(h2));
}

// ---------------- mean over 256 spatial positions ----------------
__global__ void rowmean_k(const float* __restrict__ XE, float* __restrict__ xm)
{
    int bt = blockIdx.x;
    int c = threadIdx.x;
    float s = 0.f;
    const float* p = XE + (size_t)bt * 256 * C2 + c;
    for (int hw = 0; hw < 256; hw++) s += p[(size_t)hw * C2];
    xm[bt * C2 + c] = s * (1.f / 256.f);
}

// ---------------- flux scan + gate ----------------
__global__ void fluxscan_k(const float* __restrict__ xm, const float* __restrict__ dt,
                           const float* __restrict__ lamf_p, const float* __restrict__ Wg,
                           float* __restrict__ flux, float* __restrict__ gate)
{
    int tid = blockIdx.x * blockDim.x + threadIdx.x;
    int b = tid / DD, e = tid % DD;
    float lamf = softplus_f(lamf_p[e]);
    float wg = Wg[e];
    float fr = 0.f, fi = 0.f;
    for (int t = 0; t < TT; t++) {
        int bt = b * TT + t;
        float dtv = dt[bt];
        float a = expf(-lamf * dtv);
        float xr = xm[bt * C2 + e] * dtv;
        float xi = xm[bt * C2 + DD + e] * dtv;
        fr = fr * a + xr;
        fi = fi * a + xi;
        flux[bt * C2 + e] = fr;
        flux[bt * C2 + DD + e] = fi;
        gate[bt * DD + e] = 1.f / (1.f + expf(-fr * wg));
    }
}

// ---------------- op_decay / op_forcing ----------------
__global__ void opdecay_k(const float* __restrict__ dt, const float* __restrict__ nu,
                          const float* __restrict__ omega, float* __restrict__ OD,
                          float* __restrict__ OF)
{
    int idx = blockIdx.x * blockDim.x + threadIdx.x;
    int bt = idx / DD, e = idx % DD;
    float sp = softplus_f(nu[e]);
    float lr = fminf(fmaxf(-sp, -5.f), 0.3f);
    float li = omega[e];
    float dtv = dt[bt];
    float er = expf(lr * dtv);
    float odr = er * cosf(li * dtv);
    float odi = er * sinf(li * dtv);
    OD[bt * C2 + e] = odr;
    OD[bt * C2 + DD + e] = odi;
    float nr = odr - 1.f, ni = odi;
    float den = lr * lr + li * li;
    OF[bt * C2 + e] = (nr * lr + ni * li) / den;
    OF[bt * C2 + DD + e] = (ni * lr - nr * li) / den;
}

// ---------------- fused forcing + u scan, emits bf16 splits ----------------
__global__ void fuscan_k(const float* __restrict__ XE, const float* __restrict__ gate,
                         const float* __restrict__ src, const float* __restrict__ OF,
                         const float* __restrict__ OD,
                         bf16* __restrict__ U0, bf16* __restrict__ U1)
{
    int tid = blockIdx.x * blockDim.x + threadIdx.x;  // BB*256*DD
    int e = tid % DD;
    int hw = (tid / DD) & 255;
    int b = tid / (DD * 256);
    float ur = 0.f, ui = 0.f;
    for (int t = 0; t < TT; t++) {
        int bt = b * TT + t;
        size_t base = (size_t)(bt * 256 + hw) * C2;
        float xr = XE[base + e], xi = XE[base + DD + e];
        float g = gate[bt * DD + e];
        float sr = src[bt * C2 + e], si = src[bt * C2 + DD + e];
        float fr = xr * g + sr * (1.f - g);
        float fi = xi * g + si * (1.f - g);
        float ofr = OF[bt * C2 + e], ofi = OF[bt * C2 + DD + e];
        float utr = fr * ofr - fi * ofi;
        float uti = fr * ofi + fi * ofr;
        float odr = OD[bt * C2 + e], odi = OD[bt * C2 + DD + e];
        float nr = ur * odr - ui * odi + utr;
        float ni = ur * odi + ui * odr + uti;
        ur = nr; ui = ni;
        bf16 hr = __float2bfloat16(ur);
        bf16 hi = __float2bfloat16(ui);
        U0[base + e] = hr;
        U0[base + DD + e] = hi;
        U1[base + e] = __float2bfloat16(ur - __bfloat162float(hr));
        U1[base + DD + e] = __float2bfloat16(ui - __bfloat162float(hi));
    }
}

// ---------------- host side ----------------
template <typename T>
static T* sym(const void* s)
{
    void* p = nullptr;
    cudaGetSymbolAddress(&p, s);
    return (T*)p;
}

template <int MODE, bool CONV>
static void launch_gemm(const bf16* A0, const bf16* A1, const bf16* B0, const bf16* B1,
                        float* C, bf16* C0, bf16* C1, const float* Caux,
                        const float* bias, int N, int K)
{
    static bool attr_done = false;
    cudaFuncSetAttribute(hgemm_k<MODE, CONV>, cudaFuncAttributeMaxDynamicSharedMemorySize, SMEM_TOTAL_G);
    (void)attr_done;
    dim3 grid(N / 128, NP / 256);
    hgemm_k<MODE, CONV><<<grid, 256, SMEM_TOTAL_G>>>(A0, A1, B0, B1, C, C0, C1, Caux, bias, N, K);
}

extern "C" void kernel_launch(void* const* d_in, const int* in_sizes, int n_in,
                              void* d_out, int out_size)
{
    const float* x       = (const float*)d_in[0];
    const float* dt      = (const float*)d_in[1];
    const float* enc_w   = (const float*)d_in[2];
    const float* enc_b   = (const float*)d_in[3];
    const float* ns_g    = (const float*)d_in[4];
    const float* ns_b    = (const float*)d_in[5];
    const float* cw      = (const float*)d_in[6];
    const float* cb      = (const float*)d_in[7];
    const float* nt_g    = (const float*)d_in[8];
    const float* nt_b    = (const float*)d_in[9];
    const float* E_re    = (const float*)d_in[10];
    const float* E_im    = (const float*)d_in[11];
    const float* Ei_re   = (const float*)d_in[12];
    const float* Ei_im   = (const float*)d_in[13];
    const float* lamflux = (const float*)d_in[14];
    const float* Ws_re   = (const float*)d_in[15];
    const float* Ws_im   = (const float*)d_in[16];
    const float* Wg      = (const float*)d_in[17];
    const float* nu      = (const float*)d_in[18];
    const float* omega   = (const float*)d_in[19];
    const float* w1_re   = (const float*)d_in[20];
    const float* w1_im   = (const float*)d_in[21];
    const float* w2_re   = (const float*)d_in[22];
    const float* w2_im   = (const float*)d_in[23];
    const float* dec_w   = (const float*)d_in[24];
    const float* dec_b   = (const float*)d_in[25];
    float* out = (float*)d_out;

    float* Z   = sym<float>(g_Z);
    float* XE  = sym<float>(g_XE);
    float* DEC = sym<float>(g_DEC);
    bf16* IM0  = sym<bf16>(g_IM0);
    bf16* IM1  = sym<bf16>(g_IM1);
    bf16* Ab0  = sym<bf16>(g_Ab0);
    bf16* Ab1  = sym<bf16>(g_Ab1);
    bf16* Zb0  = sym<bf16>(g_Zb0);
    bf16* Zb1  = sym<bf16>(g_Zb1);
    bf16* Hb0  = sym<bf16>(g_Hb0);
    bf16* Hb1  = sym<bf16>(g_Hb1);
    bf16* Wcb0 = sym<bf16>(g_Wcb0);
    bf16* Wcb1 = sym<bf16>(g_Wcb1);
    bf16* Eb0  = sym<bf16>(g_Eb0);
    bf16* Eb1  = sym<bf16>(g_Eb1);
    bf16* Eib0 = sym<bf16>(g_Eib0);
    bf16* Eib1 = sym<bf16>(g_Eib1);
    bf16* W1b0 = sym<bf16>(g_W1b0);
    bf16* W1b1 = sym<bf16>(g_W1b1);
    bf16* W2b0 = sym<bf16>(g_W2b0);
    bf16* W2b1 = sym<bf16>(g_W2b1);
    bf16* encb0 = sym<bf16>(g_encb0);
    bf16* encb1 = sym<bf16>(g_encb1);
    bf16* decb0 = sym<bf16>(g_decb0);
    bf16* decb1 = sym<bf16>(g_decb1);
    float* Wsb  = sym<float>(g_Wsbig);
    float* xm   = sym<float>(g_xmean);
    float* flux = sym<float>(g_flux);
    float* src  = sym<float>(g_src);
    float* gate = sym<float>(g_gate);
    float* OD   = sym<float>(g_OD);
    float* OF   = sym<float>(g_OF);

    // ---- build weights ----
    {
        dim3 blk(32, 8);
        for (int l = 0; l < LL; l++) {
            size_t oE = (size_t)l * C2 * C2;
            dim3 gE(C2 / 32, C2 / 32);
            build_cbigT_tile_k<<<gE, blk>>>(Eb0 + oE, Eb1 + oE,
                                            E_re + (size_t)l * DD * DD, E_im + (size_t)l * DD * DD, DD, DD);
            build_cbigT_tile_k<<<gE, blk>>>(Eib0 + oE, Eib1 + oE,
                                            Ei_re + (size_t)l * DD * DD, Ei_im + (size_t)l * DD * DD, DD, DD);
            build_cbig_k<<<(C2 * C2) / 256, 256>>>(Wsb + oE,
                                                   Ws_re + (size_t)l * DD * DD, Ws_im + (size_t)l * DD * DD, DD, DD);
            size_t o1 = (size_t)l * DFF2 * C2;
            dim3 g1(C2 / 32, DFF2 / 32);     // W1: K2=768, N2=3072
            build_cbigT_tile_k<<<g1, blk>>>(W1b0 + o1, W1b1 + o1,
                                            w1_re + (size_t)l * DD * DFF, w1_im + (size_t)l * DD * DFF, DD, DFF);
            dim3 g2(DFF2 / 32, C2 / 32);     // W2: K2=3072, N2=768
            build_cbigT_tile_k<<<g2, blk>>>(W2b0 + o1, W2b1 + o1,
                                            w2_re + (size_t)l * DFF * DD, w2_im + (size_t)l * DFF * DD, DFF, DD);
        }
        build_convwT_k<<<dim3(C2, LL), 256>>>(Wcb0, Wcb1, cw);
        split4_k<<<(C2 * KENC / 4 + 255) / 256, 256>>>(enc_w, encb0, encb1, (size_t)C2 * KENC / 4);
        split4_k<<<(NDEC * C2 / 4 + 255) / 256, 256>>>(dec_w, decb0, decb1, (size_t)NDEC * C2 / 4);
    }

    // ---- encoder ----
    enc_im2col4_k<<<((size_t)NP * KENC / 4) / 256, 256>>>(IM0, IM1, x);
    launch_gemm<1, false>(IM0, IM1, encb0, encb1, Z, nullptr, nullptr, nullptr, enc_b, C2, KENC);

    for (int l = 0; l < LL; l++) {
        // spatial: LN -> implicit conv3x3 GEMM; Z += conv+cb, emit Zb splits
        layernorm_k<<<NP, 256>>>(Z, ns_g + l * C2, ns_b + l * C2, Ab0, Ab1);
        launch_gemm<3, true>(Ab0, Ab1, Wcb0 + (size_t)l * C2 * KC, Wcb1 + (size_t)l * C2 * KC,
                             Z, Zb0, Zb1, nullptr, cb + l * C2, C2, KC);

        // spectral: XE = Z @ E
        launch_gemm<0, false>(Zb0, Zb1, Eb0 + (size_t)l * C2 * C2, Eb1 + (size_t)l * C2 * C2,
                              XE, nullptr, nullptr, nullptr, nullptr, C2, C2);

        // temporal flux path
        rowmean_k<<<BT, C2>>>(XE, xm);
        fluxscan_k<<<6, 256>>>(xm, dt, lamflux + l * DD, Wg + l * DD, flux, gate);
        gemm_small_k<<<(BT * C2) / 256, 256>>>(flux, Wsb + (size_t)l * C2 * C2, src, BT, C2, C2);
        opdecay_k<<<(BT * DD) / 256, 256>>>(dt, nu + l * DD, omega + l * DD, OD, OF);
        fuscan_k<<<(BB * 256 * DD) / 256, 256>>>(XE, gate, src, OF, OD, Ab0, Ab1);

        // decode back: DEC = u_out @ Ei
        launch_gemm<0, false>(Ab0, Ab1, Eib0 + (size_t)l * C2 * C2, Eib1 + (size_t)l * C2 * C2,
                              DEC, nullptr, nullptr, nullptr, nullptr, C2, C2);

        // MLP on LN(DEC); Z += DEC + delta (fused)
        layernorm_k<<<NP, 256>>>(DEC, nt_g + l * C2, nt_b + l * C2, Zb0, Zb1);
        launch_gemm<4, false>(Zb0, Zb1, W1b0 + (size_t)l * DFF2 * C2, W1b1 + (size_t)l * DFF2 * C2,
                              nullptr, Hb0, Hb1, nullptr, nullptr, DFF2, C2);
        launch_gemm<6, false>(Hb0, Hb1, W2b0 + (size_t)l * C2 * DFF2, W2b1 + (size_t)l * C2 * DFF2,
                              Z, nullptr, nullptr, DEC, nullptr, C2, DFF2);
    }

    // ---- decoder GEMM with fused pixel-shuffle scatter ----
    split4_k<<<((size_t)NP * C2 / 4) / 256, 256>>>(Z, Ab0, Ab1, (size_t)NP * C2 / 4);
    launch_gemm<7, false>(Ab0, Ab1, decb0, decb1, out, nullptr, nullptr, nullptr, dec_b, NDEC, C2);

    (void)in_sizes; (void)n_in; (void)out_size;
}

// round 9
// speedup vs baseline: 2.7238x; 1.2971x over previous
#include <cuda_runtime.h>
#include <cuda_fp16.h>
#include <math.h>
#include <stdint.h>

// ---------------- constants ----------------
#define BB 4
#define TT 12
#define BT 48
#define DD 384
#define C2 768
#define NP 12288
#define KC 6912
#define DFF 1536
#define DFF2 3072
#define KENC 1024
#define NDEC 1024
#define LL 4

typedef __half hf;

// ---------------- device scratch ----------------
__device__ float g_Z[(size_t)NP * C2];
__device__ float g_XE[(size_t)NP * C2];
__device__ float g_DEC[(size_t)NP * C2];
__device__ hf g_IM0[(size_t)NP * KENC];
__device__ hf g_IM1[(size_t)NP * KENC];
__device__ hf g_Ab0[(size_t)NP * C2];
__device__ hf g_Ab1[(size_t)NP * C2];
__device__ hf g_Zb0[(size_t)NP * C2];
__device__ hf g_Zb1[(size_t)NP * C2];
__device__ hf g_Hb0[(size_t)NP * DFF2];
__device__ hf g_Hb1[(size_t)NP * DFF2];
__device__ hf g_Wcb[(size_t)LL * C2 * KC];
__device__ hf g_Eb[(size_t)LL * C2 * C2];
__device__ hf g_Eib[(size_t)LL * C2 * C2];
__device__ hf g_W1b[(size_t)LL * DFF2 * C2];   // [N=3072][K=768]
__device__ hf g_W2b[(size_t)LL * C2 * DFF2];   // [N=768][K=3072]
__device__ hf g_encb[C2 * KENC];
__device__ hf g_decb[NDEC * C2];
__device__ float g_Wsbig[(size_t)LL * C2 * C2];
__device__ float g_xmean[BT * C2];
__device__ float g_flux[BT * C2];
__device__ float g_src[BT * C2];
__device__ float g_gate[BT * DD];
__device__ float g_OD[BT * C2];
__device__ float g_OF[BT * C2];

// ---------------- helpers ----------------
__device__ __forceinline__ float softplus_f(float x) {
    return (x > 20.f) ? x : log1pf(expf(x));
}
__device__ __forceinline__ float gelu_tanh(float x) {
    float x3 = x * x * x;
    float t = tanhf(0.7978845608028654f * (x + 0.044715f * x3));
    return 0.5f * x * (1.f + t);
}
__device__ __forceinline__ uint32_t smem_u32(const void* p) {
    uint32_t a;
    asm("{ .reg .u64 t; cvta.to.shared.u64 t, %1; cvt.u32.u64 %0, t; }" : "=r"(a) : "l"(p));
    return a;
}
__device__ __forceinline__ void cp16(uint32_t dst, const void* src) {
    asm volatile("cp.async.cg.shared.global [%0], [%1], 16;" :: "r"(dst), "l"(src) : "memory");
}
__device__ __forceinline__ void cp16z(uint32_t dst, const void* src, uint32_t sz) {
    asm volatile("cp.async.cg.shared.global [%0], [%1], 16, %2;" :: "r"(dst), "l"(src), "r"(sz) : "memory");
}
#define CP_COMMIT() asm volatile("cp.async.commit_group;" ::: "memory")
#define CP_WAIT0() asm volatile("cp.async.wait_group 0;" ::: "memory")
#define CP_WAIT1() asm volatile("cp.async.wait_group 1;" ::: "memory")

#define LDSM4(r, addr) \
    asm volatile("ldmatrix.sync.aligned.m8n8.x4.shared.b16 {%0,%1,%2,%3}, [%4];" \
                 : "=r"((r)[0]), "=r"((r)[1]), "=r"((r)[2]), "=r"((r)[3]) : "r"(addr))

#define MMA16816(d, a, bb0, bb1) \
    asm volatile("mma.sync.aligned.m16n8k16.row.col.f32.f16.f16.f32 " \
                 "{%0,%1,%2,%3}, {%4,%5,%6,%7}, {%8,%9}, {%0,%1,%2,%3};" \
                 : "+f"((d)[0]), "+f"((d)[1]), "+f"((d)[2]), "+f"((d)[3]) \
                 : "r"((a)[0]), "r"((a)[1]), "r"((a)[2]), "r"((a)[3]), \
                   "r"(bb0), "r"(bb1))

__device__ __forceinline__ void split_f(float v, hf& h, hf& l) {
    h = __float2half(v);
    l = __float2half(v - __half2float(h));
}

// ---------------- warp-MMA fp16 GEMM ----------------
// C[M=12288, N] = A @ B^T with A = A0+A1 (fp16 split), B single fp16.
// acc = A0 B + A1 B  (2 products; B rounding ~2^-11 is the only error source).
// Block tile 256x128x32, 8 warps (4M x 2N), warp tile 64x64.
// smem/stage: A 2x(256x80B)=40960 + B 128x80B=10240 -> 51200B; x2 stages.
// grid: x = N/128 (fast -> A tile L2 reuse), y = M/256.
// MODE: 0 store, 1 store+bias, 3 acc+bias+split-emit, 4 gelu->split, 6 Z-fuse, 7 dec-scatter
// CONV: A-loader does implicit 3x3 im2col from A [NP][C2] (K = 9*768).
#define MATA_B 20480
#define MATB_B 10240
#define STAGE_B 51200
#define SMEM_TOTAL_G (2 * STAGE_B)

template <int MODE, bool CONV>
__global__ __launch_bounds__(256) void hgemm_k(
    const hf* __restrict__ A0, const hf* __restrict__ A1,
    const hf* __restrict__ B,
    float* __restrict__ C, hf* __restrict__ C0, hf* __restrict__ C1,
    const float* __restrict__ Caux, const float* __restrict__ bias, int N, int K)
{
    extern __shared__ char smem[];
    uint32_t sb = smem_u32(smem);
    const int tid = threadIdx.x;
    const int wid = tid >> 5;
    const int lane = tid & 31;
    const int n0 = blockIdx.x * 128;
    const int m0 = blockIdx.y * 256;
    const int wm = wid & 3;       // 0..3 (M, x64)
    const int wn = wid >> 2;      // 0..1 (N, x64)

    auto load_chunk = [&](int k0, int buf) {
        uint32_t st = sb + buf * STAGE_B;
        // A: 2 mats x 256 rows x 4 vecs = 2048
#pragma unroll
        for (int i = 0; i < 8; i++) {
            int id = tid + 256 * i;
            int mat = id >> 10;
            int cid = id & 1023;
            int row = cid >> 2, c4 = cid & 3;
            uint32_t dst = st + mat * MATA_B + row * 80 + c4 * 16;
            const hf* Asrc = mat ? A1 : A0;
            if (CONV) {
                int kk = k0 + c4 * 8;
                int rs = kk / 768;
                int ci = kk - rs * 768;
                int dy = rs / 3 - 1, dx = rs - (rs / 3) * 3 - 1;
                int m = m0 + row;
                int bt = m >> 8;
                int h = (m >> 4) & 15, w = m & 15;
                int hh = h + dy, ww = w + dx;
                bool ok = ((unsigned)hh < 16u) && ((unsigned)ww < 16u);
                const hf* sp = Asrc + ((size_t)((bt << 8) + (hh << 4) + ww) * 768 + ci);
                if (!ok) sp = Asrc;
                cp16z(dst, sp, ok ? 16u : 0u);
            } else {
                cp16(dst, Asrc + (size_t)(m0 + row) * K + k0 + c4 * 8);
            }
        }
        // B: 128 rows x 4 vecs = 512
#pragma unroll
        for (int i = 0; i < 2; i++) {
            int id = tid + 256 * i;
            int row = id >> 2, c4 = id & 3;
            uint32_t dst = st + 2 * MATA_B + row * 80 + c4 * 16;
            cp16(dst, B + (size_t)(n0 + row) * K + k0 + c4 * 8);
        }
    };

    float acc[4][8][4];
#pragma unroll
    for (int i = 0; i < 4; i++)
#pragma unroll
        for (int j = 0; j < 8; j++)
#pragma unroll
            for (int e = 0; e < 4; e++) acc[i][j][e] = 0.f;

    const int nc = K >> 5;
    load_chunk(0, 0);
    CP_COMMIT();

    const int lrow = lane & 15;
    const int lcol = lane >> 4;

    for (int c = 0; c < nc; c++) {
        int buf = c & 1;
        if (c + 1 < nc) {
            load_chunk((c + 1) << 5, buf ^ 1);
            CP_COMMIT();
            CP_WAIT1();
        } else {
            CP_WAIT0();
        }
        __syncthreads();
        uint32_t st = sb + buf * STAGE_B;
#pragma unroll
        for (int ks = 0; ks < 2; ks++) {
            uint32_t a0[4][4], a1[4][4];
#pragma unroll
            for (int mi = 0; mi < 4; mi++) {
                uint32_t ad = st + (wm * 64 + mi * 16 + lrow) * 80 + ks * 32 + lcol * 16;
                LDSM4(a0[mi], ad);
                LDSM4(a1[mi], ad + MATA_B);
            }
#pragma unroll
            for (int nq = 0; nq < 4; nq++) {
                uint32_t br[4];
                uint32_t bd = st + 2 * MATA_B + (wn * 64 + nq * 16 + lrow) * 80 + ks * 32 + lcol * 16;
                LDSM4(br, bd);
#pragma unroll
                for (int mi = 0; mi < 4; mi++) {
                    MMA16816(acc[mi][nq * 2],     a0[mi], br[0], br[2]);
                    MMA16816(acc[mi][nq * 2 + 1], a0[mi], br[1], br[3]);
                    MMA16816(acc[mi][nq * 2],     a1[mi], br[0], br[2]);
                    MMA16816(acc[mi][nq * 2 + 1], a1[mi], br[1], br[3]);
                }
            }
        }
        __syncthreads();
    }

    // epilogue
#pragma unroll
    for (int mi = 0; mi < 4; mi++) {
#pragma unroll
        for (int nj = 0; nj < 8; nj++) {
            int row = m0 + wm * 64 + mi * 16 + (lane >> 2);
            int col = n0 + wn * 64 + nj * 8 + (lane & 3) * 2;
            float* d = acc[mi][nj];
#pragma unroll
            for (int h = 0; h < 2; h++) {
                int r = row + h * 8;
                float v0 = d[h * 2 + 0], v1 = d[h * 2 + 1];
                if (MODE == 1 || MODE == 3 || MODE == 7) {
                    v0 += bias[col];
                    v1 += bias[col + 1];
                }
                size_t co = (size_t)r * N + col;
                if (MODE == 0 || MODE == 1) {
                    C[co] = v0;
                    C[co + 1] = v1;
                } else if (MODE == 3) {
                    float z0 = C[co] + v0, z1 = C[co + 1] + v1;
                    C[co] = z0;
                    C[co + 1] = z1;
                    hf h0, l0, h1, l1;
                    split_f(z0, h0, l0);
                    split_f(z1, h1, l1);
                    C0[co] = h0; C0[co + 1] = h1;
                    C1[co] = l0; C1[co + 1] = l1;
                } else if (MODE == 4) {
                    float gq0 = gelu_tanh(v0), gq1 = gelu_tanh(v1);
                    hf h0, l0, h1, l1;
                    split_f(gq0, h0, l0);
                    split_f(gq1, h1, l1);
                    C0[co] = h0; C0[co + 1] = h1;
                    C1[co] = l0; C1[co + 1] = l1;
                } else if (MODE == 6) {
                    C[co] += Caux[co] + v0;
                    C[co + 1] += Caux[co + 1] + v1;
                } else if (MODE == 7) {
                    // pixel-shuffle scatter: r -> (bt,hp,wp), col -> (co4,pi,pj)
                    int bt = r >> 8;
                    int hp = (r >> 4) & 15, wp = r & 15;
                    int co4 = col >> 8;
                    int rem = col & 255;
                    int pi = rem >> 4, pj = rem & 15;
                    size_t o = (((size_t)(bt * 4 + co4) * 256 + hp * 16 + pi) * 256) + wp * 16 + pj;
                    C[o] = v0;
                    C[o + 1] = v1;
                }
            }
        }
    }
}

// ---------------- tiny fp32 GEMM (M=48) ----------------
__global__ void gemm_small_k(const float* __restrict__ A, const float* __restrict__ B,
                             float* __restrict__ C, int M, int N, int K)
{
    int idx = blockIdx.x * blockDim.x + threadIdx.x;
    if (idx >= M * N) return;
    int m = idx / N, n = idx % N;
    float s = 0.f;
    for (int k = 0; k < K; k++) s += A[(size_t)m * K + k] * B[(size_t)k * N + n];
    C[idx] = s;
}

// ---------------- weight builders ----------------
// fp32 big [2K][2N] for gemm_small
__global__ void build_cbig_k(float* __restrict__ dst, const float* __restrict__ re,
                             const float* __restrict__ im, int Kd, int Nd)
{
    int idx = blockIdx.x * blockDim.x + threadIdx.x;
    int N2 = 2 * Nd;
    if (idx >= 2 * Kd * N2) return;
    int k2 = idx / N2, n2 = idx % N2;
    bool ki = k2 >= Kd, ni = n2 >= Nd;
    int k = ki ? k2 - Kd : k2;
    int n = ni ? n2 - Nd : n2;
    float v;
    if (!ki && !ni) v = re[(size_t)k * Nd + n];
    else if (!ki && ni) v = im[(size_t)k * Nd + n];
    else if (ki && !ni) v = -im[(size_t)k * Nd + n];
    else v = re[(size_t)k * Nd + n];
    dst[idx] = v;
}

// tiled transpose: dst[n2][k2] = big[k2][n2] as single fp16
// grid (2Kd/32, 2Nd/32), block (32,8)
__global__ void build_cbigT_tile_k(hf* __restrict__ d0,
                                   const float* __restrict__ re, const float* __restrict__ im,
                                   int Kd, int Nd)
{
    __shared__ float tile[32][33];
    int k2_0 = blockIdx.x * 32, n2_0 = blockIdx.y * 32;
    bool ki = k2_0 >= Kd, ni = n2_0 >= Nd;
    int k0 = k2_0 - (ki ? Kd : 0), n0 = n2_0 - (ni ? Nd : 0);
    const float* s = (ki != ni) ? im : re;
    float sign = (ki && !ni) ? -1.f : 1.f;
    int tx = threadIdx.x, ty = threadIdx.y;
#pragma unroll
    for (int j = 0; j < 4; j++) {
        int r = ty + j * 8;
        tile[r][tx] = s[(size_t)(k0 + r) * Nd + n0 + tx];
    }
    __syncthreads();
    int K2 = 2 * Kd;
#pragma unroll
    for (int j = 0; j < 4; j++) {
        int r = ty + j * 8;
        float v = sign * tile[tx][r];
        d0[(size_t)(n2_0 + r) * K2 + k2_0 + tx] = __float2half(v);
    }
}

// conv weights: dst[l][co][rs*768+ci] = cw[l][co][ci][rs]; grid (C2, LL)
__global__ void build_convwT_k(hf* __restrict__ d0, const float* __restrict__ cw)
{
    __shared__ float s[KC];
    int co = blockIdx.x, l = blockIdx.y;
    const float* srcr = cw + ((size_t)(l * C2 + co)) * KC;
    for (int i = threadIdx.x; i < KC; i += 256) s[i] = srcr[i];
    __syncthreads();
    size_t base = ((size_t)l * C2 + co) * KC;
    for (int k = threadIdx.x; k < KC; k += 256) {
        int rs = k / 768;
        int ci = k - rs * 768;
        d0[base + k] = __float2half(s[ci * 9 + rs]);
    }
}

// fp32 -> single fp16 (weights), vectorized x4
__global__ void cvtw4_k(const float* __restrict__ src, hf* __restrict__ d0, size_t n4)
{
    size_t idx = (size_t)blockIdx.x * blockDim.x + threadIdx.x;
    if (idx >= n4) return;
    float4 v = ((const float4*)src)[idx];
    __half2 p0 = {__float2half(v.x), __float2half(v.y)};
    __half2 p1 = {__float2half(v.z), __float2half(v.w)};
    ((__half2*)d0)[idx * 2] = p0;
    ((__half2*)d0)[idx * 2 + 1] = p1;
}

// fp32 -> fp16 split (activations), vectorized x4
__global__ void split4_k(const float* __restrict__ src, hf* __restrict__ d0,
                         hf* __restrict__ d1, size_t n4)
{
    size_t idx = (size_t)blockIdx.x * blockDim.x + threadIdx.x;
    if (idx >= n4) return;
    float4 v = ((const float4*)src)[idx];
    hf h0, l0, h1, l1, h2, l2, h3, l3;
    split_f(v.x, h0, l0);
    split_f(v.y, h1, l1);
    split_f(v.z, h2, l2);
    split_f(v.w, h3, l3);
    __half2 p0 = {h0, h1}, p1 = {h2, h3};
    __half2 q0 = {l0, l1}, q1 = {l2, l3};
    ((__half2*)d0)[idx * 2] = p0;
    ((__half2*)d0)[idx * 2 + 1] = p1;
    ((__half2*)d1)[idx * 2] = q0;
    ((__half2*)d1)[idx * 2 + 1] = q1;
}

// ---------------- encoder im2col (vectorized x4, fp16 split) ----------------
__global__ void enc_im2col4_k(hf* __restrict__ P0, hf* __restrict__ P1,
                              const float* __restrict__ x)
{
    size_t idx = (size_t)blockIdx.x * blockDim.x + threadIdx.x;  // NP*KENC/4
    size_t flat = idx * 4;
    int kk = flat % KENC;
    int n = flat / KENC;
    int cin = kk >> 8;
    int ii = (kk >> 4) & 15;
    int jj = kk & 15;
    int bt = n >> 8;
    int ph = (n >> 4) & 15;
    int pw = n & 15;
    const float* xp = x + ((((size_t)(bt * 4 + cin) * 256) + ph * 16 + ii) * 256 + pw * 16 + jj);
    float4 v = *(const float4*)xp;
    hf h0, l0, h1, l1, h2, l2, h3, l3;
    split_f(v.x, h0, l0);
    split_f(v.y, h1, l1);
    split_f(v.z, h2, l2);
    split_f(v.w, h3, l3);
    __half2 p0 = {h0, h1}, p1 = {h2, h3};
    __half2 q0 = {l0, l1}, q1 = {l2, l3};
    ((__half2*)P0)[idx * 2] = p0;
    ((__half2*)P0)[idx * 2 + 1] = p1;
    ((__half2*)P1)[idx * 2] = q0;
    ((__half2*)P1)[idx * 2 + 1] = q1;
}

// ---------------- layernorm over 768 channels, emits fp16 splits ----------------
__global__ void layernorm_k(const float* __restrict__ X, const float* __restrict__ g,
                            const float* __restrict__ b,
                            hf* __restrict__ Y0, hf* __restrict__ Y1)
{
    __shared__ float red[256];
    int n = blockIdx.x;
    int tid = threadIdx.x;
    const float* x = X + (size_t)n * C2;
    float v0 = x[tid], v1 = x[tid + 256], v2 = x[tid + 512];
    red[tid] = v0 + v1 + v2;
    __syncthreads();
    for (int off = 128; off > 0; off >>= 1) {
        if (tid < off) red[tid] += red[tid + off];
        __syncthreads();
    }
    float m = red[0] * (1.f / 768.f);
    __syncthreads();
    float d0 = v0 - m, d1 = v1 - m, d2 = v2 - m;
    red[tid] = d0 * d0 + d1 * d1 + d2 * d2;
    __syncthreads();
    for (int off = 128; off > 0; off >>= 1) {
        if (tid < off) red[tid] += red[tid + off];
        __syncthreads();
    }
    float var = red[0] * (1.f / 768.f);
    float rstd = rsqrtf(var + 1e-5f);
    float o0 = d0 * rstd * g[tid] + b[tid];
    float o1 = d1 * rstd * g[tid + 256] + b[tid + 256];
    float o2 = d2 * rstd * g[tid + 512] + b[tid + 512];
    size_t base = (size_t)n * C2;
    hf h0, l0, h1, l1, h2, l2;
    split_f(o0, h0, l0);
    split_f(o1, h1, l1);
    split_f(o2, h2, l2);
    Y0[base + tid] = h0;
    Y0[base + tid + 256] = h1;
    Y0[base + tid + 512] = h2;
    Y1[base + tid] = l0;
    Y1[base + tid + 256] = l1;
    Y1[base + tid + 512] = l2;
}

// ---------------- mean over 256 spatial positions ----------------
__global__ void rowmean_k(const float* __restrict__ XE, float* __restrict__ xm)
{
    int bt = blockIdx.x;
    int c = threadIdx.x;
    float s = 0.f;
    const float* p = XE + (size_t)bt * 256 * C2 + c;
    for (int hw = 0; hw < 256; hw++) s += p[(size_t)hw * C2];
    xm[bt * C2 + c] = s * (1.f / 256.f);
}

// ---------------- flux scan + gate ----------------
__global__ void fluxscan_k(const float* __restrict__ xm, const float* __restrict__ dt,
                           const float* __restrict__ lamf_p, const float* __restrict__ Wg,
                           float* __restrict__ flux, float* __restrict__ gate)
{
    int tid = blockIdx.x * blockDim.x + threadIdx.x;
    int b = tid / DD, e = tid % DD;
    float lamf = softplus_f(lamf_p[e]);
    float wg = Wg[e];
    float fr = 0.f, fi = 0.f;
    for (int t = 0; t < TT; t++) {
        int bt = b * TT + t;
        float dtv = dt[bt];
        float a = expf(-lamf * dtv);
        float xr = xm[bt * C2 + e] * dtv;
        float xi = xm[bt * C2 + DD + e] * dtv;
        fr = fr * a + xr;
        fi = fi * a + xi;
        flux[bt * C2 + e] = fr;
        flux[bt * C2 + DD + e] = fi;
        gate[bt * DD + e] = 1.f / (1.f + expf(-fr * wg));
    }
}

// ---------------- op_decay / op_forcing ----------------
__global__ void opdecay_k(const float* __restrict__ dt, const float* __restrict__ nu,
                          const float* __restrict__ omega, float* __restrict__ OD,
                          float* __restrict__ OF)
{
    int idx = blockIdx.x * blockDim.x + threadIdx.x;
    int bt = idx / DD, e = idx % DD;
    float sp = softplus_f(nu[e]);
    float lr = fminf(fmaxf(-sp, -5.f), 0.3f);
    float li = omega[e];
    float dtv = dt[bt];
    float er = expf(lr * dtv);
    float odr = er * cosf(li * dtv);
    float odi = er * sinf(li * dtv);
    OD[bt * C2 + e] = odr;
    OD[bt * C2 + DD + e] = odi;
    float nr = odr - 1.f, ni = odi;
    float den = lr * lr + li * li;
    OF[bt * C2 + e] = (nr * lr + ni * li) / den;
    OF[bt * C2 + DD + e] = (ni * lr - nr * li) / den;
}

// ---------------- fused forcing + u scan, emits fp16 splits ----------------
__global__ void fuscan_k(const float* __restrict__ XE, const float* __restrict__ gate,
                         const float* __restrict__ src, const float* __restrict__ OF,
                         const float* __restrict__ OD,
                         hf* __restrict__ U0, hf* __restrict__ U1)
{
    int tid = blockIdx.x * blockDim.x + threadIdx.x;  // BB*256*DD
    int e = tid % DD;
    int hw = (tid / DD) & 255;
    int b = tid / (DD * 256);
    float ur = 0.f, ui = 0.f;
    for (int t = 0; t < TT; t++) {
        int bt = b * TT + t;
        size_t base = (size_t)(bt * 256 + hw) * C2;
        float xr = XE[base + e], xi = XE[base + DD + e];
        float g = gate[bt * DD + e];
        float sr = src[bt * C2 + e], si = src[bt * C2 + DD + e];
        float fr = xr * g + sr * (1.f - g);
        float fi = xi * g + si * (1.f - g);
        float ofr = OF[bt * C2 + e], ofi = OF[bt * C2 + DD + e];
        float utr = fr * ofr - fi * ofi;
        float uti = fr * ofi + fi * ofr;
        float odr = OD[bt * C2 + e], odi = OD[bt * C2 + DD + e];
        float nr = ur * odr - ui * odi + utr;
        float ni = ur * odi + ui * odr + uti;
        ur = nr; ui = ni;
        hf hr, lr2, hi, li2;
        split_f(ur, hr, lr2);
        split_f(ui, hi, li2);
        U0[base + e] = hr;
        U0[base + DD + e] = hi;
        U1[base + e] = lr2;
        U1[base + DD + e] = li2;
    }
}

// ---------------- host side ----------------
template <typename T>
static T* sym(const void* s)
{
    void* p = nullptr;
    cudaGetSymbolAddress(&p, s);
    return (T*)p;
}

template <int MODE, bool CONV>
static void launch_gemm(const hf* A0, const hf* A1, const hf* B,
                        float* C, hf* C0, hf* C1, const float* Caux,
                        const float* bias, int N, int K)
{
    cudaFuncSetAttribute(hgemm_k<MODE, CONV>, cudaFuncAttributeMaxDynamicSharedMemorySize, SMEM_TOTAL_G);
    dim3 grid(N / 128, NP / 256);
    hgemm_k<MODE, CONV><<<grid, 256, SMEM_TOTAL_G>>>(A0, A1, B, C, C0, C1, Caux, bias, N, K);
}

extern "C" void kernel_launch(void* const* d_in, const int* in_sizes, int n_in,
                              void* d_out, int out_size)
{
    const float* x       = (const float*)d_in[0];
    const float* dt      = (const float*)d_in[1];
    const float* enc_w   = (const float*)d_in[2];
    const float* enc_b   = (const float*)d_in[3];
    const float* ns_g    = (const float*)d_in[4];
    const float* ns_b    = (const float*)d_in[5];
    const float* cw      = (const float*)d_in[6];
    const float* cb      = (const float*)d_in[7];
    const float* nt_g    = (const float*)d_in[8];
    const float* nt_b    = (const float*)d_in[9];
    const float* E_re    = (const float*)d_in[10];
    const float* E_im    = (const float*)d_in[11];
    const float* Ei_re   = (const float*)d_in[12];
    const float* Ei_im   = (const float*)d_in[13];
    const float* lamflux = (const float*)d_in[14];
    const float* Ws_re   = (const float*)d_in[15];
    const float* Ws_im   = (const float*)d_in[16];
    const float* Wg      = (const float*)d_in[17];
    const float* nu      = (const float*)d_in[18];
    const float* omega   = (const float*)d_in[19];
    const float* w1_re   = (const float*)d_in[20];
    const float* w1_im   = (const float*)d_in[21];
    const float* w2_re   = (const float*)d_in[22];
    const float* w2_im   = (const float*)d_in[23];
    const float* dec_w   = (const float*)d_in[24];
    const float* dec_b   = (const float*)d_in[25];
    float* out = (float*)d_out;

    float* Z   = sym<float>(g_Z);
    float* XE  = sym<float>(g_XE);
    float* DEC = sym<float>(g_DEC);
    hf* IM0  = sym<hf>(g_IM0);
    hf* IM1  = sym<hf>(g_IM1);
    hf* Ab0  = sym<hf>(g_Ab0);
    hf* Ab1  = sym<hf>(g_Ab1);
    hf* Zb0  = sym<hf>(g_Zb0);
    hf* Zb1  = sym<hf>(g_Zb1);
    hf* Hb0  = sym<hf>(g_Hb0);
    hf* Hb1  = sym<hf>(g_Hb1);
    hf* Wcb  = sym<hf>(g_Wcb);
    hf* Eb   = sym<hf>(g_Eb);
    hf* Eib  = sym<hf>(g_Eib);
    hf* W1b  = sym<hf>(g_W1b);
    hf* W2b  = sym<hf>(g_W2b);
    hf* encb = sym<hf>(g_encb);
    hf* decb = sym<hf>(g_decb);
    float* Wsb  = sym<float>(g_Wsbig);
    float* xm   = sym<float>(g_xmean);
    float* flux = sym<float>(g_flux);
    float* src  = sym<float>(g_src);
    float* gate = sym<float>(g_gate);
    float* OD   = sym<float>(g_OD);
    float* OF   = sym<float>(g_OF);

    // ---- build weights ----
    {
        dim3 blk(32, 8);
        for (int l = 0; l < LL; l++) {
            size_t oE = (size_t)l * C2 * C2;
            dim3 gE(C2 / 32, C2 / 32);
            build_cbigT_tile_k<<<gE, blk>>>(Eb + oE,
                                            E_re + (size_t)l * DD * DD, E_im + (size_t)l * DD * DD, DD, DD);
            build_cbigT_tile_k<<<gE, blk>>>(Eib + oE,
                                            Ei_re + (size_t)l * DD * DD, Ei_im + (size_t)l * DD * DD, DD, DD);
            build_cbig_k<<<(C2 * C2) / 256, 256>>>(Wsb + oE,
                                                   Ws_re + (size_t)l * DD * DD, Ws_im + (size_t)l * DD * DD, DD, DD);
            size_t o1 = (size_t)l * DFF2 * C2;
            dim3 g1(C2 / 32, DFF2 / 32);     // W1: K2=768, N2=3072
            build_cbigT_tile_k<<<g1, blk>>>(W1b + o1,
                                            w1_re + (size_t)l * DD * DFF, w1_im + (size_t)l * DD * DFF, DD, DFF);
            dim3 g2(DFF2 / 32, C2 / 32);     // W2: K2=3072, N2=768
            build_cbigT_tile_k<<<g2, blk>>>(W2b + o1,
                                            w2_re + (size_t)l * DFF * DD, w2_im + (size_t)l * DFF * DD, DFF, DD);
        }
        build_convwT_k<<<dim3(C2, LL), 256>>>(Wcb, cw);
        cvtw4_k<<<(C2 * KENC / 4 + 255) / 256, 256>>>(enc_w, encb, (size_t)C2 * KENC / 4);
        cvtw4_k<<<(NDEC * C2 / 4 + 255) / 256, 256>>>(dec_w, decb, (size_t)NDEC * C2 / 4);
    }

    // ---- encoder ----
    enc_im2col4_k<<<((size_t)NP * KENC / 4) / 256, 256>>>(IM0, IM1, x);
    launch_gemm<1, false>(IM0, IM1, encb, Z, nullptr, nullptr, nullptr, enc_b, C2, KENC);

    for (int l = 0; l < LL; l++) {
        // spatial: LN -> implicit conv3x3 GEMM; Z += conv+cb, emit Zb splits
        layernorm_k<<<NP, 256>>>(Z, ns_g + l * C2, ns_b + l * C2, Ab0, Ab1);
        launch_gemm<3, true>(Ab0, Ab1, Wcb + (size_t)l * C2 * KC,
                             Z, Zb0, Zb1, nullptr, cb + l * C2, C2, KC);

        // spectral: XE = Z @ E
        launch_gemm<0, false>(Zb0, Zb1, Eb + (size_t)l * C2 * C2,
                              XE, nullptr, nullptr, nullptr, nullptr, C2, C2);

        // temporal flux path
        rowmean_k<<<BT, C2>>>(XE, xm);
        fluxscan_k<<<6, 256>>>(xm, dt, lamflux + l * DD, Wg + l * DD, flux, gate);
        gemm_small_k<<<(BT * C2) / 256, 256>>>(flux, Wsb + (size_t)l * C2 * C2, src, BT, C2, C2);
        opdecay_k<<<(BT * DD) / 256, 256>>>(dt, nu + l * DD, omega + l * DD, OD, OF);
        fuscan_k<<<(BB * 256 * DD) / 256, 256>>>(XE, gate, src, OF, OD, Ab0, Ab1);

        // decode back: DEC = u_out @ Ei
        launch_gemm<0, false>(Ab0, Ab1, Eib + (size_t)l * C2 * C2,
                              DEC, nullptr, nullptr, nullptr, nullptr, C2, C2);

        // MLP on LN(DEC); Z += DEC + delta (fused)
        layernorm_k<<<NP, 256>>>(DEC, nt_g + l * C2, nt_b + l * C2, Zb0, Zb1);
        launch_gemm<4, false>(Zb0, Zb1, W1b + (size_t)l * DFF2 * C2,
                              nullptr, Hb0, Hb1, nullptr, nullptr, DFF2, C2);
        launch_gemm<6, false>(Hb0, Hb1, W2b + (size_t)l * C2 * DFF2,
                              Z, nullptr, nullptr, DEC, nullptr, C2, DFF2);
    }

    // ---- decoder GEMM with fused pixel-shuffle scatter ----
    split4_k<<<((size_t)NP * C2 / 4) / 256, 256>>>(Z, Ab0, Ab1, (size_t)NP * C2 / 4);
    launch_gemm<7, false>(Ab0, Ab1, decb, out, nullptr, nullptr, nullptr, dec_b, NDEC, C2);

    (void)in_sizes; (void)n_in; (void)out_size;
}

// round 10
// speedup vs baseline: 4.5119x; 1.6565x over previous
#include <cuda_runtime.h>
#include <cuda_fp16.h>
#include <math.h>
#include <stdint.h>

// ---------------- constants ----------------
#define BB 4
#define TT 12
#define BT 48
#define DD 384
#define C2 768
#define NP 12288
#define KC 6912
#define DFF 1536
#define DFF2 3072
#define KENC 1024
#define NDEC 1024
#define LL 4

typedef __half hf;

// ---------------- device scratch ----------------
__device__ float g_Z[(size_t)NP * C2];
__device__ float g_XE[(size_t)NP * C2];
__device__ float g_DEC[(size_t)NP * C2];
__device__ hf g_IM[(size_t)NP * KENC];
__device__ hf g_Ab[(size_t)NP * C2];
__device__ hf g_Zb[(size_t)NP * C2];
__device__ hf g_Hb[(size_t)NP * DFF2];
__device__ hf g_Wcb[(size_t)LL * C2 * KC];
__device__ hf g_Eb[(size_t)LL * C2 * C2];
__device__ hf g_Eib[(size_t)LL * C2 * C2];
__device__ hf g_W1b[(size_t)LL * DFF2 * C2];   // [N=3072][K=768]
__device__ hf g_W2b[(size_t)LL * C2 * DFF2];   // [N=768][K=3072]
__device__ hf g_encb[C2 * KENC];
__device__ hf g_decb[NDEC * C2];
__device__ float g_Wsbig[(size_t)LL * C2 * C2];
__device__ float g_xmean[BT * C2];
__device__ float g_flux[BT * C2];
__device__ float g_src[BT * C2];
__device__ float g_gate[BT * DD];
__device__ float g_OD[BT * C2];
__device__ float g_OF[BT * C2];

// ---------------- helpers ----------------
__device__ __forceinline__ float softplus_f(float x) {
    return (x > 20.f) ? x : log1pf(expf(x));
}
__device__ __forceinline__ float gelu_tanh(float x) {
    float x3 = x * x * x;
    float t = tanhf(0.7978845608028654f * (x + 0.044715f * x3));
    return 0.5f * x * (1.f + t);
}
__device__ __forceinline__ uint32_t smem_u32(const void* p) {
    uint32_t a;
    asm("{ .reg .u64 t; cvta.to.shared.u64 t, %1; cvt.u32.u64 %0, t; }" : "=r"(a) : "l"(p));
    return a;
}
__device__ __forceinline__ void cp16(uint32_t dst, const void* src) {
    asm volatile("cp.async.cg.shared.global [%0], [%1], 16;" :: "r"(dst), "l"(src) : "memory");
}
__device__ __forceinline__ void cp16z(uint32_t dst, const void* src, uint32_t sz) {
    asm volatile("cp.async.cg.shared.global [%0], [%1], 16, %2;" :: "r"(dst), "l"(src), "r"(sz) : "memory");
}
#define CP_COMMIT() asm volatile("cp.async.commit_group;" ::: "memory")
#define CP_WAIT0() asm volatile("cp.async.wait_group 0;" ::: "memory")
#define CP_WAIT1() asm volatile("cp.async.wait_group 1;" ::: "memory")

#define LDSM4(r, addr) \
    asm volatile("ldmatrix.sync.aligned.m8n8.x4.shared.b16 {%0,%1,%2,%3}, [%4];" \
                 : "=r"((r)[0]), "=r"((r)[1]), "=r"((r)[2]), "=r"((r)[3]) : "r"(addr))

#define MMA16816(d, a, bb0, bb1) \
    asm volatile("mma.sync.aligned.m16n8k16.row.col.f32.f16.f16.f32 " \
                 "{%0,%1,%2,%3}, {%4,%5,%6,%7}, {%8,%9}, {%0,%1,%2,%3};" \
                 : "+f"((d)[0]), "+f"((d)[1]), "+f"((d)[2]), "+f"((d)[3]) \
                 : "r"((a)[0]), "r"((a)[1]), "r"((a)[2]), "r"((a)[3]), \
                   "r"(bb0), "r"(bb1))

// ---------------- warp-MMA fp16 GEMM (single product) ----------------
// C[M=12288, N] = A @ B^T, A and B single fp16.
// Block tile 256x128x32, 8 warps (4M x 2N), warp tile 64x64.
// smem/stage: A 256x80B=20480 + B 128x80B=10240 -> 30720B; x2 stages = 60KB (2 CTA/SM).
// grid: x = N/128 (fast -> A tile L2 reuse), y = M/256.
// MODE: 0 store, 1 store+bias, 3 acc+bias+hf-emit, 4 gelu->hf, 6 Z-fuse, 7 dec-scatter
// CONV: A-loader does implicit 3x3 im2col from A [NP][C2] (K = 9*768).
#define MATA_B 20480
#define STAGE_B 30720
#define SMEM_TOTAL_G (2 * STAGE_B)

template <int MODE, bool CONV>
__global__ __launch_bounds__(256) void hgemm_k(
    const hf* __restrict__ A0, const hf* __restrict__ B,
    float* __restrict__ C, hf* __restrict__ C0,
    const float* __restrict__ Caux, const float* __restrict__ bias, int N, int K)
{
    extern __shared__ char smem[];
    uint32_t sb = smem_u32(smem);
    const int tid = threadIdx.x;
    const int wid = tid >> 5;
    const int lane = tid & 31;
    const int n0 = blockIdx.x * 128;
    const int m0 = blockIdx.y * 256;
    const int wm = wid & 3;       // 0..3 (M, x64)
    const int wn = wid >> 2;      // 0..1 (N, x64)

    auto load_chunk = [&](int k0, int buf) {
        uint32_t st = sb + buf * STAGE_B;
        // A: 256 rows x 4 vecs = 1024
#pragma unroll
        for (int i = 0; i < 4; i++) {
            int id = tid + 256 * i;
            int row = id >> 2, c4 = id & 3;
            uint32_t dst = st + row * 80 + c4 * 16;
            if (CONV) {
                int kk = k0 + c4 * 8;
                int rs = kk / 768;
                int ci = kk - rs * 768;
                int dy = rs / 3 - 1, dx = rs - (rs / 3) * 3 - 1;
                int m = m0 + row;
                int bt = m >> 8;
                int h = (m >> 4) & 15, w = m & 15;
                int hh = h + dy, ww = w + dx;
                bool ok = ((unsigned)hh < 16u) && ((unsigned)ww < 16u);
                const hf* sp = A0 + ((size_t)((bt << 8) + (hh << 4) + ww) * 768 + ci);
                if (!ok) sp = A0;
                cp16z(dst, sp, ok ? 16u : 0u);
            } else {
                cp16(dst, A0 + (size_t)(m0 + row) * K + k0 + c4 * 8);
            }
        }
        // B: 128 rows x 4 vecs = 512
#pragma unroll
        for (int i = 0; i < 2; i++) {
            int id = tid + 256 * i;
            int row = id >> 2, c4 = id & 3;
            uint32_t dst = st + MATA_B + row * 80 + c4 * 16;
            cp16(dst, B + (size_t)(n0 + row) * K + k0 + c4 * 8);
        }
    };

    float acc[4][8][4];
#pragma unroll
    for (int i = 0; i < 4; i++)
#pragma unroll
        for (int j = 0; j < 8; j++)
#pragma unroll
            for (int e = 0; e < 4; e++) acc[i][j][e] = 0.f;

    const int nc = K >> 5;
    load_chunk(0, 0);
    CP_COMMIT();

    const int lrow = lane & 15;
    const int lcol = lane >> 4;

    for (int c = 0; c < nc; c++) {
        int buf = c & 1;
        if (c + 1 < nc) {
            load_chunk((c + 1) << 5, buf ^ 1);
            CP_COMMIT();
            CP_WAIT1();
        } else {
            CP_WAIT0();
        }
        __syncthreads();
        uint32_t st = sb + buf * STAGE_B;
#pragma unroll
        for (int ks = 0; ks < 2; ks++) {
            uint32_t a0[4][4];
#pragma unroll
            for (int mi = 0; mi < 4; mi++) {
                uint32_t ad = st + (wm * 64 + mi * 16 + lrow) * 80 + ks * 32 + lcol * 16;
                LDSM4(a0[mi], ad);
            }
#pragma unroll
            for (int nq = 0; nq < 4; nq++) {
                uint32_t br[4];
                uint32_t bd = st + MATA_B + (wn * 64 + nq * 16 + lrow) * 80 + ks * 32 + lcol * 16;
                LDSM4(br, bd);
#pragma unroll
                for (int mi = 0; mi < 4; mi++) {
                    MMA16816(acc[mi][nq * 2],     a0[mi], br[0], br[2]);
                    MMA16816(acc[mi][nq * 2 + 1], a0[mi], br[1], br[3]);
                }
            }
        }
        __syncthreads();
    }

    // epilogue
#pragma unroll
    for (int mi = 0; mi < 4; mi++) {
#pragma unroll
        for (int nj = 0; nj < 8; nj++) {
            int row = m0 + wm * 64 + mi * 16 + (lane >> 2);
            int col = n0 + wn * 64 + nj * 8 + (lane & 3) * 2;
            float* d = acc[mi][nj];
#pragma unroll
            for (int h = 0; h < 2; h++) {
                int r = row + h * 8;
                float v0 = d[h * 2 + 0], v1 = d[h * 2 + 1];
                if (MODE == 1 || MODE == 3 || MODE == 7) {
                    v0 += bias[col];
                    v1 += bias[col + 1];
                }
                size_t co = (size_t)r * N + col;
                if (MODE == 0 || MODE == 1) {
                    C[co] = v0;
                    C[co + 1] = v1;
                } else if (MODE == 3) {
                    float z0 = C[co] + v0, z1 = C[co + 1] + v1;
                    C[co] = z0;
                    C[co + 1] = z1;
                    C0[co] = __float2half(z0);
                    C0[co + 1] = __float2half(z1);
                } else if (MODE == 4) {
                    C0[co] = __float2half(gelu_tanh(v0));
                    C0[co + 1] = __float2half(gelu_tanh(v1));
                } else if (MODE == 6) {
                    C[co] += Caux[co] + v0;
                    C[co + 1] += Caux[co + 1] + v1;
                } else if (MODE == 7) {
                    // pixel-shuffle scatter: r -> (bt,hp,wp), col -> (co4,pi,pj)
                    int bt = r >> 8;
                    int hp = (r >> 4) & 15, wp = r & 15;
                    int co4 = col >> 8;
                    int rem = col & 255;
                    int pi = rem >> 4, pj = rem & 15;
                    size_t o = (((size_t)(bt * 4 + co4) * 256 + hp * 16 + pi) * 256) + wp * 16 + pj;
                    C[o] = v0;
                    C[o + 1] = v1;
                }
            }
        }
    }
}

// ---------------- tiny fp32 GEMM (M=48) ----------------
__global__ void gemm_small_k(const float* __restrict__ A, const float* __restrict__ B,
                             float* __restrict__ C, int M, int N, int K)
{
    int idx = blockIdx.x * blockDim.x + threadIdx.x;
    if (idx >= M * N) return;
    int m = idx / N, n = idx % N;
    float s = 0.f;
    for (int k = 0; k < K; k++) s += A[(size_t)m * K + k] * B[(size_t)k * N + n];
    C[idx] = s;
}

// ---------------- weight builders ----------------
// fp32 big [2K][2N] for gemm_small
__global__ void build_cbig_k(float* __restrict__ dst, const float* __restrict__ re,
                             const float* __restrict__ im, int Kd, int Nd)
{
    int idx = blockIdx.x * blockDim.x + threadIdx.x;
    int N2 = 2 * Nd;
    if (idx >= 2 * Kd * N2) return;
    int k2 = idx / N2, n2 = idx % N2;
    bool ki = k2 >= Kd, ni = n2 >= Nd;
    int k = ki ? k2 - Kd : k2;
    int n = ni ? n2 - Nd : n2;
    float v;
    if (!ki && !ni) v = re[(size_t)k * Nd + n];
    else if (!ki && ni) v = im[(size_t)k * Nd + n];
    else if (ki && !ni) v = -im[(size_t)k * Nd + n];
    else v = re[(size_t)k * Nd + n];
    dst[idx] = v;
}

// tiled transpose: dst[n2][k2] = big[k2][n2] as single fp16
// grid (2Kd/32, 2Nd/32), block (32,8)
__global__ void build_cbigT_tile_k(hf* __restrict__ d0,
                                   const float* __restrict__ re, const float* __restrict__ im,
                                   int Kd, int Nd)
{
    __shared__ float tile[32][33];
    int k2_0 = blockIdx.x * 32, n2_0 = blockIdx.y * 32;
    bool ki = k2_0 >= Kd, ni = n2_0 >= Nd;
    int k0 = k2_0 - (ki ? Kd : 0), n0 = n2_0 - (ni ? Nd : 0);
    const float* s = (ki != ni) ? im : re;
    float sign = (ki && !ni) ? -1.f : 1.f;
    int tx = threadIdx.x, ty = threadIdx.y;
#pragma unroll
    for (int j = 0; j < 4; j++) {
        int r = ty + j * 8;
        tile[r][tx] = s[(size_t)(k0 + r) * Nd + n0 + tx];
    }
    __syncthreads();
    int K2 = 2 * Kd;
#pragma unroll
    for (int j = 0; j < 4; j++) {
        int r = ty + j * 8;
        float v = sign * tile[tx][r];
        d0[(size_t)(n2_0 + r) * K2 + k2_0 + tx] = __float2half(v);
    }
}

// conv weights: dst[l][co][rs*768+ci] = cw[l][co][ci][rs]; grid (C2, LL)
__global__ void build_convwT_k(hf* __restrict__ d0, const float* __restrict__ cw)
{
    __shared__ float s[KC];
    int co = blockIdx.x, l = blockIdx.y;
    const float* srcr = cw + ((size_t)(l * C2 + co)) * KC;
    for (int i = threadIdx.x; i < KC; i += 256) s[i] = srcr[i];
    __syncthreads();
    size_t base = ((size_t)l * C2 + co) * KC;
    for (int k = threadIdx.x; k < KC; k += 256) {
        int rs = k / 768;
        int ci = k - rs * 768;
        d0[base + k] = __float2half(s[ci * 9 + rs]);
    }
}

// fp32 -> single fp16, vectorized x4
__global__ void cvt4_k(const float* __restrict__ src, hf* __restrict__ d0, size_t n4)
{
    size_t idx = (size_t)blockIdx.x * blockDim.x + threadIdx.x;
    if (idx >= n4) return;
    float4 v = ((const float4*)src)[idx];
    __half2 p0 = {__float2half(v.x), __float2half(v.y)};
    __half2 p1 = {__float2half(v.z), __float2half(v.w)};
    ((__half2*)d0)[idx * 2] = p0;
    ((__half2*)d0)[idx * 2 + 1] = p1;
}

// ---------------- encoder im2col (vectorized x4, fp16) ----------------
__global__ void enc_im2col4_k(hf* __restrict__ P0, const float* __restrict__ x)
{
    size_t idx = (size_t)blockIdx.x * blockDim.x + threadIdx.x;  // NP*KENC/4
    size_t flat = idx * 4;
    int kk = flat % KENC;
    int n = flat / KENC;
    int cin = kk >> 8;
    int ii = (kk >> 4) & 15;
    int jj = kk & 15;
    int bt = n >> 8;
    int ph = (n >> 4) & 15;
    int pw = n & 15;
    const float* xp = x + ((((size_t)(bt * 4 + cin) * 256) + ph * 16 + ii) * 256 + pw * 16 + jj);
    float4 v = *(const float4*)xp;
    __half2 p0 = {__float2half(v.x), __float2half(v.y)};
    __half2 p1 = {__float2half(v.z), __float2half(v.w)};
    ((__half2*)P0)[idx * 2] = p0;
    ((__half2*)P0)[idx * 2 + 1] = p1;
}

// ---------------- layernorm over 768 channels, emits fp16 ----------------
__global__ void layernorm_k(const float* __restrict__ X, const float* __restrict__ g,
                            const float* __restrict__ b, hf* __restrict__ Y0)
{
    __shared__ float red[256];
    int n = blockIdx.x;
    int tid = threadIdx.x;
    const float* x = X + (size_t)n * C2;
    float v0 = x[tid], v1 = x[tid + 256], v2 = x[tid + 512];
    red[tid] = v0 + v1 + v2;
    __syncthreads();
    for (int off = 128; off > 0; off >>= 1) {
        if (tid < off) red[tid] += red[tid + off];
        __syncthreads();
    }
    float m = red[0] * (1.f / 768.f);
    __syncthreads();
    float d0 = v0 - m, d1 = v1 - m, d2 = v2 - m;
    red[tid] = d0 * d0 + d1 * d1 + d2 * d2;
    __syncthreads();
    for (int off = 128; off > 0; off >>= 1) {
        if (tid < off) red[tid] += red[tid + off];
        __syncthreads();
    }
    float var = red[0] * (1.f / 768.f);
    float rstd = rsqrtf(var + 1e-5f);
    size_t base = (size_t)n * C2;
    Y0[base + tid]       = __float2half(d0 * rstd * g[tid] + b[tid]);
    Y0[base + tid + 256] = __float2half(d1 * rstd * g[tid + 256] + b[tid + 256]);
    Y0[base + tid + 512] = __float2half(d2 * rstd * g[tid + 512] + b[tid + 512]);
}

// ---------------- mean over 256 spatial positions ----------------
__global__ void rowmean_k(const float* __restrict__ XE, float* __restrict__ xm)
{
    int bt = blockIdx.x;
    int c = threadIdx.x;
    float s = 0.f;
    const float* p = XE + (size_t)bt * 256 * C2 + c;
    for (int hw = 0; hw < 256; hw++) s += p[(size_t)hw * C2];
    xm[bt * C2 + c] = s * (1.f / 256.f);
}

// ---------------- flux scan + gate ----------------
__global__ void fluxscan_k(const float* __restrict__ xm, const float* __restrict__ dt,
                           const float* __restrict__ lamf_p, const float* __restrict__ Wg,
                           float* __restrict__ flux, float* __restrict__ gate)
{
    int tid = blockIdx.x * blockDim.x + threadIdx.x;
    int b = tid / DD, e = tid % DD;
    float lamf = softplus_f(lamf_p[e]);
    float wg = Wg[e];
    float fr = 0.f, fi = 0.f;
    for (int t = 0; t < TT; t++) {
        int bt = b * TT + t;
        float dtv = dt[bt];
        float a = expf(-lamf * dtv);
        float xr = xm[bt * C2 + e] * dtv;
        float xi = xm[bt * C2 + DD + e] * dtv;
        fr = fr * a + xr;
        fi = fi * a + xi;
        flux[bt * C2 + e] = fr;
        flux[bt * C2 + DD + e] = fi;
        gate[bt * DD + e] = 1.f / (1.f + expf(-fr * wg));
    }
}

// ---------------- op_decay / op_forcing ----------------
__global__ void opdecay_k(const float* __restrict__ dt, const float* __restrict__ nu,
                          const float* __restrict__ omega, float* __restrict__ OD,
                          float* __restrict__ OF)
{
    int idx = blockIdx.x * blockDim.x + threadIdx.x;
    int bt = idx / DD, e = idx % DD;
    float sp = softplus_f(nu[e]);
    float lr = fminf(fmaxf(-sp, -5.f), 0.3f);
    float li = omega[e];
    float dtv = dt[bt];
    float er = expf(lr * dtv);
    float odr = er * cosf(li * dtv);
    float odi = er * sinf(li * dtv);
    OD[bt * C2 + e] = odr;
    OD[bt * C2 + DD + e] = odi;
    float nr = odr - 1.f, ni = odi;
    float den = lr * lr + li * li;
    OF[bt * C2 + e] = (nr * lr + ni * li) / den;
    OF[bt * C2 + DD + e] = (ni * lr - nr * li) / den;
}

// ---------------- fused forcing + u scan, emits fp16 ----------------
__global__ void fuscan_k(const float* __restrict__ XE, const float* __restrict__ gate,
                         const float* __restrict__ src, const float* __restrict__ OF,
                         const float* __restrict__ OD, hf* __restrict__ U0)
{
    int tid = blockIdx.x * blockDim.x + threadIdx.x;  // BB*256*DD
    int e = tid % DD;
    int hw = (tid / DD) & 255;
    int b = tid / (DD * 256);
    float ur = 0.f, ui = 0.f;
    for (int t = 0; t < TT; t++) {
        int bt = b * TT + t;
        size_t base = (size_t)(bt * 256 + hw) * C2;
        float xr = XE[base + e], xi = XE[base + DD + e];
        float g = gate[bt * DD + e];
        float sr = src[bt * C2 + e], si = src[bt * C2 + DD + e];
        float fr = xr * g + sr * (1.f - g);
        float fi = xi * g + si * (1.f - g);
        float ofr = OF[bt * C2 + e], ofi = OF[bt * C2 + DD + e];
        float utr = fr * ofr - fi * ofi;
        float uti = fr * ofi + fi * ofr;
        float odr = OD[bt * C2 + e], odi = OD[bt * C2 + DD + e];
        float nr = ur * odr - ui * odi + utr;
        float ni = ur * odi + ui * odr + uti;
        ur = nr; ui = ni;
        U0[base + e] = __float2half(ur);
        U0[base + DD + e] = __float2half(ui);
    }
}

// ---------------- host side ----------------
template <typename T>
static T* sym(const void* s)
{
    void* p = nullptr;
    cudaGetSymbolAddress(&p, s);
    return (T*)p;
}

template <int MODE, bool CONV>
static void launch_gemm(const hf* A0, const hf* B,
                        float* C, hf* C0, const float* Caux,
                        const float* bias, int N, int K)
{
    cudaFuncSetAttribute(hgemm_k<MODE, CONV>, cudaFuncAttributeMaxDynamicSharedMemorySize, SMEM_TOTAL_G);
    dim3 grid(N / 128, NP / 256);
    hgemm_k<MODE, CONV><<<grid, 256, SMEM_TOTAL_G>>>(A0, B, C, C0, Caux, bias, N, K);
}

extern "C" void kernel_launch(void* const* d_in, const int* in_sizes, int n_in,
                              void* d_out, int out_size)
{
    const float* x       = (const float*)d_in[0];
    const float* dt      = (const float*)d_in[1];
    const float* enc_w   = (const float*)d_in[2];
    const float* enc_b   = (const float*)d_in[3];
    const float* ns_g    = (const float*)d_in[4];
    const float* ns_b    = (const float*)d_in[5];
    const float* cw      = (const float*)d_in[6];
    const float* cb      = (const float*)d_in[7];
    const float* nt_g    = (const float*)d_in[8];
    const float* nt_b    = (const float*)d_in[9];
    const float* E_re    = (const float*)d_in[10];
    const float* E_im    = (const float*)d_in[11];
    const float* Ei_re   = (const float*)d_in[12];
    const float* Ei_im   = (const float*)d_in[13];
    const float* lamflux = (const float*)d_in[14];
    const float* Ws_re   = (const float*)d_in[15];
    const float* Ws_im   = (const float*)d_in[16];
    const float* Wg      = (const float*)d_in[17];
    const float* nu      = (const float*)d_in[18];
    const float* omega   = (const float*)d_in[19];
    const float* w1_re   = (const float*)d_in[20];
    const float* w1_im   = (const float*)d_in[21];
    const float* w2_re   = (const float*)d_in[22];
    const float* w2_im   = (const float*)d_in[23];
    const float* dec_w   = (const float*)d_in[24];
    const float* dec_b   = (const float*)d_in[25];
    float* out = (float*)d_out;

    float* Z   = sym<float>(g_Z);
    float* XE  = sym<float>(g_XE);
    float* DEC = sym<float>(g_DEC);
    hf* IM   = sym<hf>(g_IM);
    hf* Ab   = sym<hf>(g_Ab);
    hf* Zb   = sym<hf>(g_Zb);
    hf* Hb   = sym<hf>(g_Hb);
    hf* Wcb  = sym<hf>(g_Wcb);
    hf* Eb   = sym<hf>(g_Eb);
    hf* Eib  = sym<hf>(g_Eib);
    hf* W1b  = sym<hf>(g_W1b);
    hf* W2b  = sym<hf>(g_W2b);
    hf* encb = sym<hf>(g_encb);
    hf* decb = sym<hf>(g_decb);
    float* Wsb  = sym<float>(g_Wsbig);
    float* xm   = sym<float>(g_xmean);
    float* flux = sym<float>(g_flux);
    float* src  = sym<float>(g_src);
    float* gate = sym<float>(g_gate);
    float* OD   = sym<float>(g_OD);
    float* OF   = sym<float>(g_OF);

    // ---- build weights ----
    {
        dim3 blk(32, 8);
        for (int l = 0; l < LL; l++) {
            size_t oE = (size_t)l * C2 * C2;
            dim3 gE(C2 / 32, C2 / 32);
            build_cbigT_tile_k<<<gE, blk>>>(Eb + oE,
                                            E_re + (size_t)l * DD * DD, E_im + (size_t)l * DD * DD, DD, DD);
            build_cbigT_tile_k<<<gE, blk>>>(Eib + oE,
                                            Ei_re + (size_t)l * DD * DD, Ei_im + (size_t)l * DD * DD, DD, DD);
            build_cbig_k<<<(C2 * C2) / 256, 256>>>(Wsb + oE,
                                                   Ws_re + (size_t)l * DD * DD, Ws_im + (size_t)l * DD * DD, DD, DD);
            size_t o1 = (size_t)l * DFF2 * C2;
            dim3 g1(C2 / 32, DFF2 / 32);     // W1: K2=768, N2=3072
            build_cbigT_tile_k<<<g1, blk>>>(W1b + o1,
                                            w1_re + (size_t)l * DD * DFF, w1_im + (size_t)l * DD * DFF, DD, DFF);
            dim3 g2(DFF2 / 32, C2 / 32);     // W2: K2=3072, N2=768
            build_cbigT_tile_k<<<g2, blk>>>(W2b + o1,
                                            w2_re + (size_t)l * DFF * DD, w2_im + (size_t)l * DFF * DD, DFF, DD);
        }
        build_convwT_k<<<dim3(C2, LL), 256>>>(Wcb, cw);
        cvt4_k<<<(C2 * KENC / 4 + 255) / 256, 256>>>(enc_w, encb, (size_t)C2 * KENC / 4);
        cvt4_k<<<(NDEC * C2 / 4 + 255) / 256, 256>>>(dec_w, decb, (size_t)NDEC * C2 / 4);
    }

    // ---- encoder ----
    enc_im2col4_k<<<((size_t)NP * KENC / 4) / 256, 256>>>(IM, x);
    launch_gemm<1, false>(IM, encb, Z, nullptr, nullptr, enc_b, C2, KENC);

    for (int l = 0; l < LL; l++) {
        // spatial: LN -> implicit conv3x3 GEMM; Z += conv+cb, emit Zb fp16
        layernorm_k<<<NP, 256>>>(Z, ns_g + l * C2, ns_b + l * C2, Ab);
        launch_gemm<3, true>(Ab, Wcb + (size_t)l * C2 * KC, Z, Zb, nullptr, cb + l * C2, C2, KC);

        // spectral: XE = Z @ E
        launch_gemm<0, false>(Zb, Eb + (size_t)l * C2 * C2, XE, nullptr, nullptr, nullptr, C2, C2);

        // temporal flux path
        rowmean_k<<<BT, C2>>>(XE, xm);
        fluxscan_k<<<6, 256>>>(xm, dt, lamflux + l * DD, Wg + l * DD, flux, gate);
        gemm_small_k<<<(BT * C2) / 256, 256>>>(flux, Wsb + (size_t)l * C2 * C2, src, BT, C2, C2);
        opdecay_k<<<(BT * DD) / 256, 256>>>(dt, nu + l * DD, omega + l * DD, OD, OF);
        fuscan_k<<<(BB * 256 * DD) / 256, 256>>>(XE, gate, src, OF, OD, Ab);

        // decode back: DEC = u_out @ Ei
        launch_gemm<0, false>(Ab, Eib + (size_t)l * C2 * C2, DEC, nullptr, nullptr, nullptr, C2, C2);

        // MLP on LN(DEC); Z += DEC + delta (fused)
        layernorm_k<<<NP, 256>>>(DEC, nt_g + l * C2, nt_b + l * C2, Zb);
        launch_gemm<4, false>(Zb, W1b + (size_t)l * DFF2 * C2, nullptr, Hb, nullptr, nullptr, DFF2, C2);
        launch_gemm<6, false>(Hb, W2b + (size_t)l * C2 * DFF2, Z, nullptr, DEC, nullptr, C2, DFF2);
    }

    // ---- decoder GEMM with fused pixel-shuffle scatter ----
    cvt4_k<<<((size_t)NP * C2 / 4) / 256, 256>>>(Z, Ab, (size_t)NP * C2 / 4);
    launch_gemm<7, false>(Ab, decb, out, nullptr, nullptr, dec_b, NDEC, C2);

    (void)in_sizes; (void)n_in; (void)out_size;
}

// round 12
// speedup vs baseline: 4.8542x; 1.0759x over previous
#include <cuda_runtime.h>
#include <cuda_fp16.h>
#include <math.h>
#include <stdint.h>

// ---------------- constants ----------------
#define BB 4
#define TT 12
#define BT 48
#define DD 384
#define C2 768
#define NP 12288
#define KC 6912
#define DFF 1536
#define DFF2 3072
#define KENC 1024
#define NDEC 1024
#define LL 4

typedef __half hf;

// ---------------- device scratch ----------------
__device__ float g_Z[(size_t)NP * C2];
__device__ float g_XE[(size_t)NP * C2];
__device__ float g_DEC[(size_t)NP * C2];
__device__ hf g_IM[(size_t)NP * KENC];
__device__ hf g_Ab[(size_t)NP * C2];
__device__ hf g_Zb[(size_t)NP * C2];
__device__ hf g_Fb[(size_t)NP * C2];      // fp16 of final Z (decoder input)
__device__ hf g_Hb[(size_t)NP * DFF2];
__device__ hf g_Wcb[(size_t)LL * C2 * KC];
__device__ hf g_Eb[(size_t)LL * C2 * C2];
__device__ hf g_Eib[(size_t)LL * C2 * C2];
__device__ hf g_W1b[(size_t)LL * DFF2 * C2];   // [N=3072][K=768]
__device__ hf g_W2b[(size_t)LL * C2 * DFF2];   // [N=768][K=3072]
__device__ hf g_encb[C2 * KENC];
__device__ hf g_decb[NDEC * C2];
__device__ float g_Wsbig[(size_t)LL * C2 * C2];
__device__ float g_xmean[BT * C2];
__device__ float g_flux[BT * C2];
__device__ float g_src[BT * C2];
__device__ float g_gate[BT * DD];
__device__ float g_OD[BT * C2];
__device__ float g_OF[BT * C2];

// ---------------- helpers ----------------
__device__ __forceinline__ float softplus_f(float x) {
    return (x > 20.f) ? x : log1pf(expf(x));
}
__device__ __forceinline__ float gelu_tanh(float x) {
    float x3 = x * x * x;
    float t = tanhf(0.7978845608028654f * (x + 0.044715f * x3));
    return 0.5f * x * (1.f + t);
}
__device__ __forceinline__ uint32_t smem_u32(const void* p) {
    uint32_t a;
    asm("{ .reg .u64 t; cvta.to.shared.u64 t, %1; cvt.u32.u64 %0, t; }" : "=r"(a) : "l"(p));
    return a;
}
__device__ __forceinline__ void cp16(uint32_t dst, const void* src) {
    asm volatile("cp.async.cg.shared.global [%0], [%1], 16;" :: "r"(dst), "l"(src) : "memory");
}
__device__ __forceinline__ void cp16z(uint32_t dst, const void* src, uint32_t sz) {
    asm volatile("cp.async.cg.shared.global [%0], [%1], 16, %2;" :: "r"(dst), "l"(src), "r"(sz) : "memory");
}
#define CP_COMMIT() asm volatile("cp.async.commit_group;" ::: "memory")

#define LDSM4(r, addr) \
    asm volatile("ldmatrix.sync.aligned.m8n8.x4.shared.b16 {%0,%1,%2,%3}, [%4];" \
                 : "=r"((r)[0]), "=r"((r)[1]), "=r"((r)[2]), "=r"((r)[3]) : "r"(addr))

#define MMA16816(d, a, bb0, bb1) \
    asm volatile("mma.sync.aligned.m16n8k16.row.col.f32.f16.f16.f32 " \
                 "{%0,%1,%2,%3}, {%4,%5,%6,%7}, {%8,%9}, {%0,%1,%2,%3};" \
                 : "+f"((d)[0]), "+f"((d)[1]), "+f"((d)[2]), "+f"((d)[3]) \
                 : "r"((a)[0]), "r"((a)[1]), "r"((a)[2]), "r"((a)[3]), \
                   "r"(bb0), "r"(bb1))

// ---------------- warp-MMA fp16 GEMM (single product, 3-stage pipeline) ----------------
// C[M=12288, N] = A @ B^T, A and B single fp16.
// Block tile 256x128x32, 8 warps (4M x 2N), warp tile 64x64.
// smem/stage: A 256x80B=20480 + B 128x80B=10240 -> 30720B; x3 stages = 92160B (2 CTA/SM).
// grid: x = N/128 (fast -> A tile L2 reuse), y = M/256.
// MODE: 0 store, 1 store+bias, 3 acc+bias+hf-emit, 4 gelu->hf, 6 Z-fuse+hf-emit, 7 dec-scatter
// CONV: A-loader does implicit 3x3 im2col from A [NP][C2] (K = 9*768).
// NOTE: load_chunk takes k0 as an ELEMENT offset (chunk << 5) — cp.async 16B
// alignment depends on it (R11 regression: passing a chunk index misaligns src).
#define MATA_B 20480
#define STAGE_B 30720
#define SMEM_TOTAL_G (3 * STAGE_B)

template <int MODE, bool CONV>
__global__ __launch_bounds__(256) void hgemm_k(
    const hf* __restrict__ A0, const hf* __restrict__ B,
    float* __restrict__ C, hf* __restrict__ C0,
    const float* __restrict__ Caux, const float* __restrict__ bias, int N, int K)
{
    extern __shared__ char smem[];
    uint32_t sb = smem_u32(smem);
    const int tid = threadIdx.x;
    const int wid = tid >> 5;
    const int lane = tid & 31;
    const int n0 = blockIdx.x * 128;
    const int m0 = blockIdx.y * 256;
    const int wm = wid & 3;       // 0..3 (M, x64)
    const int wn = wid >> 2;      // 0..1 (N, x64)

    auto load_chunk = [&](int k0, int buf) {
        uint32_t st = sb + buf * STAGE_B;
        // A: 256 rows x 4 vecs = 1024
#pragma unroll
        for (int i = 0; i < 4; i++) {
            int id = tid + 256 * i;
            int row = id >> 2, c4 = id & 3;
            uint32_t dst = st + row * 80 + c4 * 16;
            if (CONV) {
                int kk = k0 + c4 * 8;
                int rs = kk / 768;
                int ci = kk - rs * 768;
                int dy = rs / 3 - 1, dx = rs - (rs / 3) * 3 - 1;
                int m = m0 + row;
                int bt = m >> 8;
                int h = (m >> 4) & 15, w = m & 15;
                int hh = h + dy, ww = w + dx;
                bool ok = ((unsigned)hh < 16u) && ((unsigned)ww < 16u);
                const hf* sp = A0 + ((size_t)((bt << 8) + (hh << 4) + ww) * 768 + ci);
                if (!ok) sp = A0;
                cp16z(dst, sp, ok ? 16u : 0u);
            } else {
                cp16(dst, A0 + (size_t)(m0 + row) * K + k0 + c4 * 8);
            }
        }
        // B: 128 rows x 4 vecs = 512
#pragma unroll
        for (int i = 0; i < 2; i++) {
            int id = tid + 256 * i;
            int row = id >> 2, c4 = id & 3;
            uint32_t dst = st + MATA_B + row * 80 + c4 * 16;
            cp16(dst, B + (size_t)(n0 + row) * K + k0 + c4 * 8);
        }
    };

    float acc[4][8][4];
#pragma unroll
    for (int i = 0; i < 4; i++)
#pragma unroll
        for (int j = 0; j < 8; j++)
#pragma unroll
            for (int e = 0; e < 4; e++) acc[i][j][e] = 0.f;

    const int nc = K >> 5;   // all GEMMs have nc >= 24
    load_chunk(0, 0);
    CP_COMMIT();
    load_chunk(32, 1);
    CP_COMMIT();

    const int lrow = lane & 15;
    const int lcol = lane >> 4;

    for (int c = 0; c < nc; c++) {
        int buf = c % 3;
        if (c + 2 < nc) {
            load_chunk((c + 2) << 5, (c + 2) % 3);
            CP_COMMIT();
            asm volatile("cp.async.wait_group 2;" ::: "memory");
        } else if (c + 1 < nc) {
            asm volatile("cp.async.wait_group 1;" ::: "memory");
        } else {
            asm volatile("cp.async.wait_group 0;" ::: "memory");
        }
        __syncthreads();
        uint32_t st = sb + buf * STAGE_B;
#pragma unroll
        for (int ks = 0; ks < 2; ks++) {
            uint32_t a0[4][4];
#pragma unroll
            for (int mi = 0; mi < 4; mi++) {
                uint32_t ad = st + (wm * 64 + mi * 16 + lrow) * 80 + ks * 32 + lcol * 16;
                LDSM4(a0[mi], ad);
            }
#pragma unroll
            for (int nq = 0; nq < 4; nq++) {
                uint32_t br[4];
                uint32_t bd = st + MATA_B + (wn * 64 + nq * 16 + lrow) * 80 + ks * 32 + lcol * 16;
                LDSM4(br, bd);
#pragma unroll
                for (int mi = 0; mi < 4; mi++) {
                    MMA16816(acc[mi][nq * 2],     a0[mi], br[0], br[2]);
                    MMA16816(acc[mi][nq * 2 + 1], a0[mi], br[1], br[3]);
                }
            }
        }
        __syncthreads();
    }

    // epilogue (vectorized: float2 / half2)
#pragma unroll
    for (int mi = 0; mi < 4; mi++) {
#pragma unroll
        for (int nj = 0; nj < 8; nj++) {
            int row = m0 + wm * 64 + mi * 16 + (lane >> 2);
            int col = n0 + wn * 64 + nj * 8 + (lane & 3) * 2;
            float* d = acc[mi][nj];
#pragma unroll
            for (int h = 0; h < 2; h++) {
                int r = row + h * 8;
                float v0 = d[h * 2 + 0], v1 = d[h * 2 + 1];
                if (MODE == 1 || MODE == 3 || MODE == 7) {
                    v0 += bias[col];
                    v1 += bias[col + 1];
                }
                size_t co = (size_t)r * N + col;
                if (MODE == 0 || MODE == 1) {
                    *(float2*)(C + co) = make_float2(v0, v1);
                } else if (MODE == 3) {
                    float2 zc = *(const float2*)(C + co);
                    float z0 = zc.x + v0, z1 = zc.y + v1;
                    *(float2*)(C + co) = make_float2(z0, z1);
                    *(__half2*)(C0 + co) = __floats2half2_rn(z0, z1);
                } else if (MODE == 4) {
                    *(__half2*)(C0 + co) = __floats2half2_rn(gelu_tanh(v0), gelu_tanh(v1));
                } else if (MODE == 6) {
                    float2 ax = *(const float2*)(Caux + co);
                    float2 zc = *(const float2*)(C + co);
                    float z0 = zc.x + ax.x + v0, z1 = zc.y + ax.y + v1;
                    *(float2*)(C + co) = make_float2(z0, z1);
                    *(__half2*)(C0 + co) = __floats2half2_rn(z0, z1);
                } else if (MODE == 7) {
                    // pixel-shuffle scatter: r -> (bt,hp,wp), col -> (co4,pi,pj)
                    int bt = r >> 8;
                    int hp = (r >> 4) & 15, wp = r & 15;
                    int co4 = col >> 8;
                    int rem = col & 255;
                    int pi = rem >> 4, pj = rem & 15;
                    size_t o = (((size_t)(bt * 4 + co4) * 256 + hp * 16 + pi) * 256) + wp * 16 + pj;
                    *(float2*)(C + o) = make_float2(v0, v1);
                }
            }
        }
    }
}

// ---------------- tiny fp32 GEMM (M=48) ----------------
__global__ void gemm_small_k(const float* __restrict__ A, const float* __restrict__ B,
                             float* __restrict__ C, int M, int N, int K)
{
    int idx = blockIdx.x * blockDim.x + threadIdx.x;
    if (idx >= M * N) return;
    int m = idx / N, n = idx % N;
    float s = 0.f;
    for (int k = 0; k < K; k++) s += A[(size_t)m * K + k] * B[(size_t)k * N + n];
    C[idx] = s;
}

// ---------------- weight builders (batched over layers) ----------------
// fp32 big [2K][2N] for gemm_small; blockIdx.y = layer
__global__ void build_cbig_k(float* __restrict__ dst, const float* __restrict__ re,
                             const float* __restrict__ im, int Kd, int Nd)
{
    int l = blockIdx.y;
    dst += (size_t)l * (4 * Kd * Nd);
    re += (size_t)l * Kd * Nd;
    im += (size_t)l * Kd * Nd;
    int idx = blockIdx.x * blockDim.x + threadIdx.x;
    int N2 = 2 * Nd;
    if (idx >= 2 * Kd * N2) return;
    int k2 = idx / N2, n2 = idx % N2;
    bool ki = k2 >= Kd, ni = n2 >= Nd;
    int k = ki ? k2 - Kd : k2;
    int n = ni ? n2 - Nd : n2;
    float v;
    if (!ki && !ni) v = re[(size_t)k * Nd + n];
    else if (!ki && ni) v = im[(size_t)k * Nd + n];
    else if (ki && !ni) v = -im[(size_t)k * Nd + n];
    else v = re[(size_t)k * Nd + n];
    dst[idx] = v;
}

// tiled transpose: dst[n2][k2] = big[k2][n2] as single fp16; blockIdx.z = layer
// grid (2Kd/32, 2Nd/32, L), block (32,8)
__global__ void build_cbigT_tile_k(hf* __restrict__ d0,
                                   const float* __restrict__ re, const float* __restrict__ im,
                                   int Kd, int Nd)
{
    __shared__ float tile[32][33];
    int l = blockIdx.z;
    d0 += (size_t)l * (4 * Kd * Nd);
    re += (size_t)l * Kd * Nd;
    im += (size_t)l * Kd * Nd;
    int k2_0 = blockIdx.x * 32, n2_0 = blockIdx.y * 32;
    bool ki = k2_0 >= Kd, ni = n2_0 >= Nd;
    int k0 = k2_0 - (ki ? Kd : 0), n0 = n2_0 - (ni ? Nd : 0);
    const float* s = (ki != ni) ? im : re;
    float sign = (ki && !ni) ? -1.f : 1.f;
    int tx = threadIdx.x, ty = threadIdx.y;
#pragma unroll
    for (int j = 0; j < 4; j++) {
        int r = ty + j * 8;
        tile[r][tx] = s[(size_t)(k0 + r) * Nd + n0 + tx];
    }
    __syncthreads();
    int K2 = 2 * Kd;
#pragma unroll
    for (int j = 0; j < 4; j++) {
        int r = ty + j * 8;
        float v = sign * tile[tx][r];
        d0[(size_t)(n2_0 + r) * K2 + k2_0 + tx] = __float2half(v);
    }
}

// conv weights: dst[l][co][rs*768+ci] = cw[l][co][ci][rs]; grid (C2, LL)
__global__ void build_convwT_k(hf* __restrict__ d0, const float* __restrict__ cw)
{
    __shared__ float s[KC];
    int co = blockIdx.x, l = blockIdx.y;
    const float* srcr = cw + ((size_t)(l * C2 + co)) * KC;
    for (int i = threadIdx.x; i < KC; i += 256) s[i] = srcr[i];
    __syncthreads();
    size_t base = ((size_t)l * C2 + co) * KC;
    for (int k = threadIdx.x; k < KC; k += 256) {
        int rs = k / 768;
        int ci = k - rs * 768;
        d0[base + k] = __float2half(s[ci * 9 + rs]);
    }
}

// fp32 -> single fp16, vectorized x4
__global__ void cvt4_k(const float* __restrict__ src, hf* __restrict__ d0, size_t n4)
{
    size_t idx = (size_t)blockIdx.x * blockDim.x + threadIdx.x;
    if (idx >= n4) return;
    float4 v = ((const float4*)src)[idx];
    __half2 p0 = {__float2half(v.x), __float2half(v.y)};
    __half2 p1 = {__float2half(v.z), __float2half(v.w)};
    ((__half2*)d0)[idx * 2] = p0;
    ((__half2*)d0)[idx * 2 + 1] = p1;
}

// ---------------- encoder im2col (vectorized x4, fp16) ----------------
__global__ void enc_im2col4_k(hf* __restrict__ P0, const float* __restrict__ x)
{
    size_t idx = (size_t)blockIdx.x * blockDim.x + threadIdx.x;  // NP*KENC/4
    size_t flat = idx * 4;
    int kk = flat % KENC;
    int n = flat / KENC;
    int cin = kk >> 8;
    int ii = (kk >> 4) & 15;
    int jj = kk & 15;
    int bt = n >> 8;
    int ph = (n >> 4) & 15;
    int pw = n & 15;
    const float* xp = x + ((((size_t)(bt * 4 + cin) * 256) + ph * 16 + ii) * 256 + pw * 16 + jj);
    float4 v = *(const float4*)xp;
    __half2 p0 = {__float2half(v.x), __float2half(v.y)};
    __half2 p1 = {__float2half(v.z), __float2half(v.w)};
    ((__half2*)P0)[idx * 2] = p0;
    ((__half2*)P0)[idx * 2 + 1] = p1;
}

// ---------------- layernorm over 768 channels, emits fp16 ----------------
__global__ void layernorm_k(const float* __restrict__ X, const float* __restrict__ g,
                            const float* __restrict__ b, hf* __restrict__ Y0)
{
    __shared__ float red[256];
    int n = blockIdx.x;
    int tid = threadIdx.x;
    const float* x = X + (size_t)n * C2;
    float v0 = x[tid], v1 = x[tid + 256], v2 = x[tid + 512];
    red[tid] = v0 + v1 + v2;
    __syncthreads();
    for (int off = 128; off > 0; off >>= 1) {
        if (tid < off) red[tid] += red[tid + off];
        __syncthreads();
    }
    float m = red[0] * (1.f / 768.f);
    __syncthreads();
    float d0 = v0 - m, d1 = v1 - m, d2 = v2 - m;
    red[tid] = d0 * d0 + d1 * d1 + d2 * d2;
    __syncthreads();
    for (int off = 128; off > 0; off >>= 1) {
        if (tid < off) red[tid] += red[tid + off];
        __syncthreads();
    }
    float var = red[0] * (1.f / 768.f);
    float rstd = rsqrtf(var + 1e-5f);
    size_t base = (size_t)n * C2;
    Y0[base + tid]       = __float2half(d0 * rstd * g[tid] + b[tid]);
    Y0[base + tid + 256] = __float2half(d1 * rstd * g[tid + 256] + b[tid + 256]);
    Y0[base + tid + 512] = __float2half(d2 * rstd * g[tid + 512] + b[tid + 512]);
}

// ---------------- mean over 256 spatial positions ----------------
__global__ void rowmean_k(const float* __restrict__ XE, float* __restrict__ xm)
{
    int bt = blockIdx.x;
    int c = threadIdx.x;
    float s = 0.f;
    const float* p = XE + (size_t)bt * 256 * C2 + c;
    for (int hw = 0; hw < 256; hw++) s += p[(size_t)hw * C2];
    xm[bt * C2 + c] = s * (1.f / 256.f);
}

// ---------------- flux scan + gate ----------------
__global__ void fluxscan_k(const float* __restrict__ xm, const float* __restrict__ dt,
                           const float* __restrict__ lamf_p, const float* __restrict__ Wg,
                           float* __restrict__ flux, float* __restrict__ gate)
{
    int tid = blockIdx.x * blockDim.x + threadIdx.x;
    int b = tid / DD, e = tid % DD;
    float lamf = softplus_f(lamf_p[e]);
    float wg = Wg[e];
    float fr = 0.f, fi = 0.f;
    for (int t = 0; t < TT; t++) {
        int bt = b * TT + t;
        float dtv = dt[bt];
        float a = expf(-lamf * dtv);
        float xr = xm[bt * C2 + e] * dtv;
        float xi = xm[bt * C2 + DD + e] * dtv;
        fr = fr * a + xr;
        fi = fi * a + xi;
        flux[bt * C2 + e] = fr;
        flux[bt * C2 + DD + e] = fi;
        gate[bt * DD + e] = 1.f / (1.f + expf(-fr * wg));
    }
}

// ---------------- op_decay / op_forcing ----------------
__global__ void opdecay_k(const float* __restrict__ dt, const float* __restrict__ nu,
                          const float* __restrict__ omega, float* __restrict__ OD,
                          float* __restrict__ OF)
{
    int idx = blockIdx.x * blockDim.x + threadIdx.x;
    int bt = idx / DD, e = idx % DD;
    float sp = softplus_f(nu[e]);
    float lr = fminf(fmaxf(-sp, -5.f), 0.3f);
    float li = omega[e];
    float dtv = dt[bt];
    float er = expf(lr * dtv);
    float odr = er * cosf(li * dtv);
    float odi = er * sinf(li * dtv);
    OD[bt * C2 + e] = odr;
    OD[bt * C2 + DD + e] = odi;
    float nr = odr - 1.f, ni = odi;
    float den = lr * lr + li * li;
    OF[bt * C2 + e] = (nr * lr + ni * li) / den;
    OF[bt * C2 + DD + e] = (ni * lr - nr * li) / den;
}

// ---------------- fused forcing + u scan, emits fp16 ----------------
__global__ void fuscan_k(const float* __restrict__ XE, const float* __restrict__ gate,
                         const float* __restrict__ src, const float* __restrict__ OF,
                         const float* __restrict__ OD, hf* __restrict__ U0)
{
    int tid = blockIdx.x * blockDim.x + threadIdx.x;  // BB*256*DD
    int e = tid % DD;
    int hw = (tid / DD) & 255;
    int b = tid / (DD * 256);
    float ur = 0.f, ui = 0.f;
    for (int t = 0; t < TT; t++) {
        int bt = b * TT + t;
        size_t base = (size_t)(bt * 256 + hw) * C2;
        float xr = XE[base + e], xi = XE[base + DD + e];
        float g = gate[bt * DD + e];
        float sr = src[bt * C2 + e], si = src[bt * C2 + DD + e];
        float fr = xr * g + sr * (1.f - g);
        float fi = xi * g + si * (1.f - g);
        float ofr = OF[bt * C2 + e], ofi = OF[bt * C2 + DD + e];
        float utr = fr * ofr - fi * ofi;
        float uti = fr * ofi + fi * ofr;
        float odr = OD[bt * C2 + e], odi = OD[bt * C2 + DD + e];
        float nr = ur * odr - ui * odi + utr;
        float ni = ur * odi + ui * odr + uti;
        ur = nr; ui = ni;
        U0[base + e] = __float2half(ur);
        U0[base + DD + e] = __float2half(ui);
    }
}

// ---------------- host side ----------------
template <typename T>
static T* sym(const void* s)
{
    void* p = nullptr;
    cudaGetSymbolAddress(&p, s);
    return (T*)p;
}

template <int MODE, bool CONV>
static void launch_gemm(const hf* A0, const hf* B,
                        float* C, hf* C0, const float* Caux,
                        const float* bias, int N, int K)
{
    cudaFuncSetAttribute(hgemm_k<MODE, CONV>, cudaFuncAttributeMaxDynamicSharedMemorySize, SMEM_TOTAL_G);
    dim3 grid(N / 128, NP / 256);
    hgemm_k<MODE, CONV><<<grid, 256, SMEM_TOTAL_G>>>(A0, B, C, C0, Caux, bias, N, K);
}

extern "C" void kernel_launch(void* const* d_in, const int* in_sizes, int n_in,
                              void* d_out, int out_size)
{
    const float* x       = (const float*)d_in[0];
    const float* dt      = (const float*)d_in[1];
    const float* enc_w   = (const float*)d_in[2];
    const float* enc_b   = (const float*)d_in[3];
    const float* ns_g    = (const float*)d_in[4];
    const float* ns_b    = (const float*)d_in[5];
    const float* cw      = (const float*)d_in[6];
    const float* cb      = (const float*)d_in[7];
    const float* nt_g    = (const float*)d_in[8];
    const float* nt_b    = (const float*)d_in[9];
    const float* E_re    = (const float*)d_in[10];
    const float* E_im    = (const float*)d_in[11];
    const float* Ei_re   = (const float*)d_in[12];
    const float* Ei_im   = (const float*)d_in[13];
    const float* lamflux = (const float*)d_in[14];
    const float* Ws_re   = (const float*)d_in[15];
    const float* Ws_im   = (const float*)d_in[16];
    const float* Wg      = (const float*)d_in[17];
    const float* nu      = (const float*)d_in[18];
    const float* omega   = (const float*)d_in[19];
    const float* w1_re   = (const float*)d_in[20];
    const float* w1_im   = (const float*)d_in[21];
    const float* w2_re   = (const float*)d_in[22];
    const float* w2_im   = (const float*)d_in[23];
    const float* dec_w   = (const float*)d_in[24];
    const float* dec_b   = (const float*)d_in[25];
    float* out = (float*)d_out;

    float* Z   = sym<float>(g_Z);
    float* XE  = sym<float>(g_XE);
    float* DEC = sym<float>(g_DEC);
    hf* IM   = sym<hf>(g_IM);
    hf* Ab   = sym<hf>(g_Ab);
    hf* Zb   = sym<hf>(g_Zb);
    hf* Fb   = sym<hf>(g_Fb);
    hf* Hb   = sym<hf>(g_Hb);
    hf* Wcb  = sym<hf>(g_Wcb);
    hf* Eb   = sym<hf>(g_Eb);
    hf* Eib  = sym<hf>(g_Eib);
    hf* W1b  = sym<hf>(g_W1b);
    hf* W2b  = sym<hf>(g_W2b);
    hf* encb = sym<hf>(g_encb);
    hf* decb = sym<hf>(g_decb);
    float* Wsb  = sym<float>(g_Wsbig);
    float* xm   = sym<float>(g_xmean);
    float* flux = sym<float>(g_flux);
    float* src  = sym<float>(g_src);
    float* gate = sym<float>(g_gate);
    float* OD   = sym<float>(g_OD);
    float* OF   = sym<float>(g_OF);

    // ---- build weights (batched across layers) ----
    {
        dim3 blk(32, 8);
        build_cbigT_tile_k<<<dim3(C2 / 32, C2 / 32, LL), blk>>>(Eb, E_re, E_im, DD, DD);
        build_cbigT_tile_k<<<dim3(C2 / 32, C2 / 32, LL), blk>>>(Eib, Ei_re, Ei_im, DD, DD);
        build_cbig_k<<<dim3((C2 * C2) / 256, LL), 256>>>(Wsb, Ws_re, Ws_im, DD, DD);
        build_cbigT_tile_k<<<dim3(C2 / 32, DFF2 / 32, LL), blk>>>(W1b, w1_re, w1_im, DD, DFF);
        build_cbigT_tile_k<<<dim3(DFF2 / 32, C2 / 32, LL), blk>>>(W2b, w2_re, w2_im, DFF, DD);
        build_convwT_k<<<dim3(C2, LL), 256>>>(Wcb, cw);
        cvt4_k<<<(C2 * KENC / 4 + 255) / 256, 256>>>(enc_w, encb, (size_t)C2 * KENC / 4);
        cvt4_k<<<(NDEC * C2 / 4 + 255) / 256, 256>>>(dec_w, decb, (size_t)NDEC * C2 / 4);
    }

    // ---- encoder ----
    enc_im2col4_k<<<((size_t)NP * KENC / 4) / 256, 256>>>(IM, x);
    launch_gemm<1, false>(IM, encb, Z, nullptr, nullptr, enc_b, C2, KENC);

    for (int l = 0; l < LL; l++) {
        // spatial: LN -> implicit conv3x3 GEMM; Z += conv+cb, emit Zb fp16
        layernorm_k<<<NP, 256>>>(Z, ns_g + l * C2, ns_b + l * C2, Ab);
        launch_gemm<3, true>(Ab, Wcb + (size_t)l * C2 * KC, Z, Zb, nullptr, cb + l * C2, C2, KC);

        // spectral: XE = Z @ E
        launch_gemm<0, false>(Zb, Eb + (size_t)l * C2 * C2, XE, nullptr, nullptr, nullptr, C2, C2);

        // temporal flux path
        rowmean_k<<<BT, C2>>>(XE, xm);
        fluxscan_k<<<6, 256>>>(xm, dt, lamflux + l * DD, Wg + l * DD, flux, gate);
        gemm_small_k<<<(BT * C2) / 256, 256>>>(flux, Wsb + (size_t)l * C2 * C2, src, BT, C2, C2);
        opdecay_k<<<(BT * DD) / 256, 256>>>(dt, nu + l * DD, omega + l * DD, OD, OF);
        fuscan_k<<<(BB * 256 * DD) / 256, 256>>>(XE, gate, src, OF, OD, Ab);

        // decode back: DEC = u_out @ Ei
        launch_gemm<0, false>(Ab, Eib + (size_t)l * C2 * C2, DEC, nullptr, nullptr, nullptr, C2, C2);

        // MLP on LN(DEC); Z += DEC + delta (fused, also emits fp16(Z) -> Fb)
        layernorm_k<<<NP, 256>>>(DEC, nt_g + l * C2, nt_b + l * C2, Zb);
        launch_gemm<4, false>(Zb, W1b + (size_t)l * DFF2 * C2, nullptr, Hb, nullptr, nullptr, DFF2, C2);
        launch_gemm<6, false>(Hb, W2b + (size_t)l * C2 * DFF2, Z, Fb, DEC, nullptr, C2, DFF2);
    }

    // ---- decoder GEMM with fused pixel-shuffle scatter (input: Fb from last Z-fuse) ----
    launch_gemm<7, false>(Fb, decb, out, nullptr, nullptr, dec_b, NDEC, C2);

    (void)in_sizes; (void)n_in; (void)out_size;
}

// round 14
// speedup vs baseline: 4.8583x; 1.0008x over previous
#include <cuda_runtime.h>
#include <cuda_fp16.h>
#include <math.h>
#include <stdint.h>

// ---------------- constants ----------------
#define BB 4
#define TT 12
#define BT 48
#define DD 384
#define C2 768
#define NP 12288
#define KC 6912
#define DFF 1536
#define DFF2 3072
#define KENC 1024
#define NDEC 1024
#define LL 4

typedef __half hf;

// ---------------- device scratch ----------------
__device__ float g_Z[(size_t)NP * C2];
__device__ float g_XE[(size_t)NP * C2];
__device__ float g_DEC[(size_t)NP * C2];
__device__ hf g_IM[(size_t)NP * KENC];
__device__ hf g_Ab[(size_t)NP * C2];
__device__ hf g_Zb[(size_t)NP * C2];
__device__ hf g_Fb[(size_t)NP * C2];      // fp16 of final Z (decoder input)
__device__ hf g_Hb[(size_t)NP * DFF2];
__device__ hf g_Wcb[(size_t)LL * C2 * KC];
__device__ hf g_Eb[(size_t)LL * C2 * C2];
__device__ hf g_Eib[(size_t)LL * C2 * C2];
__device__ hf g_W1b[(size_t)LL * DFF2 * C2];   // [N=3072][K=768]
__device__ hf g_W2b[(size_t)LL * C2 * DFF2];   // [N=768][K=3072]
__device__ hf g_encb[C2 * KENC];
__device__ hf g_decb[NDEC * C2];
__device__ float g_Wsbig[(size_t)LL * C2 * C2];
__device__ float g_xmean[BT * C2];
__device__ float g_flux[BT * C2];
__device__ float g_src[BT * C2];
__device__ float g_gate[BT * DD];
__device__ float g_OD[BT * C2];
__device__ float g_OF[BT * C2];

// ---------------- helpers ----------------
__device__ __forceinline__ float softplus_f(float x) {
    return (x > 20.f) ? x : log1pf(expf(x));
}
__device__ __forceinline__ float gelu_tanh(float x) {
    float x3 = x * x * x;
    float t = tanhf(0.7978845608028654f * (x + 0.044715f * x3));
    return 0.5f * x * (1.f + t);
}
__device__ __forceinline__ uint32_t smem_u32(const void* p) {
    uint32_t a;
    asm("{ .reg .u64 t; cvta.to.shared.u64 t, %1; cvt.u32.u64 %0, t; }" : "=r"(a) : "l"(p));
    return a;
}
__device__ __forceinline__ void cp16(uint32_t dst, const void* src) {
    asm volatile("cp.async.cg.shared.global [%0], [%1], 16;" :: "r"(dst), "l"(src) : "memory");
}
__device__ __forceinline__ void cp16z(uint32_t dst, const void* src, uint32_t sz) {
    asm volatile("cp.async.cg.shared.global [%0], [%1], 16, %2;" :: "r"(dst), "l"(src), "r"(sz) : "memory");
}
#define CP_COMMIT() asm volatile("cp.async.commit_group;" ::: "memory")

#define LDSM4(r, addr) \
    asm volatile("ldmatrix.sync.aligned.m8n8.x4.shared.b16 {%0,%1,%2,%3}, [%4];" \
                 : "=r"((r)[0]), "=r"((r)[1]), "=r"((r)[2]), "=r"((r)[3]) : "r"(addr))

#define MMA16816(d, a, bb0, bb1) \
    asm volatile("mma.sync.aligned.m16n8k16.row.col.f32.f16.f16.f32 " \
                 "{%0,%1,%2,%3}, {%4,%5,%6,%7}, {%8,%9}, {%0,%1,%2,%3};" \
                 : "+f"((d)[0]), "+f"((d)[1]), "+f"((d)[2]), "+f"((d)[3]) \
                 : "r"((a)[0]), "r"((a)[1]), "r"((a)[2]), "r"((a)[3]), \
                   "r"(bb0), "r"(bb1))

// ---------------- warp-MMA fp16 GEMM (single product, 3-stage pipeline) ----------------
// C[M=12288, N] = A @ B^T, A and B single fp16.
// Block tile 256x128x32, 8 warps (4M x 2N), warp tile 64x64.
// smem/stage: A 256x80B=20480 + B 128x80B=10240 -> 30720B; x3 stages = 92160B (2 CTA/SM).
// grid: x = N/128 (fast -> A tile L2 reuse), y = M/256.
// MODE: 0 store, 1 store+bias, 3 acc+bias+hf-emit, 4 gelu->hf, 6 Z-fuse+hf-emit, 7 dec-scatter
// CONV: implicit 3x3 im2col from A [NP][C2] (K = 9*768). Spatial math hoisted:
//   rs = k0/768 is UNIFORM per chunk (k0%768 <= 736, +c4*8 <= 24 < 768),
//   tap address = rowA + (dy*16+dx)*768 + (k0 - rs*768); per-thread row ptrs
//   and (h,w) precomputed once before the mainloop.
// NOTE: load_chunk takes k0 as an ELEMENT offset (chunk << 5) — cp.async 16B
// alignment depends on it (R11 regression: passing a chunk index misaligns src).
#define MATA_B 20480
#define STAGE_B 30720
#define SMEM_TOTAL_G (3 * STAGE_B)

template <int MODE, bool CONV>
__global__ __launch_bounds__(256) void hgemm_k(
    const hf* __restrict__ A0, const hf* __restrict__ B,
    float* __restrict__ C, hf* __restrict__ C0,
    const float* __restrict__ Caux, const float* __restrict__ bias, int N, int K)
{
    extern __shared__ char smem[];
    uint32_t sb = smem_u32(smem);
    const int tid = threadIdx.x;
    const int wid = tid >> 5;
    const int lane = tid & 31;
    const int n0 = blockIdx.x * 128;
    const int m0 = blockIdx.y * 256;
    const int wm = wid & 3;       // 0..3 (M, x64)
    const int wn = wid >> 2;      // 0..1 (N, x64)

    // CONV precompute: per-slot row pointer and spatial coords (c4 = tid&3 is
    // constant across i; row = (tid>>2) + 64*i).
    const hf* rowA[4];
    int hA[4], wA[4];
    if (CONV) {
#pragma unroll
        for (int i = 0; i < 4; i++) {
            int m = m0 + (tid >> 2) + 64 * i;
            hA[i] = (m >> 4) & 15;
            wA[i] = m & 15;
            rowA[i] = A0 + (size_t)m * 768 + (tid & 3) * 8;
        }
    }

    auto load_chunk = [&](int k0, int buf) {
        uint32_t st = sb + buf * STAGE_B;
        // A: 256 rows x 4 vecs = 1024
        if (CONV) {
            int rs = k0 / 768;               // uniform across chunk
            int ci0 = k0 - rs * 768;
            int dy = rs / 3 - 1, dx = rs - (rs / 3) * 3 - 1;
            intptr_t doff = (intptr_t)(dy * 16 + dx) * 768 + ci0;
#pragma unroll
            for (int i = 0; i < 4; i++) {
                uint32_t dst = st + ((tid >> 2) + 64 * i) * 80 + (tid & 3) * 16;
                int hh = hA[i] + dy, ww = wA[i] + dx;
                bool ok = ((unsigned)hh < 16u) && ((unsigned)ww < 16u);
                const hf* sp = ok ? (rowA[i] + doff) : A0;
                cp16z(dst, sp, ok ? 16u : 0u);
            }
        } else {
#pragma unroll
            for (int i = 0; i < 4; i++) {
                int id = tid + 256 * i;
                int row = id >> 2, c4 = id & 3;
                uint32_t dst = st + row * 80 + c4 * 16;
                cp16(dst, A0 + (size_t)(m0 + row) * K + k0 + c4 * 8);
            }
        }
        // B: 128 rows x 4 vecs = 512
#pragma unroll
        for (int i = 0; i < 2; i++) {
            int id = tid + 256 * i;
            int row = id >> 2, c4 = id & 3;
            uint32_t dst = st + MATA_B + row * 80 + c4 * 16;
            cp16(dst, B + (size_t)(n0 + row) * K + k0 + c4 * 8);
        }
    };

    float acc[4][8][4];
#pragma unroll
    for (int i = 0; i < 4; i++)
#pragma unroll
        for (int j = 0; j < 8; j++)
#pragma unroll
            for (int e = 0; e < 4; e++) acc[i][j][e] = 0.f;

    const int nc = K >> 5;   // all GEMMs have nc >= 24
    load_chunk(0, 0);
    CP_COMMIT();
    load_chunk(32, 1);
    CP_COMMIT();

    const int lrow = lane & 15;
    const int lcol = lane >> 4;

    for (int c = 0; c < nc; c++) {
        int buf = c % 3;
        if (c + 2 < nc) {
            load_chunk((c + 2) << 5, (c + 2) % 3);
            CP_COMMIT();
            asm volatile("cp.async.wait_group 2;" ::: "memory");
        } else if (c + 1 < nc) {
            asm volatile("cp.async.wait_group 1;" ::: "memory");
        } else {
            asm volatile("cp.async.wait_group 0;" ::: "memory");
        }
        __syncthreads();
        uint32_t st = sb + buf * STAGE_B;
#pragma unroll
        for (int ks = 0; ks < 2; ks++) {
            uint32_t a0[4][4];
#pragma unroll
            for (int mi = 0; mi < 4; mi++) {
                uint32_t ad = st + (wm * 64 + mi * 16 + lrow) * 80 + ks * 32 + lcol * 16;
                LDSM4(a0[mi], ad);
            }
#pragma unroll
            for (int nq = 0; nq < 4; nq++) {
                uint32_t br[4];
                uint32_t bd = st + MATA_B + (wn * 64 + nq * 16 + lrow) * 80 + ks * 32 + lcol * 16;
                LDSM4(br, bd);
#pragma unroll
                for (int mi = 0; mi < 4; mi++) {
                    MMA16816(acc[mi][nq * 2],     a0[mi], br[0], br[2]);
                    MMA16816(acc[mi][nq * 2 + 1], a0[mi], br[1], br[3]);
                }
            }
        }
        __syncthreads();
    }

    // epilogue (vectorized: float2 / half2)
#pragma unroll
    for (int mi = 0; mi < 4; mi++) {
#pragma unroll
        for (int nj = 0; nj < 8; nj++) {
            int row = m0 + wm * 64 + mi * 16 + (lane >> 2);
            int col = n0 + wn * 64 + nj * 8 + (lane & 3) * 2;
            float* d = acc[mi][nj];
#pragma unroll
            for (int h = 0; h < 2; h++) {
                int r = row + h * 8;
                float v0 = d[h * 2 + 0], v1 = d[h * 2 + 1];
                if (MODE == 1 || MODE == 3 || MODE == 7) {
                    v0 += bias[col];
                    v1 += bias[col + 1];
                }
                size_t co = (size_t)r * N + col;
                if (MODE == 0 || MODE == 1) {
                    *(float2*)(C + co) = make_float2(v0, v1);
                } else if (MODE == 3) {
                    float2 zc = *(const float2*)(C + co);
                    float z0 = zc.x + v0, z1 = zc.y + v1;
                    *(float2*)(C + co) = make_float2(z0, z1);
                    *(__half2*)(C0 + co) = __floats2half2_rn(z0, z1);
                } else if (MODE == 4) {
                    *(__half2*)(C0 + co) = __floats2half2_rn(gelu_tanh(v0), gelu_tanh(v1));
                } else if (MODE == 6) {
                    float2 ax = *(const float2*)(Caux + co);
                    float2 zc = *(const float2*)(C + co);
                    float z0 = zc.x + ax.x + v0, z1 = zc.y + ax.y + v1;
                    *(float2*)(C + co) = make_float2(z0, z1);
                    *(__half2*)(C0 + co) = __floats2half2_rn(z0, z1);
                } else if (MODE == 7) {
                    // pixel-shuffle scatter: r -> (bt,hp,wp), col -> (co4,pi,pj)
                    int bt = r >> 8;
                    int hp = (r >> 4) & 15, wp = r & 15;
                    int co4 = col >> 8;
                    int rem = col & 255;
                    int pi = rem >> 4, pj = rem & 15;
                    size_t o = (((size_t)(bt * 4 + co4) * 256 + hp * 16 + pi) * 256) + wp * 16 + pj;
                    *(float2*)(C + o) = make_float2(v0, v1);
                }
            }
        }
    }
}

// ---------------- tiny fp32 GEMM (M=48) ----------------
__global__ void gemm_small_k(const float* __restrict__ A, const float* __restrict__ B,
                             float* __restrict__ C, int M, int N, int K)
{
    int idx = blockIdx.x * blockDim.x + threadIdx.x;
    if (idx >= M * N) return;
    int m = idx / N, n = idx % N;
    float s = 0.f;
    for (int k = 0; k < K; k++) s += A[(size_t)m * K + k] * B[(size_t)k * N + n];
    C[idx] = s;
}

// ---------------- weight builders (batched over layers) ----------------
// fp32 big [2K][2N] for gemm_small; blockIdx.y = layer
__global__ void build_cbig_k(float* __restrict__ dst, const float* __restrict__ re,
                             const float* __restrict__ im, int Kd, int Nd)
{
    int l = blockIdx.y;
    dst += (size_t)l * (4 * Kd * Nd);
    re += (size_t)l * Kd * Nd;
    im += (size_t)l * Kd * Nd;
    int idx = blockIdx.x * blockDim.x + threadIdx.x;
    int N2 = 2 * Nd;
    if (idx >= 2 * Kd * N2) return;
    int k2 = idx / N2, n2 = idx % N2;
    bool ki = k2 >= Kd, ni = n2 >= Nd;
    int k = ki ? k2 - Kd : k2;
    int n = ni ? n2 - Nd : n2;
    float v;
    if (!ki && !ni) v = re[(size_t)k * Nd + n];
    else if (!ki && ni) v = im[(size_t)k * Nd + n];
    else if (ki && !ni) v = -im[(size_t)k * Nd + n];
    else v = re[(size_t)k * Nd + n];
    dst[idx] = v;
}

// tiled transpose: dst[n2][k2] = big[k2][n2] as single fp16; blockIdx.z = layer
// grid (2Kd/32, 2Nd/32, L), block (32,8)
__global__ void build_cbigT_tile_k(hf* __restrict__ d0,
                                   const float* __restrict__ re, const float* __restrict__ im,
                                   int Kd, int Nd)
{
    __shared__ float tile[32][33];
    int l = blockIdx.z;
    d0 += (size_t)l * (4 * Kd * Nd);
    re += (size_t)l * Kd * Nd;
    im += (size_t)l * Kd * Nd;
    int k2_0 = blockIdx.x * 32, n2_0 = blockIdx.y * 32;
    bool ki = k2_0 >= Kd, ni = n2_0 >= Nd;
    int k0 = k2_0 - (ki ? Kd : 0), n0 = n2_0 - (ni ? Nd : 0);
    const float* s = (ki != ni) ? im : re;
    float sign = (ki && !ni) ? -1.f : 1.f;
    int tx = threadIdx.x, ty = threadIdx.y;
#pragma unroll
    for (int j = 0; j < 4; j++) {
        int r = ty + j * 8;
        tile[r][tx] = s[(size_t)(k0 + r) * Nd + n0 + tx];
    }
    __syncthreads();
    int K2 = 2 * Kd;
#pragma unroll
    for (int j = 0; j < 4; j++) {
        int r = ty + j * 8;
        float v = sign * tile[tx][r];
        d0[(size_t)(n2_0 + r) * K2 + k2_0 + tx] = __float2half(v);
    }
}

// conv weights: dst[l][co][rs*768+ci] = cw[l][co][ci][rs]; grid (C2, LL)
__global__ void build_convwT_k(hf* __restrict__ d0, const float* __restrict__ cw)
{
    __shared__ float s[KC];
    int co = blockIdx.x, l = blockIdx.y;
    const float* srcr = cw + ((size_t)(l * C2 + co)) * KC;
    for (int i = threadIdx.x; i < KC; i += 256) s[i] = srcr[i];
    __syncthreads();
    size_t base = ((size_t)l * C2 + co) * KC;
    for (int k = threadIdx.x; k < KC; k += 256) {
        int rs = k / 768;
        int ci = k - rs * 768;
        d0[base + k] = __float2half(s[ci * 9 + rs]);
    }
}

// fp32 -> single fp16, vectorized x4
__global__ void cvt4_k(const float* __restrict__ src, hf* __restrict__ d0, size_t n4)
{
    size_t idx = (size_t)blockIdx.x * blockDim.x + threadIdx.x;
    if (idx >= n4) return;
    float4 v = ((const float4*)src)[idx];
    __half2 p0 = {__float2half(v.x), __float2half(v.y)};
    __half2 p1 = {__float2half(v.z), __float2half(v.w)};
    ((__half2*)d0)[idx * 2] = p0;
    ((__half2*)d0)[idx * 2 + 1] = p1;
}

// ---------------- encoder im2col (vectorized x4, fp16) ----------------
__global__ void enc_im2col4_k(hf* __restrict__ P0, const float* __restrict__ x)
{
    size_t idx = (size_t)blockIdx.x * blockDim.x + threadIdx.x;  // NP*KENC/4
    size_t flat = idx * 4;
    int kk = flat % KENC;
    int n = flat / KENC;
    int cin = kk >> 8;
    int ii = (kk >> 4) & 15;
    int jj = kk & 15;
    int bt = n >> 8;
    int ph = (n >> 4) & 15;
    int pw = n & 15;
    const float* xp = x + ((((size_t)(bt * 4 + cin) * 256) + ph * 16 + ii) * 256 + pw * 16 + jj);
    float4 v = *(const float4*)xp;
    __half2 p0 = {__float2half(v.x), __float2half(v.y)};
    __half2 p1 = {__float2half(v.z), __float2half(v.w)};
    ((__half2*)P0)[idx * 2] = p0;
    ((__half2*)P0)[idx * 2 + 1] = p1;
}

// ---------------- layernorm over 768 channels, emits fp16 ----------------
__global__ void layernorm_k(const float* __restrict__ X, const float* __restrict__ g,
                            const float* __restrict__ b, hf* __restrict__ Y0)
{
    __shared__ float red[256];
    int n = blockIdx.x;
    int tid = threadIdx.x;
    const float* x = X + (size_t)n * C2;
    float v0 = x[tid], v1 = x[tid + 256], v2 = x[tid + 512];
    red[tid] = v0 + v1 + v2;
    __syncthreads();
    for (int off = 128; off > 0; off >>= 1) {
        if (tid < off) red[tid] += red[tid + off];
        __syncthreads();
    }
    float m = red[0] * (1.f / 768.f);
    __syncthreads();
    float d0 = v0 - m, d1 = v1 - m, d2 = v2 - m;
    red[tid] = d0 * d0 + d1 * d1 + d2 * d2;
    __syncthreads();
    for (int off = 128; off > 0; off >>= 1) {
        if (tid < off) red[tid] += red[tid + off];
        __syncthreads();
    }
    float var = red[0] * (1.f / 768.f);
    float rstd = rsqrtf(var + 1e-5f);
    size_t base = (size_t)n * C2;
    Y0[base + tid]       = __float2half(d0 * rstd * g[tid] + b[tid]);
    Y0[base + tid + 256] = __float2half(d1 * rstd * g[tid + 256] + b[tid + 256]);
    Y0[base + tid + 512] = __float2half(d2 * rstd * g[tid + 512] + b[tid + 512]);
}

// ---------------- mean over 256 spatial positions (parallel + atomic) ----------------
__global__ void xmzero_k(float* __restrict__ xm)
{
    xm[blockIdx.x * 256 + threadIdx.x] = 0.f;
}
// grid (BT, 8), block 768: each block sums 32 hw positions for all channels.
__global__ void rowmean_k(const float* __restrict__ XE, float* __restrict__ xm)
{
    int bt = blockIdx.x;
    int seg = blockIdx.y;
    int c = threadIdx.x;
    float s = 0.f;
    const float* p = XE + ((size_t)bt * 256 + seg * 32) * C2 + c;
    for (int hw = 0; hw < 32; hw++) s += p[(size_t)hw * C2];
    atomicAdd(&xm[bt * C2 + c], s * (1.f / 256.f));
}

// ---------------- flux scan + gate ----------------
__global__ void fluxscan_k(const float* __restrict__ xm, const float* __restrict__ dt,
                           const float* __restrict__ lamf_p, const float* __restrict__ Wg,
                           float* __restrict__ flux, float* __restrict__ gate)
{
    int tid = blockIdx.x * blockDim.x + threadIdx.x;
    int b = tid / DD, e = tid % DD;
    float lamf = softplus_f(lamf_p[e]);
    float wg = Wg[e];
    float fr = 0.f, fi = 0.f;
    for (int t = 0; t < TT; t++) {
        int bt = b * TT + t;
        float dtv = dt[bt];
        float a = expf(-lamf * dtv);
        float xr = xm[bt * C2 + e] * dtv;
        float xi = xm[bt * C2 + DD + e] * dtv;
        fr = fr * a + xr;
        fi = fi * a + xi;
        flux[bt * C2 + e] = fr;
        flux[bt * C2 + DD + e] = fi;
        gate[bt * DD + e] = 1.f / (1.f + expf(-fr * wg));
    }
}

// ---------------- op_decay / op_forcing ----------------
__global__ void opdecay_k(const float* __restrict__ dt, const float* __restrict__ nu,
                          const float* __restrict__ omega, float* __restrict__ OD,
                          float* __restrict__ OF)
{
    int idx = blockIdx.x * blockDim.x + threadIdx.x;
    int bt = idx / DD, e = idx % DD;
    float sp = softplus_f(nu[e]);
    float lr = fminf(fmaxf(-sp, -5.f), 0.3f);
    float li = omega[e];
    float dtv = dt[bt];
    float er = expf(lr * dtv);
    float odr = er * cosf(li * dtv);
    float odi = er * sinf(li * dtv);
    OD[bt * C2 + e] = odr;
    OD[bt * C2 + DD + e] = odi;
    float nr = odr - 1.f, ni = odi;
    float den = lr * lr + li * li;
    OF[bt * C2 + e] = (nr * lr + ni * li) / den;
    OF[bt * C2 + DD + e] = (ni * lr - nr * li) / den;
}

// ---------------- fused forcing + u scan, emits fp16 ----------------
__global__ void fuscan_k(const float* __restrict__ XE, const float* __restrict__ gate,
                         const float* __restrict__ src, const float* __restrict__ OF,
                         const float* __restrict__ OD, hf* __restrict__ U0)
{
    int tid = blockIdx.x * blockDim.x + threadIdx.x;  // BB*256*DD
    int e = tid % DD;
    int hw = (tid / DD) & 255;
    int b = tid / (DD * 256);
    float ur = 0.f, ui = 0.f;
    for (int t = 0; t < TT; t++) {
        int bt = b * TT + t;
        size_t base = (size_t)(bt * 256 + hw) * C2;
        float xr = XE[base + e], xi = XE[base + DD + e];
        float g = gate[bt * DD + e];
        float sr = src[bt * C2 + e], si = src[bt * C2 + DD + e];
        float fr = xr * g + sr * (1.f - g);
        float fi = xi * g + si * (1.f - g);
        float ofr = OF[bt * C2 + e], ofi = OF[bt * C2 + DD + e];
        float utr = fr * ofr - fi * ofi;
        float uti = fr * ofi + fi * ofr;
        float odr = OD[bt * C2 + e], odi = OD[bt * C2 + DD + e];
        float nr = ur * odr - ui * odi + utr;
        float ni = ur * odi + ui * odr + uti;
        ur = nr; ui = ni;
        U0[base + e] = __float2half(ur);
        U0[base + DD + e] = __float2half(ui);
    }
}

// ---------------- host side ----------------
template <typename T>
static T* sym(const void* s)
{
    void* p = nullptr;
    cudaGetSymbolAddress(&p, s);
    return (T*)p;
}

template <int MODE, bool CONV>
static void launch_gemm(const hf* A0, const hf* B,
                        float* C, hf* C0, const float* Caux,
                        const float* bias, int N, int K)
{
    cudaFuncSetAttribute(hgemm_k<MODE, CONV>, cudaFuncAttributeMaxDynamicSharedMemorySize, SMEM_TOTAL_G);
    dim3 grid(N / 128, NP / 256);
    hgemm_k<MODE, CONV><<<grid, 256, SMEM_TOTAL_G>>>(A0, B, C, C0, Caux, bias, N, K);
}

extern "C" void kernel_launch(void* const* d_in, const int* in_sizes, int n_in,
                              void* d_out, int out_size)
{
    const float* x       = (const float*)d_in[0];
    const float* dt      = (const float*)d_in[1];
    const float* enc_w   = (const float*)d_in[2];
    const float* enc_b   = (const float*)d_in[3];
    const float* ns_g    = (const float*)d_in[4];
    const float* ns_b    = (const float*)d_in[5];
    const float* cw      = (const float*)d_in[6];
    const float* cb      = (const float*)d_in[7];
    const float* nt_g    = (const float*)d_in[8];
    const float* nt_b    = (const float*)d_in[9];
    const float* E_re    = (const float*)d_in[10];
    const float* E_im    = (const float*)d_in[11];
    const float* Ei_re   = (const float*)d_in[12];
    const float* Ei_im   = (const float*)d_in[13];
    const float* lamflux = (const float*)d_in[14];
    const float* Ws_re   = (const float*)d_in[15];
    const float* Ws_im   = (const float*)d_in[16];
    const float* Wg      = (const float*)d_in[17];
    const float* nu      = (const float*)d_in[18];
    const float* omega   = (const float*)d_in[19];
    const float* w1_re   = (const float*)d_in[20];
    const float* w1_im   = (const float*)d_in[21];
    const float* w2_re   = (const float*)d_in[22];
    const float* w2_im   = (const float*)d_in[23];
    const float* dec_w   = (const float*)d_in[24];
    const float* dec_b   = (const float*)d_in[25];
    float* out = (float*)d_out;

    float* Z   = sym<float>(g_Z);
    float* XE  = sym<float>(g_XE);
    float* DEC = sym<float>(g_DEC);
    hf* IM   = sym<hf>(g_IM);
    hf* Ab   = sym<hf>(g_Ab);
    hf* Zb   = sym<hf>(g_Zb);
    hf* Fb   = sym<hf>(g_Fb);
    hf* Hb   = sym<hf>(g_Hb);
    hf* Wcb  = sym<hf>(g_Wcb);
    hf* Eb   = sym<hf>(g_Eb);
    hf* Eib  = sym<hf>(g_Eib);
    hf* W1b  = sym<hf>(g_W1b);
    hf* W2b  = sym<hf>(g_W2b);
    hf* encb = sym<hf>(g_encb);
    hf* decb = sym<hf>(g_decb);
    float* Wsb  = sym<float>(g_Wsbig);
    float* xm   = sym<float>(g_xmean);
    float* flux = sym<float>(g_flux);
    float* src  = sym<float>(g_src);
    float* gate = sym<float>(g_gate);
    float* OD   = sym<float>(g_OD);
    float* OF   = sym<float>(g_OF);

    // ---- build weights (batched across layers) ----
    {
        dim3 blk(32, 8);
        build_cbigT_tile_k<<<dim3(C2 / 32, C2 / 32, LL), blk>>>(Eb, E_re, E_im, DD, DD);
        build_cbigT_tile_k<<<dim3(C2 / 32, C2 / 32, LL), blk>>>(Eib, Ei_re, Ei_im, DD, DD);
        build_cbig_k<<<dim3((C2 * C2) / 256, LL), 256>>>(Wsb, Ws_re, Ws_im, DD, DD);
        build_cbigT_tile_k<<<dim3(C2 / 32, DFF2 / 32, LL), blk>>>(W1b, w1_re, w1_im, DD, DFF);
        build_cbigT_tile_k<<<dim3(DFF2 / 32, C2 / 32, LL), blk>>>(W2b, w2_re, w2_im, DFF, DD);
        build_convwT_k<<<dim3(C2, LL), 256>>>(Wcb, cw);
        cvt4_k<<<(C2 * KENC / 4 + 255) / 256, 256>>>(enc_w, encb, (size_t)C2 * KENC / 4);
        cvt4_k<<<(NDEC * C2 / 4 + 255) / 256, 256>>>(dec_w, decb, (size_t)NDEC * C2 / 4);
    }

    // ---- encoder ----
    enc_im2col4_k<<<((size_t)NP * KENC / 4) / 256, 256>>>(IM, x);
    launch_gemm<1, false>(IM, encb, Z, nullptr, nullptr, enc_b, C2, KENC);

    for (int l = 0; l < LL; l++) {
        // spatial: LN -> implicit conv3x3 GEMM; Z += conv+cb, emit Zb fp16
        layernorm_k<<<NP, 256>>>(Z, ns_g + l * C2, ns_b + l * C2, Ab);
        launch_gemm<3, true>(Ab, Wcb + (size_t)l * C2 * KC, Z, Zb, nullptr, cb + l * C2, C2, KC);

        // spectral: XE = Z @ E
        launch_gemm<0, false>(Zb, Eb + (size_t)l * C2 * C2, XE, nullptr, nullptr, nullptr, C2, C2);

        // temporal flux path
        xmzero_k<<<(BT * C2) / 256, 256>>>(xm);
        rowmean_k<<<dim3(BT, 8), C2>>>(XE, xm);
        fluxscan_k<<<6, 256>>>(xm, dt, lamflux + l * DD, Wg + l * DD, flux, gate);
        gemm_small_k<<<(BT * C2) / 256, 256>>>(flux, Wsb + (size_t)l * C2 * C2, src, BT, C2, C2);
        opdecay_k<<<(BT * DD) / 256, 256>>>(dt, nu + l * DD, omega + l * DD, OD, OF);
        fuscan_k<<<(BB * 256 * DD) / 256, 256>>>(XE, gate, src, OF, OD, Ab);

        // decode back: DEC = u_out @ Ei
        launch_gemm<0, false>(Ab, Eib + (size_t)l * C2 * C2, DEC, nullptr, nullptr, nullptr, C2, C2);

        // MLP on LN(DEC); Z += DEC + delta (fused, also emits fp16(Z) -> Fb)
        layernorm_k<<<NP, 256>>>(DEC, nt_g + l * C2, nt_b + l * C2, Zb);
        launch_gemm<4, false>(Zb, W1b + (size_t)l * DFF2 * C2, nullptr, Hb, nullptr, nullptr, DFF2, C2);
        launch_gemm<6, false>(Hb, W2b + (size_t)l * C2 * DFF2, Z, Fb, DEC, nullptr, C2, DFF2);
    }

    // ---- decoder GEMM with fused pixel-shuffle scatter (input: Fb from last Z-fuse) ----
    launch_gemm<7, false>(Fb, decb, out, nullptr, nullptr, dec_b, NDEC, C2);

    (void)in_sizes; (void)n_in; (void)out_size;
}